// round 1
// baseline (speedup 1.0000x reference)
#include <cuda_runtime.h>
#include <math.h>

#define Bc 2
#define Sc 1024
#define Mc 1024
#define Dc 1024
#define Hc 16
#define DHc 64
#define DFFc 4096
#define Stc 2048
#define Zc (Bc*Hc)

// ---------------- scratch (device globals: no allocation allowed) ----------------
__device__ float g_xn [Bc*Sc*Dc];
__device__ float g_h  [Bc*Stc*Dc];
__device__ float g_qt [Bc*Sc*Dc];
__device__ float g_q  [Zc*Sc*DHc];
__device__ float g_q2 [Zc*Sc*DHc];
__device__ float g_kv [Bc*Stc*2*Dc];
__device__ float g_k  [Zc*Stc*DHc];
__device__ float g_v  [Zc*Stc*DHc];
__device__ float g_scb[(size_t)Zc*Sc*Stc];   // scores (content / logits / probs)
__device__ float g_psb[(size_t)Zc*Sc*Stc];   // pos scores
__device__ float g_o  [Bc*Sc*Dc];
__device__ float g_tmp[Bc*Sc*Dc];
__device__ float g_out[Bc*Sc*Dc];
__device__ float g_out2[Bc*Sc*Dc];
__device__ float g_ff [(size_t)Bc*Sc*DFFc];

// ---------------- generic SGEMM: C = act(A@B + bias) + Res ----------------
// A: Mr x K row-major, B: K x N row-major, tiles 128x128x8, 256 threads, 8x8/thread
template<int ACT>
__global__ void sgemm128(const float* __restrict__ A, const float* __restrict__ Bm,
                         float* __restrict__ C, int Mr, int N, int K,
                         const float* __restrict__ bias, const float* __restrict__ Res)
{
    __shared__ float As[8][128];
    __shared__ float Bs[8][128];
    const int tid = threadIdx.x;
    const int tm = tid >> 4, tn = tid & 15;
    const int row0 = blockIdx.y * 128, col0 = blockIdx.x * 128;

    const int la_m = tid >> 1;
    const int la_k = (tid & 1) * 4;
    const int lb_k = tid >> 5;
    const int lb_n = (tid & 31) * 4;

    float acc[8][8];
#pragma unroll
    for (int r = 0; r < 8; r++)
#pragma unroll
        for (int c = 0; c < 8; c++) acc[r][c] = 0.f;

    for (int k0 = 0; k0 < K; k0 += 8) {
        float4 av = *(const float4*)&A[(size_t)(row0 + la_m) * K + k0 + la_k];
        As[la_k + 0][la_m] = av.x;
        As[la_k + 1][la_m] = av.y;
        As[la_k + 2][la_m] = av.z;
        As[la_k + 3][la_m] = av.w;
        *(float4*)&Bs[lb_k][lb_n] =
            *(const float4*)&Bm[(size_t)(k0 + lb_k) * N + col0 + lb_n];
        __syncthreads();
#pragma unroll
        for (int kk = 0; kk < 8; kk++) {
            float a[8], b[8];
#pragma unroll
            for (int r = 0; r < 8; r++) a[r] = As[kk][tm * 8 + r];
#pragma unroll
            for (int c = 0; c < 8; c++) b[c] = Bs[kk][tn * 8 + c];
#pragma unroll
            for (int r = 0; r < 8; r++)
#pragma unroll
                for (int c = 0; c < 8; c++) acc[r][c] += a[r] * b[c];
        }
        __syncthreads();
    }

#pragma unroll
    for (int r = 0; r < 8; r++) {
        int rr = row0 + tm * 8 + r;
#pragma unroll
        for (int c = 0; c < 8; c++) {
            int cc = col0 + tn * 8 + c;
            float v = acc[r][c];
            if (bias) v += bias[cc];
            if (ACT == 1) v = 0.5f * v * (1.0f + erff(v * 0.70710678118654752f));
            if (Res) v += Res[(size_t)rr * N + cc];
            C[(size_t)rr * N + cc] = v;
        }
    }
}

// ---------------- QK^T scores: Out[z,i,j] = sum_d Q[z,i,d]*K[.,j,d] ----------------
// POS=false: Kp is (Z, Sk, 64).  POS=true: Kp is pos_emb (Sk, Dc), head-offset slice.
template<bool POS>
__global__ void qk_kernel(const float* __restrict__ Q, const float* __restrict__ Kp,
                          float* __restrict__ Out, int Srows, int Sk)
{
    __shared__ float Qs[64][65];
    __shared__ float Ks[64][65];
    const int z = blockIdx.z;
    const int j0 = blockIdx.x * 64, i0 = blockIdx.y * 64;
    const int tid = threadIdx.x;

    const float* Qb = Q + ((size_t)z * Srows + i0) * DHc;
    for (int l = tid; l < 64 * 16; l += 256) {
        int r = l >> 4, d4 = (l & 15) * 4;
        float4 qv = *(const float4*)&Qb[r * DHc + d4];
        Qs[r][d4 + 0] = qv.x; Qs[r][d4 + 1] = qv.y;
        Qs[r][d4 + 2] = qv.z; Qs[r][d4 + 3] = qv.w;
    }
    const float* Kb;
    int ldk;
    if (POS) { Kb = Kp + (z % Hc) * DHc; ldk = Dc; }
    else     { Kb = Kp + (size_t)z * Sk * DHc; ldk = DHc; }
    for (int l = tid; l < 64 * 16; l += 256) {
        int r = l >> 4, d4 = (l & 15) * 4;
        float4 kv4 = *(const float4*)&Kb[(size_t)(j0 + r) * ldk + d4];
        Ks[r][d4 + 0] = kv4.x; Ks[r][d4 + 1] = kv4.y;
        Ks[r][d4 + 2] = kv4.z; Ks[r][d4 + 3] = kv4.w;
    }
    __syncthreads();

    const int tm = tid >> 4, tn = tid & 15;
    float acc[4][4];
#pragma unroll
    for (int r = 0; r < 4; r++)
#pragma unroll
        for (int c = 0; c < 4; c++) acc[r][c] = 0.f;
#pragma unroll 8
    for (int d = 0; d < 64; d++) {
        float a[4], b[4];
#pragma unroll
        for (int r = 0; r < 4; r++) a[r] = Qs[tm * 4 + r][d];
#pragma unroll
        for (int c = 0; c < 4; c++) b[c] = Ks[tn * 4 + c][d];
#pragma unroll
        for (int r = 0; r < 4; r++)
#pragma unroll
            for (int c = 0; c < 4; c++) acc[r][c] += a[r] * b[c];
    }
#pragma unroll
    for (int r = 0; r < 4; r++)
#pragma unroll
        for (int c = 0; c < 4; c++)
            Out[((size_t)z * Srows + i0 + tm * 4 + r) * Sk + j0 + tn * 4 + c] = acc[r][c];
}

// ---------------- logits: C[z,i,j] = mask ? -1e30 : C + rel_shift(P) ----------------
__global__ void logits_kernel(float* __restrict__ C, const float* __restrict__ P)
{
    size_t idx = (size_t)blockIdx.x * 256 + threadIdx.x;
    int j = idx & (Stc - 1);
    size_t r = idx >> 11;          // / Stc
    int i = r & (Sc - 1);
    int z = (int)(r >> 10);        // / Sc
    int b = z >> 4, h = z & 15;    // z = b*H + h
    // exact flat-index algebra of the jax pad+reshape rel_shift
    int t  = b * Sc + i + Bc;
    int bp = t / (Sc + 1);
    int i1 = t % (Sc + 1);
    float p = 0.f;
    if (i1 > 0) p = P[(((size_t)(bp * Hc + h)) * Sc + (i1 - 1)) * Stc + j];
    float val = C[idx] + p;
    if (j > i + Mc) val = -1e30f;   // mask BEFORE scale (scale folded into softmax)
    C[idx] = val;
}

// ---------------- softmax over i (query axis), per (z, j) column ----------------
__global__ void softmax_i(float* __restrict__ P, int Srows, int Sk, float scale, int cols)
{
    int col = blockIdx.x * blockDim.x + threadIdx.x;
    if (col >= cols) return;
    int z = col / Sk, j = col % Sk;
    float* base = P + (size_t)z * Srows * Sk + j;
    float mx = -3.4e38f;
    for (int i = 0; i < Srows; i++) {
        float v = base[(size_t)i * Sk] * scale;
        mx = fmaxf(mx, v);
    }
    float s = 0.f;
    for (int i = 0; i < Srows; i++)
        s += __expf(base[(size_t)i * Sk] * scale - mx);
    float inv = 1.f / s;
    for (int i = 0; i < Srows; i++) {
        float v = __expf(base[(size_t)i * Sk] * scale - mx) * inv;
        base[(size_t)i * Sk] = v;
    }
}

// ---------------- AV: O[b, i, h*64+d] = sum_j P[z,i,j] * V[z,j,d] ----------------
__global__ void av_kernel(const float* __restrict__ P, const float* __restrict__ V,
                          float* __restrict__ O, int Srows, int Sk)
{
    __shared__ float Ps[64][33];
    __shared__ float Vs[32][65];
    const int z = blockIdx.y;
    const int i0 = blockIdx.x * 64;
    const int tid = threadIdx.x;
    const int tm = tid >> 4, tn = tid & 15;

    float acc[4][4];
#pragma unroll
    for (int r = 0; r < 4; r++)
#pragma unroll
        for (int c = 0; c < 4; c++) acc[r][c] = 0.f;

    for (int j0 = 0; j0 < Sk; j0 += 32) {
        for (int l = tid; l < 64 * 8; l += 256) {
            int r = l >> 3, j4 = (l & 7) * 4;
            float4 pv = *(const float4*)&P[((size_t)z * Srows + i0 + r) * Sk + j0 + j4];
            Ps[r][j4 + 0] = pv.x; Ps[r][j4 + 1] = pv.y;
            Ps[r][j4 + 2] = pv.z; Ps[r][j4 + 3] = pv.w;
        }
        for (int l = tid; l < 32 * 16; l += 256) {
            int r = l >> 4, d4 = (l & 15) * 4;
            float4 vv = *(const float4*)&V[((size_t)z * Sk + j0 + r) * DHc + d4];
            Vs[r][d4 + 0] = vv.x; Vs[r][d4 + 1] = vv.y;
            Vs[r][d4 + 2] = vv.z; Vs[r][d4 + 3] = vv.w;
        }
        __syncthreads();
#pragma unroll 8
        for (int jj = 0; jj < 32; jj++) {
            float a[4], b[4];
#pragma unroll
            for (int r = 0; r < 4; r++) a[r] = Ps[tm * 4 + r][jj];
#pragma unroll
            for (int c = 0; c < 4; c++) b[c] = Vs[jj][tn * 4 + c];
#pragma unroll
            for (int r = 0; r < 4; r++)
#pragma unroll
                for (int c = 0; c < 4; c++) acc[r][c] += a[r] * b[c];
        }
        __syncthreads();
    }
    const int b = z >> 4, hh = z & 15;
#pragma unroll
    for (int r = 0; r < 4; r++)
#pragma unroll
        for (int c = 0; c < 4; c++)
            O[((size_t)(b * Sc) + i0 + tm * 4 + r) * Dc + hh * DHc + tn * 4 + c] = acc[r][c];
}

// ---------------- LayerNorm (row = D), optional residual AFTER the LN ----------------
__global__ void ln_kernel(const float* __restrict__ X, const float* __restrict__ gw,
                          const float* __restrict__ bw, float* __restrict__ Y,
                          const float* __restrict__ Res)
{
    __shared__ float s1[256], s2[256];
    const int row = blockIdx.x;
    const int tid = threadIdx.x;
    const float* x = X + (size_t)row * Dc;
    float4 v = *(const float4*)&x[tid * 4];
    s1[tid] = v.x + v.y + v.z + v.w;
    s2[tid] = v.x * v.x + v.y * v.y + v.z * v.z + v.w * v.w;
    __syncthreads();
    for (int st = 128; st > 0; st >>= 1) {
        if (tid < st) { s1[tid] += s1[tid + st]; s2[tid] += s2[tid + st]; }
        __syncthreads();
    }
    float mu = s1[0] * (1.f / Dc);
    float var = s2[0] * (1.f / Dc) - mu * mu;
    float rinv = rsqrtf(var + 1e-5f);
    float4 g4 = *(const float4*)&gw[tid * 4];
    float4 b4 = *(const float4*)&bw[tid * 4];
    float4 o;
    o.x = (v.x - mu) * rinv * g4.x + b4.x;
    o.y = (v.y - mu) * rinv * g4.y + b4.y;
    o.z = (v.z - mu) * rinv * g4.z + b4.z;
    o.w = (v.w - mu) * rinv * g4.w + b4.w;
    if (Res) {
        float4 r4 = *(const float4*)&Res[(size_t)row * Dc + tid * 4];
        o.x += r4.x; o.y += r4.y; o.z += r4.z; o.w += r4.w;
    }
    *(float4*)&Y[(size_t)row * Dc + tid * 4] = o;
}

// ---------------- small elementwise helpers ----------------
__global__ void concat_kernel(const float* __restrict__ mem, const float* __restrict__ xn,
                              float* __restrict__ h)
{
    size_t idx = (size_t)blockIdx.x * 256 + threadIdx.x;
    int d = idx & (Dc - 1);
    size_t r = idx >> 10;
    int t = r & (Stc - 1);
    int b = (int)(r >> 11);
    h[idx] = (t < Mc) ? mem[((size_t)b * Mc + t) * Dc + d]
                      : xn[((size_t)b * Sc + (t - Mc)) * Dc + d];
}

// split heads: q[z,i,d] = Qt[b,i,h*64+d] + u ; q2 = ... + v   (u/v/q2 nullable)
__global__ void qprep_kernel(const float* __restrict__ Qt, const float* __restrict__ uu,
                             const float* __restrict__ vv, float* __restrict__ q,
                             float* __restrict__ q2)
{
    size_t idx = (size_t)blockIdx.x * 256 + threadIdx.x;
    int hd = idx & (Dc - 1);
    size_t r = idx >> 10;
    int i = r & (Sc - 1);
    int b = (int)(r >> 10);
    int h = hd >> 6, d = hd & 63;
    float val = Qt[idx];
    size_t o = (((size_t)(b * Hc + h)) * Sc + i) * DHc + d;
    q[o] = val + (uu ? uu[hd] : 0.f);
    if (q2) q2[o] = val + vv[hd];
}

__global__ void kvsplit_kernel(const float* __restrict__ kv, float* __restrict__ k,
                               float* __restrict__ v, int Sk)
{
    size_t idx = (size_t)blockIdx.x * 256 + threadIdx.x;   // over B*Sk*Dc
    int hd = idx & (Dc - 1);
    size_t r = idx >> 10;
    int j = (int)(r % Sk);
    int b = (int)(r / Sk);
    int h = hd >> 6, d = hd & 63;
    size_t o = (((size_t)(b * Hc + h)) * Sk + j) * DHc + d;
    size_t src = ((size_t)(b * Sk + j)) * (2 * Dc);
    k[o] = kv[src + hd];
    v[o] = kv[src + Dc + hd];
}

// ---------------- host-side launcher ----------------
static inline float* sym(const void* s)
{
    void* p = nullptr;
    cudaGetSymbolAddress(&p, s);
    return (float*)p;
}

extern "C" void kernel_launch(void* const* d_in, const int* in_sizes, int n_in,
                              void* d_out, int out_size)
{
    const float* x     = (const float*)d_in[0];
    const float* enc   = (const float*)d_in[1];
    const float* pemb  = (const float*)d_in[2];
    const float* u     = (const float*)d_in[3];
    const float* vvec  = (const float*)d_in[4];
    const float* mem   = (const float*)d_in[5];
    // d_in[6] = tgt_mask (bool) — recomputed analytically: mask(i,j) = j > i+M
    const float* Wq_m  = (const float*)d_in[7];
    const float* Wkv_m = (const float*)d_in[8];
    const float* fcw_m = (const float*)d_in[9];
    const float* fcb_m = (const float*)d_in[10];
    const float* lnm_g = (const float*)d_in[11];
    const float* lnm_b = (const float*)d_in[12];
    const float* Wq_c  = (const float*)d_in[13];
    const float* Wkv_c = (const float*)d_in[14];
    const float* fcw_c = (const float*)d_in[15];
    const float* fcb_c = (const float*)d_in[16];
    const float* lnc_g = (const float*)d_in[17];
    const float* lnc_b = (const float*)d_in[18];
    const float* W1    = (const float*)d_in[19];
    const float* b1    = (const float*)d_in[20];
    const float* W2    = (const float*)d_in[21];
    const float* b2    = (const float*)d_in[22];
    const float* ln1_g = (const float*)d_in[23];
    const float* ln1_b = (const float*)d_in[24];
    const float* ln2_g = (const float*)d_in[25];
    const float* ln2_b = (const float*)d_in[26];
    const float* ln3_g = (const float*)d_in[27];
    const float* ln3_b = (const float*)d_in[28];
    float* out = (float*)d_out;

    float* xn  = sym(g_xn);   float* hcat = sym(g_h);   float* qt = sym(g_qt);
    float* q   = sym(g_q);    float* q2   = sym(g_q2);  float* kv = sym(g_kv);
    float* kk  = sym(g_k);    float* vv   = sym(g_v);
    float* scs = sym(g_scb);  float* pss  = sym(g_psb);
    float* o   = sym(g_o);    float* tmp  = sym(g_tmp);
    float* o1  = sym(g_out);  float* o2   = sym(g_out2);
    float* ff  = sym(g_ff);

    const float scale = 0.125f;   // 1/sqrt(64)
    const int rowsBS = Bc * Sc;   // 2048

    // ===== pre-norm 1 =====
    ln_kernel<<<rowsBS, 256>>>(x, ln1_g, ln1_b, xn, nullptr);

    // ===== MHA (Transformer-XL relative attention) =====
    concat_kernel<<<(Bc * Stc * Dc) / 256, 256>>>(mem, xn, hcat);
    sgemm128<0><<<dim3(Dc / 128, rowsBS / 128), 256>>>(xn, Wq_m, qt, rowsBS, Dc, Dc, nullptr, nullptr);
    qprep_kernel<<<(Bc * Sc * Dc) / 256, 256>>>(qt, u, vvec, q, q2);
    sgemm128<0><<<dim3((2 * Dc) / 128, (Bc * Stc) / 128), 256>>>(hcat, Wkv_m, kv, Bc * Stc, 2 * Dc, Dc, nullptr, nullptr);
    kvsplit_kernel<<<(Bc * Stc * Dc) / 256, 256>>>(kv, kk, vv, Stc);

    qk_kernel<false><<<dim3(Stc / 64, Sc / 64, Zc), 256>>>(q, kk, scs, Sc, Stc);   // content
    qk_kernel<true ><<<dim3(Stc / 64, Sc / 64, Zc), 256>>>(q2, pemb, pss, Sc, Stc); // position
    logits_kernel<<<(int)(((size_t)Zc * Sc * Stc) / 256), 256>>>(scs, pss);
    softmax_i<<<(Zc * Stc) / 256, 256>>>(scs, Sc, Stc, scale, Zc * Stc);
    av_kernel<<<dim3(Sc / 64, Zc), 256>>>(scs, vv, o, Sc, Stc);

    sgemm128<0><<<dim3(Dc / 128, rowsBS / 128), 256>>>(o, fcw_m, tmp, rowsBS, Dc, Dc, fcb_m, xn);
    ln_kernel<<<rowsBS, 256>>>(tmp, lnm_g, lnm_b, o1, x);          // out = x + LN(...)

    // ===== cross attention =====
    ln_kernel<<<rowsBS, 256>>>(o1, ln2_g, ln2_b, xn, nullptr);     // xn = LN(out)
    sgemm128<0><<<dim3(Dc / 128, rowsBS / 128), 256>>>(xn, Wq_c, qt, rowsBS, Dc, Dc, nullptr, nullptr);
    qprep_kernel<<<(Bc * Sc * Dc) / 256, 256>>>(qt, nullptr, nullptr, q, nullptr);
    sgemm128<0><<<dim3((2 * Dc) / 128, rowsBS / 128), 256>>>(enc, Wkv_c, kv, rowsBS, 2 * Dc, Dc, nullptr, nullptr);
    kvsplit_kernel<<<(Bc * Sc * Dc) / 256, 256>>>(kv, kk, vv, Sc);

    qk_kernel<false><<<dim3(Sc / 64, Sc / 64, Zc), 256>>>(q, kk, scs, Sc, Sc);
    softmax_i<<<(Zc * Sc) / 256, 256>>>(scs, Sc, Sc, scale, Zc * Sc);
    av_kernel<<<dim3(Sc / 64, Zc), 256>>>(scs, vv, o, Sc, Sc);

    sgemm128<0><<<dim3(Dc / 128, rowsBS / 128), 256>>>(o, fcw_c, tmp, rowsBS, Dc, Dc, fcb_c, xn);
    ln_kernel<<<rowsBS, 256>>>(tmp, lnc_g, lnc_b, o2, o1);         // out2 = out + LN(...)

    // ===== FFN =====
    ln_kernel<<<rowsBS, 256>>>(o2, ln3_g, ln3_b, xn, nullptr);     // xn = LN(out2)
    sgemm128<1><<<dim3(DFFc / 128, rowsBS / 128), 256>>>(xn, W1, ff, rowsBS, DFFc, Dc, b1, nullptr); // gelu
    sgemm128<0><<<dim3(Dc / 128, rowsBS / 128), 256>>>(ff, W2, out, rowsBS, Dc, DFFc, b2, o2);       // + out2
}

// round 2
// speedup vs baseline: 1.9778x; 1.9778x over previous
#include <cuda_runtime.h>
#include <math.h>
#include <stdint.h>

#define Bc 2
#define Sc 1024
#define Mc 1024
#define Dc 1024
#define Hc 16
#define DHc 64
#define DFFc 4096
#define Stc 2048
#define Zc (Bc*Hc)

// ---------------- scratch (device globals: no allocation allowed) ----------------
__device__ float g_xn [Bc*Sc*Dc];
__device__ float g_h  [Bc*Stc*Dc];
__device__ float g_qt [Bc*Sc*Dc];
__device__ float g_q  [Zc*Sc*DHc];
__device__ float g_q2 [Zc*Sc*DHc];
__device__ float g_kv [Bc*Stc*2*Dc];
__device__ float g_k  [Zc*Stc*DHc];
__device__ float g_v  [Zc*Stc*DHc];
__device__ float g_scb[(size_t)Zc*Sc*Stc];   // scores (logits / probs)
__device__ float g_psb[(size_t)Zc*Sc*Stc];   // raw pos scores
__device__ float g_o  [Bc*Sc*Dc];
__device__ float g_tmp[Bc*Sc*Dc];
__device__ float g_out[Bc*Sc*Dc];
__device__ float g_out2[Bc*Sc*Dc];
__device__ float g_ff [(size_t)Bc*Sc*DFFc];

// ---------------- tf32 mma helpers ----------------
__device__ __forceinline__ uint32_t f2tf(float f) {
    uint32_t r;
    asm("cvt.rna.tf32.f32 %0, %1;" : "=r"(r) : "f"(f));
    return r;
}

__device__ __forceinline__ void mma8(float* c, const uint32_t* a, const uint32_t* b) {
    asm volatile(
        "mma.sync.aligned.m16n8k8.row.col.f32.tf32.tf32.f32 "
        "{%0,%1,%2,%3}, {%4,%5,%6,%7}, {%8,%9}, {%0,%1,%2,%3};\n"
        : "+f"(c[0]), "+f"(c[1]), "+f"(c[2]), "+f"(c[3])
        : "r"(a[0]), "r"(a[1]), "r"(a[2]), "r"(a[3]), "r"(b[0]), "r"(b[1]));
}

// ---------------- dense GEMM (tf32 tensor cores): C = act(A@B + bias) + Res ----
// A: Mr x K row-major, B: K x N row-major. Tiles 128x128x32, 256 thr, 8 warps 2x4.
template<int ACT>
__global__ void gemm_tf32(const float* __restrict__ A, const float* __restrict__ Bm,
                          float* __restrict__ C, int Mr, int N, int K,
                          const float* __restrict__ bias, const float* __restrict__ Res)
{
    __shared__ uint32_t As[128][36];   // bank(r*36+k) = 4r+k : conflict-free frags
    __shared__ uint32_t Bs[32][136];   // bank(k*136+n) = 8k+n : conflict-free frags
    const int tid = threadIdx.x;
    const int lane = tid & 31, wid = tid >> 5;
    const int wm = wid & 1, wn = wid >> 1;        // warp tile: rows wm*64, cols wn*32
    const int lr = lane >> 2, lc = lane & 3;
    const int row0 = blockIdx.y * 128, col0 = blockIdx.x * 128;

    float acc[4][4][4];
#pragma unroll
    for (int mt = 0; mt < 4; mt++)
#pragma unroll
        for (int nt = 0; nt < 4; nt++)
#pragma unroll
            for (int e = 0; e < 4; e++) acc[mt][nt][e] = 0.f;

    for (int k0 = 0; k0 < K; k0 += 32) {
#pragma unroll
        for (int it = 0; it < 4; it++) {
            int lin = tid + it * 256;
            int r = lin >> 3, k4 = (lin & 7) * 4;
            float4 v = *(const float4*)&A[(size_t)(row0 + r) * K + k0 + k4];
            uint4 t = { f2tf(v.x), f2tf(v.y), f2tf(v.z), f2tf(v.w) };
            *(uint4*)&As[r][k4] = t;
        }
#pragma unroll
        for (int it = 0; it < 4; it++) {
            int lin = tid + it * 256;
            int r = lin >> 5, n4 = (lin & 31) * 4;
            float4 v = *(const float4*)&Bm[(size_t)(k0 + r) * N + col0 + n4];
            uint4 t = { f2tf(v.x), f2tf(v.y), f2tf(v.z), f2tf(v.w) };
            *(uint4*)&Bs[r][n4] = t;
        }
        __syncthreads();
#pragma unroll
        for (int k8 = 0; k8 < 32; k8 += 8) {
            uint32_t a[4][4], b[4][2];
#pragma unroll
            for (int mt = 0; mt < 4; mt++) {
                int r = wm * 64 + mt * 16 + lr;
                a[mt][0] = As[r][k8 + lc];
                a[mt][1] = As[r + 8][k8 + lc];
                a[mt][2] = As[r][k8 + lc + 4];
                a[mt][3] = As[r + 8][k8 + lc + 4];
            }
#pragma unroll
            for (int nt = 0; nt < 4; nt++) {
                int c = wn * 32 + nt * 8 + lr;
                b[nt][0] = Bs[k8 + lc][c];
                b[nt][1] = Bs[k8 + lc + 4][c];
            }
#pragma unroll
            for (int mt = 0; mt < 4; mt++)
#pragma unroll
                for (int nt = 0; nt < 4; nt++)
                    mma8(acc[mt][nt], a[mt], b[nt]);
        }
        __syncthreads();
    }

#pragma unroll
    for (int mt = 0; mt < 4; mt++)
#pragma unroll
        for (int nt = 0; nt < 4; nt++) {
            int r_ = row0 + wm * 64 + mt * 16 + lr;
            int c_ = col0 + wn * 32 + nt * 8 + 2 * lc;
#pragma unroll
            for (int hf = 0; hf < 2; hf++) {
                int rr = r_ + hf * 8;
                float v0 = acc[mt][nt][hf * 2 + 0];
                float v1 = acc[mt][nt][hf * 2 + 1];
                if (bias) { v0 += bias[c_]; v1 += bias[c_ + 1]; }
                if (ACT == 1) {
                    v0 = 0.5f * v0 * (1.0f + erff(v0 * 0.70710678118654752f));
                    v1 = 0.5f * v1 * (1.0f + erff(v1 * 0.70710678118654752f));
                }
                if (Res) {
                    v0 += Res[(size_t)rr * N + c_];
                    v1 += Res[(size_t)rr * N + c_ + 1];
                }
                C[(size_t)rr * N + c_]     = v0;
                C[(size_t)rr * N + c_ + 1] = v1;
            }
        }
}

// ---------------- QK^T (tf32): Out[z,i,j] = sum_d Q[z,i,d]*K[.,j,d] ----------------
// POS: K source is pos_emb (row stride Dc, head-offset slice).
// RELS: fused rel_shift(+pos) + causal mask epilogue (self-attn content path).
template<int POS, int RELS>
__global__ void qk_tf32(const float* __restrict__ Q, const float* __restrict__ Kp,
                        const float* __restrict__ Ppos, float* __restrict__ Out,
                        int Srows, int Sk)
{
    __shared__ uint32_t Qs[128][36];
    __shared__ uint32_t Ks[128][36];   // [j][d] : natural col-major B fragment
    const int tid = threadIdx.x;
    const int lane = tid & 31, wid = tid >> 5;
    const int wm = wid & 1, wn = wid >> 1;
    const int lr = lane >> 2, lc = lane & 3;
    const int z = blockIdx.z;
    const int j0 = blockIdx.x * 128, i0 = blockIdx.y * 128;

    const float* Kbase = POS ? (Kp + (z & 15) * DHc) : (Kp + (size_t)z * Sk * DHc);
    const int ldk = POS ? Dc : DHc;
    const float* Qbase = Q + ((size_t)z * Srows + i0) * DHc;

    float acc[4][4][4];
#pragma unroll
    for (int mt = 0; mt < 4; mt++)
#pragma unroll
        for (int nt = 0; nt < 4; nt++)
#pragma unroll
            for (int e = 0; e < 4; e++) acc[mt][nt][e] = 0.f;

#pragma unroll
    for (int d0 = 0; d0 < DHc; d0 += 32) {
#pragma unroll
        for (int it = 0; it < 4; it++) {
            int lin = tid + it * 256;
            int r = lin >> 3, k4 = (lin & 7) * 4;
            float4 v = *(const float4*)&Qbase[(size_t)r * DHc + d0 + k4];
            uint4 t = { f2tf(v.x), f2tf(v.y), f2tf(v.z), f2tf(v.w) };
            *(uint4*)&Qs[r][k4] = t;
        }
#pragma unroll
        for (int it = 0; it < 4; it++) {
            int lin = tid + it * 256;
            int r = lin >> 3, k4 = (lin & 7) * 4;
            float4 v = *(const float4*)&Kbase[(size_t)(j0 + r) * ldk + d0 + k4];
            uint4 t = { f2tf(v.x), f2tf(v.y), f2tf(v.z), f2tf(v.w) };
            *(uint4*)&Ks[r][k4] = t;
        }
        __syncthreads();
#pragma unroll
        for (int k8 = 0; k8 < 32; k8 += 8) {
            uint32_t a[4][4], b[4][2];
#pragma unroll
            for (int mt = 0; mt < 4; mt++) {
                int r = wm * 64 + mt * 16 + lr;
                a[mt][0] = Qs[r][k8 + lc];
                a[mt][1] = Qs[r + 8][k8 + lc];
                a[mt][2] = Qs[r][k8 + lc + 4];
                a[mt][3] = Qs[r + 8][k8 + lc + 4];
            }
#pragma unroll
            for (int nt = 0; nt < 4; nt++) {
                int c = wn * 32 + nt * 8 + lr;
                b[nt][0] = Ks[c][k8 + lc];
                b[nt][1] = Ks[c][k8 + lc + 4];
            }
#pragma unroll
            for (int mt = 0; mt < 4; mt++)
#pragma unroll
                for (int nt = 0; nt < 4; nt++)
                    mma8(acc[mt][nt], a[mt], b[nt]);
        }
        __syncthreads();
    }

    const int bb = z >> 4, hh = z & 15;
#pragma unroll
    for (int mt = 0; mt < 4; mt++)
#pragma unroll
        for (int nt = 0; nt < 4; nt++) {
            int i_ = i0 + wm * 64 + mt * 16 + lr;
            int j_ = j0 + wn * 32 + nt * 8 + 2 * lc;
#pragma unroll
            for (int hf = 0; hf < 2; hf++) {
                int ii = i_ + hf * 8;
#pragma unroll
                for (int e = 0; e < 2; e++) {
                    int jj = j_ + e;
                    float val = acc[mt][nt][hf * 2 + e];
                    if (RELS) {
                        // exact flat-index algebra of the jax pad+reshape rel_shift
                        int t  = bb * Sc + ii + Bc;
                        int bp = t / (Sc + 1);
                        int i1 = t % (Sc + 1);
                        if (i1 > 0)
                            val += Ppos[(((size_t)(bp * Hc + hh)) * Sc + (i1 - 1)) * Stc + jj];
                        if (jj > ii + Mc) val = -1e30f;   // mask BEFORE scale
                    }
                    Out[((size_t)z * Srows + ii) * Sk + jj] = val;
                }
            }
        }
}

// ---------------- AV (tf32): O[b,i,h*64+d] = sum_j P[z,i,j]*V[z,j,d] --------------
__global__ void av_tf32(const float* __restrict__ P, const float* __restrict__ V,
                        float* __restrict__ O, int Srows, int Sk)
{
    __shared__ uint32_t Ps[128][36];
    __shared__ uint32_t Vs[32][72];
    const int tid = threadIdx.x;
    const int lane = tid & 31, wid = tid >> 5;
    const int wm = wid >> 1, wn = wid & 1;    // 4 x 2 warps: 32 rows x 32 cols each
    const int lr = lane >> 2, lc = lane & 3;
    const int z = blockIdx.y;
    const int i0 = blockIdx.x * 128;

    float acc[2][4][4];
#pragma unroll
    for (int mt = 0; mt < 2; mt++)
#pragma unroll
        for (int nt = 0; nt < 4; nt++)
#pragma unroll
            for (int e = 0; e < 4; e++) acc[mt][nt][e] = 0.f;

    for (int j0 = 0; j0 < Sk; j0 += 32) {
#pragma unroll
        for (int it = 0; it < 4; it++) {
            int lin = tid + it * 256;
            int r = lin >> 3, k4 = (lin & 7) * 4;
            float4 v = *(const float4*)&P[((size_t)z * Srows + i0 + r) * Sk + j0 + k4];
            uint4 t = { f2tf(v.x), f2tf(v.y), f2tf(v.z), f2tf(v.w) };
            *(uint4*)&Ps[r][k4] = t;
        }
#pragma unroll
        for (int it = 0; it < 2; it++) {
            int lin = tid + it * 256;
            int r = lin >> 4, n4 = (lin & 15) * 4;
            float4 v = *(const float4*)&V[((size_t)z * Sk + j0 + r) * DHc + n4];
            uint4 t = { f2tf(v.x), f2tf(v.y), f2tf(v.z), f2tf(v.w) };
            *(uint4*)&Vs[r][n4] = t;
        }
        __syncthreads();
#pragma unroll
        for (int k8 = 0; k8 < 32; k8 += 8) {
            uint32_t a[2][4], b[4][2];
#pragma unroll
            for (int mt = 0; mt < 2; mt++) {
                int r = wm * 32 + mt * 16 + lr;
                a[mt][0] = Ps[r][k8 + lc];
                a[mt][1] = Ps[r + 8][k8 + lc];
                a[mt][2] = Ps[r][k8 + lc + 4];
                a[mt][3] = Ps[r + 8][k8 + lc + 4];
            }
#pragma unroll
            for (int nt = 0; nt < 4; nt++) {
                int c = wn * 32 + nt * 8 + lr;
                b[nt][0] = Vs[k8 + lc][c];
                b[nt][1] = Vs[k8 + lc + 4][c];
            }
#pragma unroll
            for (int mt = 0; mt < 2; mt++)
#pragma unroll
                for (int nt = 0; nt < 4; nt++)
                    mma8(acc[mt][nt], a[mt], b[nt]);
        }
        __syncthreads();
    }

    const int bb = z >> 4, hh = z & 15;
#pragma unroll
    for (int mt = 0; mt < 2; mt++)
#pragma unroll
        for (int nt = 0; nt < 4; nt++) {
            int i_ = i0 + wm * 32 + mt * 16 + lr;
            int d_ = wn * 32 + nt * 8 + 2 * lc;
#pragma unroll
            for (int hf = 0; hf < 2; hf++) {
                int ii = i_ + hf * 8;
                size_t o = ((size_t)(bb * Sc) + ii) * Dc + hh * DHc + d_;
                O[o]     = acc[mt][nt][hf * 2 + 0];
                O[o + 1] = acc[mt][nt][hf * 2 + 1];
            }
        }
}

// ---------------- softmax over i (query axis), per (z,j) column, online ----------
__global__ void softmax_i(float* __restrict__ P, int Srows, int Sk, float scale, int cols)
{
    int col = blockIdx.x * blockDim.x + threadIdx.x;
    if (col >= cols) return;
    int z = col / Sk, j = col % Sk;
    float* base = P + (size_t)z * Srows * Sk + j;
    float m = -3.4e38f, s = 0.f;
    for (int i = 0; i < Srows; i++) {
        float v = base[(size_t)i * Sk] * scale;
        if (v > m) { s = s * __expf(m - v) + 1.f; m = v; }
        else         s += __expf(v - m);
    }
    float inv = 1.f / s;
    for (int i = 0; i < Srows; i++)
        base[(size_t)i * Sk] = __expf(base[(size_t)i * Sk] * scale - m) * inv;
}

// ---------------- LayerNorm (row = D), optional residual AFTER the LN ----------------
__global__ void ln_kernel(const float* __restrict__ X, const float* __restrict__ gw,
                          const float* __restrict__ bw, float* __restrict__ Y,
                          const float* __restrict__ Res)
{
    __shared__ float s1[256], s2[256];
    const int row = blockIdx.x;
    const int tid = threadIdx.x;
    const float* x = X + (size_t)row * Dc;
    float4 v = *(const float4*)&x[tid * 4];
    s1[tid] = v.x + v.y + v.z + v.w;
    s2[tid] = v.x * v.x + v.y * v.y + v.z * v.z + v.w * v.w;
    __syncthreads();
    for (int st = 128; st > 0; st >>= 1) {
        if (tid < st) { s1[tid] += s1[tid + st]; s2[tid] += s2[tid + st]; }
        __syncthreads();
    }
    float mu = s1[0] * (1.f / Dc);
    float var = s2[0] * (1.f / Dc) - mu * mu;
    float rinv = rsqrtf(var + 1e-5f);
    float4 g4 = *(const float4*)&gw[tid * 4];
    float4 b4 = *(const float4*)&bw[tid * 4];
    float4 o;
    o.x = (v.x - mu) * rinv * g4.x + b4.x;
    o.y = (v.y - mu) * rinv * g4.y + b4.y;
    o.z = (v.z - mu) * rinv * g4.z + b4.z;
    o.w = (v.w - mu) * rinv * g4.w + b4.w;
    if (Res) {
        float4 r4 = *(const float4*)&Res[(size_t)row * Dc + tid * 4];
        o.x += r4.x; o.y += r4.y; o.z += r4.z; o.w += r4.w;
    }
    *(float4*)&Y[(size_t)row * Dc + tid * 4] = o;
}

// ---------------- small elementwise helpers ----------------
__global__ void concat_kernel(const float* __restrict__ mem, const float* __restrict__ xn,
                              float* __restrict__ h)
{
    size_t idx = (size_t)blockIdx.x * 256 + threadIdx.x;
    int d = idx & (Dc - 1);
    size_t r = idx >> 10;
    int t = r & (Stc - 1);
    int b = (int)(r >> 11);
    h[idx] = (t < Mc) ? mem[((size_t)b * Mc + t) * Dc + d]
                      : xn[((size_t)b * Sc + (t - Mc)) * Dc + d];
}

__global__ void qprep_kernel(const float* __restrict__ Qt, const float* __restrict__ uu,
                             const float* __restrict__ vv, float* __restrict__ q,
                             float* __restrict__ q2)
{
    size_t idx = (size_t)blockIdx.x * 256 + threadIdx.x;
    int hd = idx & (Dc - 1);
    size_t r = idx >> 10;
    int i = r & (Sc - 1);
    int b = (int)(r >> 10);
    int h = hd >> 6, d = hd & 63;
    float val = Qt[idx];
    size_t o = (((size_t)(b * Hc + h)) * Sc + i) * DHc + d;
    q[o] = val + (uu ? uu[hd] : 0.f);
    if (q2) q2[o] = val + vv[hd];
}

__global__ void kvsplit_kernel(const float* __restrict__ kv, float* __restrict__ k,
                               float* __restrict__ v, int Sk)
{
    size_t idx = (size_t)blockIdx.x * 256 + threadIdx.x;   // over B*Sk*Dc
    int hd = idx & (Dc - 1);
    size_t r = idx >> 10;
    int j = (int)(r % Sk);
    int b = (int)(r / Sk);
    int h = hd >> 6, d = hd & 63;
    size_t o = (((size_t)(b * Hc + h)) * Sk + j) * DHc + d;
    size_t src = ((size_t)(b * Sk + j)) * (2 * Dc);
    k[o] = kv[src + hd];
    v[o] = kv[src + Dc + hd];
}

// ---------------- host-side launcher ----------------
static inline float* sym(const void* s)
{
    void* p = nullptr;
    cudaGetSymbolAddress(&p, s);
    return (float*)p;
}

extern "C" void kernel_launch(void* const* d_in, const int* in_sizes, int n_in,
                              void* d_out, int out_size)
{
    const float* x     = (const float*)d_in[0];
    const float* enc   = (const float*)d_in[1];
    const float* pemb  = (const float*)d_in[2];
    const float* u     = (const float*)d_in[3];
    const float* vvec  = (const float*)d_in[4];
    const float* mem   = (const float*)d_in[5];
    // d_in[6] = tgt_mask (bool) — recomputed analytically: mask(i,j) = j > i+M
    const float* Wq_m  = (const float*)d_in[7];
    const float* Wkv_m = (const float*)d_in[8];
    const float* fcw_m = (const float*)d_in[9];
    const float* fcb_m = (const float*)d_in[10];
    const float* lnm_g = (const float*)d_in[11];
    const float* lnm_b = (const float*)d_in[12];
    const float* Wq_c  = (const float*)d_in[13];
    const float* Wkv_c = (const float*)d_in[14];
    const float* fcw_c = (const float*)d_in[15];
    const float* fcb_c = (const float*)d_in[16];
    const float* lnc_g = (const float*)d_in[17];
    const float* lnc_b = (const float*)d_in[18];
    const float* W1    = (const float*)d_in[19];
    const float* b1    = (const float*)d_in[20];
    const float* W2    = (const float*)d_in[21];
    const float* b2    = (const float*)d_in[22];
    const float* ln1_g = (const float*)d_in[23];
    const float* ln1_b = (const float*)d_in[24];
    const float* ln2_g = (const float*)d_in[25];
    const float* ln2_b = (const float*)d_in[26];
    const float* ln3_g = (const float*)d_in[27];
    const float* ln3_b = (const float*)d_in[28];
    float* out = (float*)d_out;

    float* xn  = sym(g_xn);   float* hcat = sym(g_h);   float* qt = sym(g_qt);
    float* q   = sym(g_q);    float* q2   = sym(g_q2);  float* kv = sym(g_kv);
    float* kk  = sym(g_k);    float* vv   = sym(g_v);
    float* scs = sym(g_scb);  float* pss  = sym(g_psb);
    float* o   = sym(g_o);    float* tmp  = sym(g_tmp);
    float* o1  = sym(g_out);  float* o2   = sym(g_out2);
    float* ff  = sym(g_ff);

    const float scale = 0.125f;   // 1/sqrt(64)
    const int rowsBS = Bc * Sc;   // 2048

    // ===== pre-norm 1 =====
    ln_kernel<<<rowsBS, 256>>>(x, ln1_g, ln1_b, xn, nullptr);

    // ===== MHA (Transformer-XL relative attention) =====
    concat_kernel<<<(Bc * Stc * Dc) / 256, 256>>>(mem, xn, hcat);
    gemm_tf32<0><<<dim3(Dc / 128, rowsBS / 128), 256>>>(xn, Wq_m, qt, rowsBS, Dc, Dc, nullptr, nullptr);
    qprep_kernel<<<(Bc * Sc * Dc) / 256, 256>>>(qt, u, vvec, q, q2);
    gemm_tf32<0><<<dim3((2 * Dc) / 128, (Bc * Stc) / 128), 256>>>(hcat, Wkv_m, kv, Bc * Stc, 2 * Dc, Dc, nullptr, nullptr);
    kvsplit_kernel<<<(Bc * Stc * Dc) / 256, 256>>>(kv, kk, vv, Stc);

    // pos scores first (content epilogue reads them via rel_shift)
    qk_tf32<1, 0><<<dim3(Stc / 128, Sc / 128, Zc), 256>>>(q2, pemb, nullptr, pss, Sc, Stc);
    // content + fused rel_shift + mask
    qk_tf32<0, 1><<<dim3(Stc / 128, Sc / 128, Zc), 256>>>(q, kk, pss, scs, Sc, Stc);
    softmax_i<<<(Zc * Stc) / 256, 256>>>(scs, Sc, Stc, scale, Zc * Stc);
    av_tf32<<<dim3(Sc / 128, Zc), 256>>>(scs, vv, o, Sc, Stc);

    gemm_tf32<0><<<dim3(Dc / 128, rowsBS / 128), 256>>>(o, fcw_m, tmp, rowsBS, Dc, Dc, fcb_m, xn);
    ln_kernel<<<rowsBS, 256>>>(tmp, lnm_g, lnm_b, o1, x);          // out = x + LN(...)

    // ===== cross attention =====
    ln_kernel<<<rowsBS, 256>>>(o1, ln2_g, ln2_b, xn, nullptr);     // xn = LN(out)
    gemm_tf32<0><<<dim3(Dc / 128, rowsBS / 128), 256>>>(xn, Wq_c, qt, rowsBS, Dc, Dc, nullptr, nullptr);
    qprep_kernel<<<(Bc * Sc * Dc) / 256, 256>>>(qt, nullptr, nullptr, q, nullptr);
    gemm_tf32<0><<<dim3((2 * Dc) / 128, rowsBS / 128), 256>>>(enc, Wkv_c, kv, rowsBS, 2 * Dc, Dc, nullptr, nullptr);
    kvsplit_kernel<<<(Bc * Sc * Dc) / 256, 256>>>(kv, kk, vv, Sc);

    qk_tf32<0, 0><<<dim3(Sc / 128, Sc / 128, Zc), 256>>>(q, kk, nullptr, scs, Sc, Sc);
    softmax_i<<<(Zc * Sc) / 256, 256>>>(scs, Sc, Sc, scale, Zc * Sc);
    av_tf32<<<dim3(Sc / 128, Zc), 256>>>(scs, vv, o, Sc, Sc);

    gemm_tf32<0><<<dim3(Dc / 128, rowsBS / 128), 256>>>(o, fcw_c, tmp, rowsBS, Dc, Dc, fcb_c, xn);
    ln_kernel<<<rowsBS, 256>>>(tmp, lnc_g, lnc_b, o2, o1);         // out2 = out + LN(...)

    // ===== FFN =====
    ln_kernel<<<rowsBS, 256>>>(o2, ln3_g, ln3_b, xn, nullptr);     // xn = LN(out2)
    gemm_tf32<1><<<dim3(DFFc / 128, rowsBS / 128), 256>>>(xn, W1, ff, rowsBS, DFFc, Dc, b1, nullptr); // gelu
    gemm_tf32<0><<<dim3(Dc / 128, rowsBS / 128), 256>>>(ff, W2, out, rowsBS, Dc, DFFc, b2, o2);       // + out2
}

// round 4
// speedup vs baseline: 2.4315x; 1.2294x over previous
#include <cuda_runtime.h>
#include <math.h>
#include <stdint.h>

#define Bc 2
#define Sc 1024
#define Mc 1024
#define Dc 1024
#define Hc 16
#define DHc 64
#define DFFc 4096
#define Stc 2048
#define Zc (Bc*Hc)
#define MEG (1024*1024)

// ---------------- scratch (device globals: no allocation allowed) ----------------
__device__ float g_xn [Bc*Sc*Dc];            // exact LN output (residual use)
__device__ float g_xnr[Bc*Sc*Dc];            // tf32-rounded LN output (GEMM use)
__device__ float g_h  [Bc*Stc*Dc];           // concat(mem, xn) rounded
__device__ float g_q  [Zc*Sc*DHc];
__device__ float g_q2 [Zc*Sc*DHc];
__device__ float g_k  [(size_t)Zc*Stc*DHc];
__device__ float g_v  [(size_t)Zc*Stc*DHc];
__device__ float g_scb[(size_t)Zc*Sc*Stc];   // logits / probs
__device__ float g_o  [Bc*Sc*Dc];
__device__ float g_tmp[Bc*Sc*Dc];
__device__ float g_out[Bc*Sc*Dc];
__device__ float g_out2[Bc*Sc*Dc];
__device__ float g_ff [(size_t)Bc*Sc*DFFc];
__device__ float g_wts[20*MEG];              // rounded weights/pemb/enc

// offsets into g_wts (floats)
#define OFF_WQ_M   0
#define OFF_WKV_M  (1*MEG)
#define OFF_FCW_M  (3*MEG)
#define OFF_WQ_C   (4*MEG)
#define OFF_WKV_C  (5*MEG)
#define OFF_FCW_C  (7*MEG)
#define OFF_W1     (8*MEG)
#define OFF_W2     (12*MEG)
#define OFF_PEMB   (16*MEG)
#define OFF_ENC    (18*MEG)

// ---------------- helpers ----------------
__device__ __forceinline__ uint32_t f2tf(float f) {
    uint32_t r;
    asm("cvt.rna.tf32.f32 %0, %1;" : "=r"(r) : "f"(f));
    return r;
}
__device__ __forceinline__ float rnd_tf(float f) { return __uint_as_float(f2tf(f)); }

__device__ __forceinline__ void cpa16(uint32_t dst, const void* src) {
    asm volatile("cp.async.cg.shared.global [%0], [%1], 16;\n" :: "r"(dst), "l"(src));
}
__device__ __forceinline__ void cpa16z(uint32_t dst, const void* src, int srcbytes) {
    asm volatile("cp.async.cg.shared.global [%0], [%1], 16, %2;\n"
                 :: "r"(dst), "l"(src), "r"(srcbytes));
}
#define CP_COMMIT() asm volatile("cp.async.commit_group;\n")
#define CP_WAIT0()  asm volatile("cp.async.wait_group 0;\n")
#define CP_WAIT1()  asm volatile("cp.async.wait_group 1;\n")

__device__ __forceinline__ void mma8(float* c, const uint32_t* a, const uint32_t* b) {
    asm volatile(
        "mma.sync.aligned.m16n8k8.row.col.f32.tf32.tf32.f32 "
        "{%0,%1,%2,%3}, {%4,%5,%6,%7}, {%8,%9}, {%0,%1,%2,%3};\n"
        : "+f"(c[0]), "+f"(c[1]), "+f"(c[2]), "+f"(c[3])
        : "r"(a[0]), "r"(a[1]), "r"(a[2]), "r"(a[3]), "r"(b[0]), "r"(b[1]));
}

// ---------------- weight pre-round ----------------
__global__ void round_copy(const float4* __restrict__ src, float4* __restrict__ dst, int n4)
{
    int i = blockIdx.x * 256 + threadIdx.x;
    if (i < n4) {
        float4 v = src[i];
        float4 o = { rnd_tf(v.x), rnd_tf(v.y), rnd_tf(v.z), rnd_tf(v.w) };
        dst[i] = o;
    }
}

// ---------------- dense GEMM, cp.async double-buffered, tf32 MMA ----------------
// A: rows x K row-major (pre-rounded). B: K x N (pre-rounded). Tiles 128x128x32.
// EPI=0: C = [RND](act(A@B + bias) + Res)
// EPI=1: head-split q write: C[bhid]=rnd(v+bias), C2[bhid]=rnd(v+bias2) (nullable)
// EPI=2: kv split: col<1024 -> C (k), else C2 (v); rounded
template<int ACT, int EPI, int RND>
__global__ void __launch_bounds__(256, 2)
gemm_tf32(const float* __restrict__ A, const float* __restrict__ Bm,
          float* __restrict__ C, float* __restrict__ C2,
          int N, int K, const float* __restrict__ bias, const float* __restrict__ bias2,
          const float* __restrict__ Res, int Sk)
{
    extern __shared__ float sm[];
    // As stage s at sm + s*4608 ([128][36]); Bs stage s at sm + 9216 + s*4352 ([32][136])
    const int tid = threadIdx.x, lane = tid & 31, wid = tid >> 5;
    const int wm = wid & 1, wn = wid >> 1;
    const int lr = lane >> 2, lc = lane & 3;
    const int row0 = blockIdx.y * 128, col0 = blockIdx.x * 128;
    const uint32_t smb = (uint32_t)__cvta_generic_to_shared(sm);

    float acc[4][4][4];
#pragma unroll
    for (int mt = 0; mt < 4; mt++)
#pragma unroll
        for (int nt = 0; nt < 4; nt++)
#pragma unroll
            for (int e = 0; e < 4; e++) acc[mt][nt][e] = 0.f;

    const int nk = K / 32;
    auto loadAB = [&](int s, int k0) {
#pragma unroll
        for (int it = 0; it < 4; it++) {
            int lin = tid + it * 256;
            int r = lin >> 3, k4 = (lin & 7) * 4;
            cpa16(smb + (uint32_t)(s * 4608 + r * 36 + k4) * 4,
                  &A[(size_t)(row0 + r) * K + k0 + k4]);
        }
#pragma unroll
        for (int it = 0; it < 4; it++) {
            int lin = tid + it * 256;
            int r = lin >> 5, n4 = (lin & 31) * 4;
            cpa16(smb + (uint32_t)(9216 + s * 4352 + r * 136 + n4) * 4,
                  &Bm[(size_t)(k0 + r) * N + col0 + n4]);
        }
        CP_COMMIT();
    };

    loadAB(0, 0);
    for (int kt = 0; kt < nk; kt++) {
        if (kt + 1 < nk) { loadAB((kt + 1) & 1, (kt + 1) * 32); CP_WAIT1(); }
        else             { CP_WAIT0(); }
        __syncthreads();
        const float* As = sm + (kt & 1) * 4608;
        const float* Bs = sm + 9216 + (kt & 1) * 4352;
#pragma unroll
        for (int k8 = 0; k8 < 32; k8 += 8) {
            uint32_t a[4][4], b[4][2];
#pragma unroll
            for (int mt = 0; mt < 4; mt++) {
                int r = wm * 64 + mt * 16 + lr;
                a[mt][0] = __float_as_uint(As[r * 36 + k8 + lc]);
                a[mt][1] = __float_as_uint(As[(r + 8) * 36 + k8 + lc]);
                a[mt][2] = __float_as_uint(As[r * 36 + k8 + lc + 4]);
                a[mt][3] = __float_as_uint(As[(r + 8) * 36 + k8 + lc + 4]);
            }
#pragma unroll
            for (int nt = 0; nt < 4; nt++) {
                int c = wn * 32 + nt * 8 + lr;
                b[nt][0] = __float_as_uint(Bs[(k8 + lc) * 136 + c]);
                b[nt][1] = __float_as_uint(Bs[(k8 + lc + 4) * 136 + c]);
            }
#pragma unroll
            for (int mt = 0; mt < 4; mt++)
#pragma unroll
                for (int nt = 0; nt < 4; nt++)
                    mma8(acc[mt][nt], a[mt], b[nt]);
        }
        __syncthreads();
    }

#pragma unroll
    for (int mt = 0; mt < 4; mt++)
#pragma unroll
        for (int nt = 0; nt < 4; nt++) {
            int r_ = row0 + wm * 64 + mt * 16 + lr;
            int c_ = col0 + wn * 32 + nt * 8 + 2 * lc;
#pragma unroll
            for (int hf = 0; hf < 2; hf++) {
                int rr = r_ + hf * 8;
                float v0 = acc[mt][nt][hf * 2 + 0];
                float v1 = acc[mt][nt][hf * 2 + 1];
                if (EPI == 0) {
                    if (bias) { v0 += bias[c_]; v1 += bias[c_ + 1]; }
                    if (ACT == 1) {
                        v0 = 0.5f * v0 * (1.0f + erff(v0 * 0.70710678118654752f));
                        v1 = 0.5f * v1 * (1.0f + erff(v1 * 0.70710678118654752f));
                    }
                    if (Res) {
                        v0 += Res[(size_t)rr * N + c_];
                        v1 += Res[(size_t)rr * N + c_ + 1];
                    }
                    if (RND) { v0 = rnd_tf(v0); v1 = rnd_tf(v1); }
                    C[(size_t)rr * N + c_]     = v0;
                    C[(size_t)rr * N + c_ + 1] = v1;
                } else if (EPI == 1) {
                    int b = rr >> 10, i = rr & 1023;
#pragma unroll
                    for (int e = 0; e < 2; e++) {
                        int cc = c_ + e;
                        int h = cc >> 6, d = cc & 63;
                        float val = e ? v1 : v0;
                        size_t dst = (((size_t)(b * Hc + h)) * Sc + i) * DHc + d;
                        C[dst] = rnd_tf(val + (bias ? bias[cc] : 0.f));
                        if (C2) C2[dst] = rnd_tf(val + bias2[cc]);
                    }
                } else { // EPI == 2
                    int b = rr / Sk, j = rr % Sk;
#pragma unroll
                    for (int e = 0; e < 2; e++) {
                        int cc = c_ + e;
                        int isv = cc >> 10;
                        int h = (cc & 1023) >> 6, d = cc & 63;
                        float val = e ? v1 : v0;
                        size_t dst = (((size_t)(b * Hc + h)) * Sk + j) * DHc + d;
                        (isv ? C2 : C)[dst] = rnd_tf(val);
                    }
                }
            }
        }
}

// ---------------- fused QK^T (+ shifted-pos + mask for self-attn) ----------------
// RELS=1: acc = Q·K^T + Q2shift·PE^T ; mask (j>i+M -> -1e30); write logits.
// RELS=0: acc = Q·K^T (cross attention).
template<int RELS>
__global__ void __launch_bounds__(256, 2)
qk_fused(const float* __restrict__ Q, const float* __restrict__ Q2,
         const float* __restrict__ Kk, const float* __restrict__ PE,
         float* __restrict__ Out, int Srows, int Sk)
{
    extern __shared__ float sm[];
    // Qs @0, Ks @4608, Q2s @9216, Ps @13824 — each [128][36]
    const int tid = threadIdx.x, lane = tid & 31, wid = tid >> 5;
    const int wm = wid & 1, wn = wid >> 1;
    const int lr = lane >> 2, lc = lane & 3;
    const int z = blockIdx.z;
    const int j0 = blockIdx.x * 128, i0 = blockIdx.y * 128;
    const int bb = z >> 4, hh = z & 15;
    const uint32_t smb = (uint32_t)__cvta_generic_to_shared(sm);

    float acc[4][4][4];
#pragma unroll
    for (int mt = 0; mt < 4; mt++)
#pragma unroll
        for (int nt = 0; nt < 4; nt++)
#pragma unroll
            for (int e = 0; e < 4; e++) acc[mt][nt][e] = 0.f;

#pragma unroll
    for (int d0 = 0; d0 < DHc; d0 += 32) {
#pragma unroll
        for (int it = 0; it < 4; it++) {
            int lin = tid + it * 256;
            int r = lin >> 3, k4 = (lin & 7) * 4;
            cpa16(smb + (uint32_t)(r * 36 + k4) * 4,
                  &Q[((size_t)z * Srows + i0 + r) * DHc + d0 + k4]);
            cpa16(smb + (uint32_t)(4608 + r * 36 + k4) * 4,
                  &Kk[((size_t)z * Sk + j0 + r) * DHc + d0 + k4]);
            if (RELS) {
                int srcrow = i0 + r + (bb == 0 ? 1 : 0);
                int ok = srcrow < Srows;
                cpa16z(smb + (uint32_t)(9216 + r * 36 + k4) * 4,
                       &Q2[((size_t)z * Srows + (ok ? srcrow : 0)) * DHc + d0 + k4],
                       ok ? 16 : 0);
                cpa16(smb + (uint32_t)(13824 + r * 36 + k4) * 4,
                      &PE[(size_t)(j0 + r) * Dc + hh * DHc + d0 + k4]);
            }
        }
        CP_COMMIT();
        CP_WAIT0();
        __syncthreads();

        const float* Qs  = sm;
        const float* Ks  = sm + 4608;
        const float* Q2s = sm + 9216;
        const float* Ps  = sm + 13824;
#pragma unroll
        for (int k8 = 0; k8 < 32; k8 += 8) {
            uint32_t a[4][4], b[4][2];
#pragma unroll
            for (int mt = 0; mt < 4; mt++) {
                int r = wm * 64 + mt * 16 + lr;
                a[mt][0] = __float_as_uint(Qs[r * 36 + k8 + lc]);
                a[mt][1] = __float_as_uint(Qs[(r + 8) * 36 + k8 + lc]);
                a[mt][2] = __float_as_uint(Qs[r * 36 + k8 + lc + 4]);
                a[mt][3] = __float_as_uint(Qs[(r + 8) * 36 + k8 + lc + 4]);
            }
#pragma unroll
            for (int nt = 0; nt < 4; nt++) {
                int c = wn * 32 + nt * 8 + lr;
                b[nt][0] = __float_as_uint(Ks[c * 36 + k8 + lc]);
                b[nt][1] = __float_as_uint(Ks[c * 36 + k8 + lc + 4]);
            }
#pragma unroll
            for (int mt = 0; mt < 4; mt++)
#pragma unroll
                for (int nt = 0; nt < 4; nt++)
                    mma8(acc[mt][nt], a[mt], b[nt]);
            if (RELS) {
#pragma unroll
                for (int mt = 0; mt < 4; mt++) {
                    int r = wm * 64 + mt * 16 + lr;
                    a[mt][0] = __float_as_uint(Q2s[r * 36 + k8 + lc]);
                    a[mt][1] = __float_as_uint(Q2s[(r + 8) * 36 + k8 + lc]);
                    a[mt][2] = __float_as_uint(Q2s[r * 36 + k8 + lc + 4]);
                    a[mt][3] = __float_as_uint(Q2s[(r + 8) * 36 + k8 + lc + 4]);
                }
#pragma unroll
                for (int nt = 0; nt < 4; nt++) {
                    int c = wn * 32 + nt * 8 + lr;
                    b[nt][0] = __float_as_uint(Ps[c * 36 + k8 + lc]);
                    b[nt][1] = __float_as_uint(Ps[c * 36 + k8 + lc + 4]);
                }
#pragma unroll
                for (int mt = 0; mt < 4; mt++)
#pragma unroll
                    for (int nt = 0; nt < 4; nt++)
                        mma8(acc[mt][nt], a[mt], b[nt]);
            }
        }
        __syncthreads();
    }

#pragma unroll
    for (int mt = 0; mt < 4; mt++)
#pragma unroll
        for (int nt = 0; nt < 4; nt++) {
            int i_ = i0 + wm * 64 + mt * 16 + lr;
            int j_ = j0 + wn * 32 + nt * 8 + 2 * lc;
#pragma unroll
            for (int hf = 0; hf < 2; hf++) {
                int ii = i_ + hf * 8;
#pragma unroll
                for (int e = 0; e < 2; e++) {
                    int jj = j_ + e;
                    float val = acc[mt][nt][hf * 2 + e];
                    if (RELS && jj > ii + Mc) val = -1e30f;   // mask BEFORE scale
                    Out[((size_t)z * Srows + ii) * Sk + jj] = val;
                }
            }
        }
}

// ---------------- AV (cp.async double-buffered): O[b,i,h*64+d] ----------------
__global__ void __launch_bounds__(256, 2)
av_tf32(const float* __restrict__ P, const float* __restrict__ V,
        float* __restrict__ O, int Srows, int Sk)
{
    extern __shared__ float sm[];
    // Ps stage s @ s*4608 ([128][36]); Vs stage s @ 9216 + s*2304 ([32][72])
    const int tid = threadIdx.x, lane = tid & 31, wid = tid >> 5;
    const int wm = wid >> 1, wn = wid & 1;    // 4 x 2 warps
    const int lr = lane >> 2, lc = lane & 3;
    const int z = blockIdx.y;
    const int i0 = blockIdx.x * 128;
    const int bb = z >> 4, hh = z & 15;
    const uint32_t smb = (uint32_t)__cvta_generic_to_shared(sm);

    float acc[2][4][4];
#pragma unroll
    for (int mt = 0; mt < 2; mt++)
#pragma unroll
        for (int nt = 0; nt < 4; nt++)
#pragma unroll
            for (int e = 0; e < 4; e++) acc[mt][nt][e] = 0.f;

    auto loadPV = [&](int s, int j0) {
#pragma unroll
        for (int it = 0; it < 4; it++) {
            int lin = tid + it * 256;
            int r = lin >> 3, k4 = (lin & 7) * 4;
            cpa16(smb + (uint32_t)(s * 4608 + r * 36 + k4) * 4,
                  &P[((size_t)z * Srows + i0 + r) * Sk + j0 + k4]);
        }
        // V tile: 32 rows x 64 cols = 512 x 16B transfers (2 iterations x 256 threads)
#pragma unroll
        for (int it = 0; it < 2; it++) {
            int lin = tid + it * 256;
            int r = lin >> 4, n4 = (lin & 15) * 4;
            cpa16(smb + (uint32_t)(9216 + s * 2304 + r * 72 + n4) * 4,
                  &V[((size_t)z * Sk + j0 + r) * DHc + n4]);
        }
        CP_COMMIT();
    };

    const int nk = Sk / 32;
    loadPV(0, 0);
    for (int kt = 0; kt < nk; kt++) {
        if (kt + 1 < nk) { loadPV((kt + 1) & 1, (kt + 1) * 32); CP_WAIT1(); }
        else             { CP_WAIT0(); }
        __syncthreads();
        const float* Ps = sm + (kt & 1) * 4608;
        const float* Vs = sm + 9216 + (kt & 1) * 2304;
#pragma unroll
        for (int k8 = 0; k8 < 32; k8 += 8) {
            uint32_t a[2][4], b[4][2];
#pragma unroll
            for (int mt = 0; mt < 2; mt++) {
                int r = wm * 32 + mt * 16 + lr;
                a[mt][0] = __float_as_uint(Ps[r * 36 + k8 + lc]);
                a[mt][1] = __float_as_uint(Ps[(r + 8) * 36 + k8 + lc]);
                a[mt][2] = __float_as_uint(Ps[r * 36 + k8 + lc + 4]);
                a[mt][3] = __float_as_uint(Ps[(r + 8) * 36 + k8 + lc + 4]);
            }
#pragma unroll
            for (int nt = 0; nt < 4; nt++) {
                int c = wn * 32 + nt * 8 + lr;
                b[nt][0] = __float_as_uint(Vs[(k8 + lc) * 72 + c]);
                b[nt][1] = __float_as_uint(Vs[(k8 + lc + 4) * 72 + c]);
            }
#pragma unroll
            for (int mt = 0; mt < 2; mt++)
#pragma unroll
                for (int nt = 0; nt < 4; nt++)
                    mma8(acc[mt][nt], a[mt], b[nt]);
        }
        __syncthreads();
    }

#pragma unroll
    for (int mt = 0; mt < 2; mt++)
#pragma unroll
        for (int nt = 0; nt < 4; nt++) {
            int i_ = i0 + wm * 32 + mt * 16 + lr;
            int d_ = wn * 32 + nt * 8 + 2 * lc;
#pragma unroll
            for (int hf = 0; hf < 2; hf++) {
                int ii = i_ + hf * 8;
                size_t o = ((size_t)(bb * Sc) + ii) * Dc + hh * DHc + d_;
                O[o]     = rnd_tf(acc[mt][nt][hf * 2 + 0]);
                O[o + 1] = rnd_tf(acc[mt][nt][hf * 2 + 1]);
            }
        }
}

// ---------------- softmax over i (query axis), per (z,j) column, online ----------
__global__ void softmax_i(float* __restrict__ P, int Srows, int Sk, float scale, int cols)
{
    int col = blockIdx.x * blockDim.x + threadIdx.x;
    if (col >= cols) return;
    int z = col / Sk, j = col % Sk;
    float* base = P + (size_t)z * Srows * Sk + j;
    float m = -3.4e38f, s = 0.f;
    for (int i = 0; i < Srows; i++) {
        float v = base[(size_t)i * Sk] * scale;
        if (v > m) { s = s * __expf(m - v) + 1.f; m = v; }
        else         s += __expf(v - m);
    }
    float inv = 1.f / s;
    for (int i = 0; i < Srows; i++)
        base[(size_t)i * Sk] = rnd_tf(__expf(base[(size_t)i * Sk] * scale - m) * inv);
}

// ---------------- LayerNorm: Y = LN(X)+Res (exact); Yr = rnd(same) optional ------
__global__ void ln_kernel(const float* __restrict__ X, const float* __restrict__ gw,
                          const float* __restrict__ bw, float* __restrict__ Y,
                          float* __restrict__ Yr, const float* __restrict__ Res)
{
    __shared__ float s1[256], s2[256];
    const int row = blockIdx.x;
    const int tid = threadIdx.x;
    const float* x = X + (size_t)row * Dc;
    float4 v = *(const float4*)&x[tid * 4];
    s1[tid] = v.x + v.y + v.z + v.w;
    s2[tid] = v.x * v.x + v.y * v.y + v.z * v.z + v.w * v.w;
    __syncthreads();
    for (int st = 128; st > 0; st >>= 1) {
        if (tid < st) { s1[tid] += s1[tid + st]; s2[tid] += s2[tid + st]; }
        __syncthreads();
    }
    float mu = s1[0] * (1.f / Dc);
    float var = s2[0] * (1.f / Dc) - mu * mu;
    float rinv = rsqrtf(var + 1e-5f);
    float4 g4 = *(const float4*)&gw[tid * 4];
    float4 b4 = *(const float4*)&bw[tid * 4];
    float4 o;
    o.x = (v.x - mu) * rinv * g4.x + b4.x;
    o.y = (v.y - mu) * rinv * g4.y + b4.y;
    o.z = (v.z - mu) * rinv * g4.z + b4.z;
    o.w = (v.w - mu) * rinv * g4.w + b4.w;
    if (Res) {
        float4 r4 = *(const float4*)&Res[(size_t)row * Dc + tid * 4];
        o.x += r4.x; o.y += r4.y; o.z += r4.z; o.w += r4.w;
    }
    *(float4*)&Y[(size_t)row * Dc + tid * 4] = o;
    if (Yr) {
        float4 r = { rnd_tf(o.x), rnd_tf(o.y), rnd_tf(o.z), rnd_tf(o.w) };
        *(float4*)&Yr[(size_t)row * Dc + tid * 4] = r;
    }
}

// ---------------- concat(mem, xnr) -> h, rounded ----------------
__global__ void concat_kernel(const float* __restrict__ mem, const float* __restrict__ xn,
                              float* __restrict__ h)
{
    size_t idx = (size_t)blockIdx.x * 256 + threadIdx.x;
    int d = idx & (Dc - 1);
    size_t r = idx >> 10;
    int t = r & (Stc - 1);
    int b = (int)(r >> 11);
    float v = (t < Mc) ? mem[((size_t)b * Mc + t) * Dc + d]
                       : xn[((size_t)b * Sc + (t - Mc)) * Dc + d];
    h[idx] = rnd_tf(v);
}

// ---------------- host-side launcher ----------------
static inline float* sym(const void* s)
{
    void* p = nullptr;
    cudaGetSymbolAddress(&p, s);
    return (float*)p;
}

extern "C" void kernel_launch(void* const* d_in, const int* in_sizes, int n_in,
                              void* d_out, int out_size)
{
    const float* x     = (const float*)d_in[0];
    const float* enc   = (const float*)d_in[1];
    const float* pemb  = (const float*)d_in[2];
    const float* u     = (const float*)d_in[3];
    const float* vvec  = (const float*)d_in[4];
    const float* mem   = (const float*)d_in[5];
    // d_in[6] = tgt_mask (bool) — recomputed analytically
    const float* Wq_m  = (const float*)d_in[7];
    const float* Wkv_m = (const float*)d_in[8];
    const float* fcw_m = (const float*)d_in[9];
    const float* fcb_m = (const float*)d_in[10];
    const float* lnm_g = (const float*)d_in[11];
    const float* lnm_b = (const float*)d_in[12];
    const float* Wq_c  = (const float*)d_in[13];
    const float* Wkv_c = (const float*)d_in[14];
    const float* fcw_c = (const float*)d_in[15];
    const float* fcb_c = (const float*)d_in[16];
    const float* lnc_g = (const float*)d_in[17];
    const float* lnc_b = (const float*)d_in[18];
    const float* W1    = (const float*)d_in[19];
    const float* b1    = (const float*)d_in[20];
    const float* W2    = (const float*)d_in[21];
    const float* b2    = (const float*)d_in[22];
    const float* ln1_g = (const float*)d_in[23];
    const float* ln1_b = (const float*)d_in[24];
    const float* ln2_g = (const float*)d_in[25];
    const float* ln2_b = (const float*)d_in[26];
    const float* ln3_g = (const float*)d_in[27];
    const float* ln3_b = (const float*)d_in[28];
    float* out = (float*)d_out;

    float* xn  = sym(g_xn);   float* xnr  = sym(g_xnr); float* hcat = sym(g_h);
    float* q   = sym(g_q);    float* q2   = sym(g_q2);
    float* kk  = sym(g_k);    float* vv   = sym(g_v);
    float* scs = sym(g_scb);  float* o    = sym(g_o);   float* tmp = sym(g_tmp);
    float* o1  = sym(g_out);  float* o2   = sym(g_out2);
    float* ff  = sym(g_ff);   float* w    = sym(g_wts);

    float* wWq_m  = w + OFF_WQ_M;
    float* wWkv_m = w + OFF_WKV_M;
    float* wfcw_m = w + OFF_FCW_M;
    float* wWq_c  = w + OFF_WQ_C;
    float* wWkv_c = w + OFF_WKV_C;
    float* wfcw_c = w + OFF_FCW_C;
    float* wW1    = w + OFF_W1;
    float* wW2    = w + OFF_W2;
    float* wpemb  = w + OFF_PEMB;
    float* wenc   = w + OFF_ENC;

    // smem opt-ins (idempotent; persists from the first uncaptured call)
    cudaFuncSetAttribute(gemm_tf32<0,0,0>, cudaFuncAttributeMaxDynamicSharedMemorySize, 71680);
    cudaFuncSetAttribute(gemm_tf32<0,1,1>, cudaFuncAttributeMaxDynamicSharedMemorySize, 71680);
    cudaFuncSetAttribute(gemm_tf32<0,2,1>, cudaFuncAttributeMaxDynamicSharedMemorySize, 71680);
    cudaFuncSetAttribute(gemm_tf32<1,0,1>, cudaFuncAttributeMaxDynamicSharedMemorySize, 71680);
    cudaFuncSetAttribute(qk_fused<1>,      cudaFuncAttributeMaxDynamicSharedMemorySize, 73728);
    cudaFuncSetAttribute(qk_fused<0>,      cudaFuncAttributeMaxDynamicSharedMemorySize, 73728);
    cudaFuncSetAttribute(av_tf32,          cudaFuncAttributeMaxDynamicSharedMemorySize, 55296);

    const float scale = 0.125f;   // 1/sqrt(64)
    const int rowsBS = Bc * Sc;   // 2048

    // ===== pre-round GEMM operands (weights / pemb / enc) =====
    auto RC = [&](const float* s_, float* d_, int n) {
        round_copy<<<n / 4 / 256, 256>>>((const float4*)s_, (float4*)d_, n / 4);
    };
    RC(Wq_m,  wWq_m,  1*MEG); RC(Wkv_m, wWkv_m, 2*MEG); RC(fcw_m, wfcw_m, 1*MEG);
    RC(Wq_c,  wWq_c,  1*MEG); RC(Wkv_c, wWkv_c, 2*MEG); RC(fcw_c, wfcw_c, 1*MEG);
    RC(W1,    wW1,    4*MEG); RC(W2,    wW2,    4*MEG);
    RC(pemb,  wpemb,  2*MEG); RC(enc,   wenc,   2*MEG);

    // ===== pre-norm 1 =====
    ln_kernel<<<rowsBS, 256>>>(x, ln1_g, ln1_b, xn, xnr, nullptr);

    // ===== self MHA (Transformer-XL relative attention) =====
    concat_kernel<<<(Bc * Stc * Dc) / 256, 256>>>(mem, xnr, hcat);
    gemm_tf32<0,1,1><<<dim3(8, 16), 256, 71680>>>(xnr, wWq_m, q, q2, Dc, Dc, u, vvec, nullptr, Sc);
    gemm_tf32<0,2,1><<<dim3(16, 32), 256, 71680>>>(hcat, wWkv_m, kk, vv, 2 * Dc, Dc, nullptr, nullptr, nullptr, Stc);

    qk_fused<1><<<dim3(16, 8, Zc), 256, 73728>>>(q, q2, kk, wpemb, scs, Sc, Stc);
    softmax_i<<<(Zc * Stc) / 256, 256>>>(scs, Sc, Stc, scale, Zc * Stc);
    av_tf32<<<dim3(8, Zc), 256, 55296>>>(scs, vv, o, Sc, Stc);

    gemm_tf32<0,0,0><<<dim3(8, 16), 256, 71680>>>(o, wfcw_m, tmp, nullptr, Dc, Dc, fcb_m, nullptr, xn, 0);
    ln_kernel<<<rowsBS, 256>>>(tmp, lnm_g, lnm_b, o1, nullptr, x);     // out = x + LN(...)

    // ===== cross attention =====
    ln_kernel<<<rowsBS, 256>>>(o1, ln2_g, ln2_b, xn, xnr, nullptr);
    gemm_tf32<0,1,1><<<dim3(8, 16), 256, 71680>>>(xnr, wWq_c, q, nullptr, Dc, Dc, nullptr, nullptr, nullptr, Sc);
    gemm_tf32<0,2,1><<<dim3(16, 16), 256, 71680>>>(wenc, wWkv_c, kk, vv, 2 * Dc, Dc, nullptr, nullptr, nullptr, Sc);

    qk_fused<0><<<dim3(8, 8, Zc), 256, 73728>>>(q, nullptr, kk, nullptr, scs, Sc, Sc);
    softmax_i<<<(Zc * Sc) / 256, 256>>>(scs, Sc, Sc, scale, Zc * Sc);
    av_tf32<<<dim3(8, Zc), 256, 55296>>>(scs, vv, o, Sc, Sc);

    gemm_tf32<0,0,0><<<dim3(8, 16), 256, 71680>>>(o, wfcw_c, tmp, nullptr, Dc, Dc, fcb_c, nullptr, xn, 0);
    ln_kernel<<<rowsBS, 256>>>(tmp, lnc_g, lnc_b, o2, nullptr, o1);    // out2 = out + LN(...)

    // ===== FFN =====
    ln_kernel<<<rowsBS, 256>>>(o2, ln3_g, ln3_b, xn, xnr, nullptr);
    gemm_tf32<1,0,1><<<dim3(32, 16), 256, 71680>>>(xnr, wW1, ff, nullptr, DFFc, Dc, b1, nullptr, nullptr, 0);
    gemm_tf32<0,0,0><<<dim3(8, 16), 256, 71680>>>(ff, wW2, out, nullptr, Dc, DFFc, b2, nullptr, o2, 0);
}

// round 5
// speedup vs baseline: 3.4381x; 1.4140x over previous
#include <cuda_runtime.h>
#include <math.h>
#include <stdint.h>

#define Bc 2
#define Sc 1024
#define Mc 1024
#define Dc 1024
#define Hc 16
#define DHc 64
#define DFFc 4096
#define Stc 2048
#define Zc (Bc*Hc)
#define MEG (1024*1024)

// ---------------- scratch (device globals: no allocation allowed) ----------------
__device__ float g_xn [Bc*Sc*Dc];            // exact LN output (residual use)
__device__ float g_xnr[Bc*Sc*Dc];            // tf32-rounded LN output (GEMM use)
__device__ float g_h  [Bc*Stc*Dc];           // concat(mem, xn) rounded
__device__ float g_q  [Zc*Sc*DHc];
__device__ float g_q2 [Zc*Sc*DHc];
__device__ float g_k  [(size_t)Zc*Stc*DHc];
__device__ float g_v  [(size_t)Zc*Stc*DHc];
__device__ float g_vn [(size_t)Zc*Stc*DHc];  // V * invZ
__device__ float g_scb[(size_t)Zc*Sc*Stc];   // logits / probs
__device__ float g_mx [Zc*Stc];              // column max
__device__ float g_iz [Zc*Stc];              // column 1/sum
__device__ float g_o  [Bc*Sc*Dc];
__device__ float g_tmp[Bc*Sc*Dc];
__device__ float g_out[Bc*Sc*Dc];
__device__ float g_out2[Bc*Sc*Dc];
__device__ float g_ff [(size_t)Bc*Sc*DFFc];
__device__ float g_wts[20*MEG];              // rounded weights/pemb/enc

// offsets into g_wts (floats)
#define OFF_WQ_M   0
#define OFF_WKV_M  (1*MEG)
#define OFF_FCW_M  (3*MEG)
#define OFF_WQ_C   (4*MEG)
#define OFF_WKV_C  (5*MEG)
#define OFF_FCW_C  (7*MEG)
#define OFF_W1     (8*MEG)
#define OFF_W2     (12*MEG)
#define OFF_PEMB   (16*MEG)
#define OFF_ENC    (18*MEG)

// ---------------- helpers ----------------
__device__ __forceinline__ uint32_t f2tf(float f) {
    uint32_t r;
    asm("cvt.rna.tf32.f32 %0, %1;" : "=r"(r) : "f"(f));
    return r;
}
__device__ __forceinline__ float rnd_tf(float f) { return __uint_as_float(f2tf(f)); }

__device__ __forceinline__ void cpa16(uint32_t dst, const void* src) {
    asm volatile("cp.async.cg.shared.global [%0], [%1], 16;\n" :: "r"(dst), "l"(src));
}
__device__ __forceinline__ void cpa16z(uint32_t dst, const void* src, int srcbytes) {
    asm volatile("cp.async.cg.shared.global [%0], [%1], 16, %2;\n"
                 :: "r"(dst), "l"(src), "r"(srcbytes));
}
#define CP_COMMIT() asm volatile("cp.async.commit_group;\n")
#define CP_WAIT0()  asm volatile("cp.async.wait_group 0;\n")
#define CP_WAIT1()  asm volatile("cp.async.wait_group 1;\n")
#define CP_WAIT2()  asm volatile("cp.async.wait_group 2;\n")

__device__ __forceinline__ void mma8(float* c, const uint32_t* a, const uint32_t* b) {
    asm volatile(
        "mma.sync.aligned.m16n8k8.row.col.f32.tf32.tf32.f32 "
        "{%0,%1,%2,%3}, {%4,%5,%6,%7}, {%8,%9}, {%0,%1,%2,%3};\n"
        : "+f"(c[0]), "+f"(c[1]), "+f"(c[2]), "+f"(c[3])
        : "r"(a[0]), "r"(a[1]), "r"(a[2]), "r"(a[3]), "r"(b[0]), "r"(b[1]));
}

// ---------------- weight pre-round ----------------
__global__ void round_copy(const float4* __restrict__ src, float4* __restrict__ dst, int n4)
{
    int i = blockIdx.x * 256 + threadIdx.x;
    if (i < n4) {
        float4 v = src[i];
        float4 o = { rnd_tf(v.x), rnd_tf(v.y), rnd_tf(v.z), rnd_tf(v.w) };
        dst[i] = o;
    }
}

// ---------------- dense GEMM, cp.async 3-stage, tf32 MMA ----------------
// A: rows x K row-major (pre-rounded). B: K x N (pre-rounded). Tiles 128x128x32.
// EPI=0: C = [RND](act(A@B + bias) + Res)
// EPI=1: head-split q write: C[bhid]=rnd(v+bias), C2[bhid]=rnd(v+bias2) (nullable)
// EPI=2: kv split: col<1024 -> C (k), else C2 (v); rounded
template<int ACT, int EPI, int RND>
__global__ void __launch_bounds__(256, 2)
gemm_tf32(const float* __restrict__ A, const float* __restrict__ Bm,
          float* __restrict__ C, float* __restrict__ C2,
          int N, int K, const float* __restrict__ bias, const float* __restrict__ bias2,
          const float* __restrict__ Res, int Sk)
{
    extern __shared__ float sm[];
    // As stage s at sm + s*4608 ([128][36]); Bs stage s at sm + 13824 + s*4352 ([32][136])
    const int tid = threadIdx.x, lane = tid & 31, wid = tid >> 5;
    const int wm = wid & 1, wn = wid >> 1;
    const int lr = lane >> 2, lc = lane & 3;
    const int row0 = blockIdx.y * 128, col0 = blockIdx.x * 128;
    const uint32_t smb = (uint32_t)__cvta_generic_to_shared(sm);

    float acc[4][4][4];
#pragma unroll
    for (int mt = 0; mt < 4; mt++)
#pragma unroll
        for (int nt = 0; nt < 4; nt++)
#pragma unroll
            for (int e = 0; e < 4; e++) acc[mt][nt][e] = 0.f;

    const int nk = K / 32;
    auto loadAB = [&](int s, int k0) {
#pragma unroll
        for (int it = 0; it < 4; it++) {
            int lin = tid + it * 256;
            int r = lin >> 3, k4 = (lin & 7) * 4;
            cpa16(smb + (uint32_t)(s * 4608 + r * 36 + k4) * 4,
                  &A[(size_t)(row0 + r) * K + k0 + k4]);
        }
#pragma unroll
        for (int it = 0; it < 4; it++) {
            int lin = tid + it * 256;
            int r = lin >> 5, n4 = (lin & 31) * 4;
            cpa16(smb + (uint32_t)(13824 + s * 4352 + r * 136 + n4) * 4,
                  &Bm[(size_t)(k0 + r) * N + col0 + n4]);
        }
        CP_COMMIT();
    };

    loadAB(0, 0);
    if (nk > 1) loadAB(1, 32);
    for (int kt = 0; kt < nk; kt++) {
        if (kt + 2 < nk) { loadAB((kt + 2) % 3, (kt + 2) * 32); CP_WAIT2(); }
        else if (kt + 1 < nk) CP_WAIT1();
        else CP_WAIT0();
        __syncthreads();
        const float* As = sm + (kt % 3) * 4608;
        const float* Bs = sm + 13824 + (kt % 3) * 4352;
#pragma unroll
        for (int k8 = 0; k8 < 32; k8 += 8) {
            uint32_t a[4][4], b[4][2];
#pragma unroll
            for (int mt = 0; mt < 4; mt++) {
                int r = wm * 64 + mt * 16 + lr;
                a[mt][0] = __float_as_uint(As[r * 36 + k8 + lc]);
                a[mt][1] = __float_as_uint(As[(r + 8) * 36 + k8 + lc]);
                a[mt][2] = __float_as_uint(As[r * 36 + k8 + lc + 4]);
                a[mt][3] = __float_as_uint(As[(r + 8) * 36 + k8 + lc + 4]);
            }
#pragma unroll
            for (int nt = 0; nt < 4; nt++) {
                int c = wn * 32 + nt * 8 + lr;
                b[nt][0] = __float_as_uint(Bs[(k8 + lc) * 136 + c]);
                b[nt][1] = __float_as_uint(Bs[(k8 + lc + 4) * 136 + c]);
            }
#pragma unroll
            for (int mt = 0; mt < 4; mt++)
#pragma unroll
                for (int nt = 0; nt < 4; nt++)
                    mma8(acc[mt][nt], a[mt], b[nt]);
        }
        __syncthreads();
    }

#pragma unroll
    for (int mt = 0; mt < 4; mt++)
#pragma unroll
        for (int nt = 0; nt < 4; nt++) {
            int r_ = row0 + wm * 64 + mt * 16 + lr;
            int c_ = col0 + wn * 32 + nt * 8 + 2 * lc;
#pragma unroll
            for (int hf = 0; hf < 2; hf++) {
                int rr = r_ + hf * 8;
                float v0 = acc[mt][nt][hf * 2 + 0];
                float v1 = acc[mt][nt][hf * 2 + 1];
                if (EPI == 0) {
                    if (bias) { v0 += bias[c_]; v1 += bias[c_ + 1]; }
                    if (ACT == 1) {
                        v0 = 0.5f * v0 * (1.0f + erff(v0 * 0.70710678118654752f));
                        v1 = 0.5f * v1 * (1.0f + erff(v1 * 0.70710678118654752f));
                    }
                    if (Res) {
                        v0 += Res[(size_t)rr * N + c_];
                        v1 += Res[(size_t)rr * N + c_ + 1];
                    }
                    if (RND) { v0 = rnd_tf(v0); v1 = rnd_tf(v1); }
                    C[(size_t)rr * N + c_]     = v0;
                    C[(size_t)rr * N + c_ + 1] = v1;
                } else if (EPI == 1) {
                    int b = rr >> 10, i = rr & 1023;
#pragma unroll
                    for (int e = 0; e < 2; e++) {
                        int cc = c_ + e;
                        int h = cc >> 6, d = cc & 63;
                        float val = e ? v1 : v0;
                        size_t dst = (((size_t)(b * Hc + h)) * Sc + i) * DHc + d;
                        C[dst] = rnd_tf(val + (bias ? bias[cc] : 0.f));
                        if (C2) C2[dst] = rnd_tf(val + bias2[cc]);
                    }
                } else { // EPI == 2
                    int b = rr / Sk, j = rr % Sk;
#pragma unroll
                    for (int e = 0; e < 2; e++) {
                        int cc = c_ + e;
                        int isv = cc >> 10;
                        int h = (cc & 1023) >> 6, d = cc & 63;
                        float val = e ? v1 : v0;
                        size_t dst = (((size_t)(b * Hc + h)) * Sk + j) * DHc + d;
                        (isv ? C2 : C)[dst] = rnd_tf(val);
                    }
                }
            }
        }
}

// ---------------- fused QK^T (+ shifted-pos + mask for self-attn) ----------------
// RELS=1: acc = Q·K^T + Q2shift·PE^T ; mask (j>i+M -> -1e30); write logits.
//         fully-masked tiles (j0 > i0+127+M) take a write-only fast path.
// RELS=0: acc = Q·K^T (cross attention).
template<int RELS>
__global__ void __launch_bounds__(256, 2)
qk_fused(const float* __restrict__ Q, const float* __restrict__ Q2,
         const float* __restrict__ Kk, const float* __restrict__ PE,
         float* __restrict__ Out, int Srows, int Sk)
{
    extern __shared__ float sm[];
    // Qs @0, Ks @4608, Q2s @9216, Ps @13824 — each [128][36]
    const int tid = threadIdx.x, lane = tid & 31, wid = tid >> 5;
    const int wm = wid & 1, wn = wid >> 1;
    const int lr = lane >> 2, lc = lane & 3;
    const int z = blockIdx.z;
    const int j0 = blockIdx.x * 128, i0 = blockIdx.y * 128;
    const int bb = z >> 4, hh = z & 15;
    const uint32_t smb = (uint32_t)__cvta_generic_to_shared(sm);

    if (RELS && j0 > i0 + 127 + Mc) {
        // fully masked tile: write -1e30, skip all MMA work
        float4 neg = { -1e30f, -1e30f, -1e30f, -1e30f };
#pragma unroll
        for (int it = 0; it < 16; it++) {
            int lin = tid + it * 256;
            int r = lin >> 5, c4 = (lin & 31) * 4;
            *(float4*)&Out[((size_t)z * Srows + i0 + r) * Sk + j0 + c4] = neg;
        }
        return;
    }

    float acc[4][4][4];
#pragma unroll
    for (int mt = 0; mt < 4; mt++)
#pragma unroll
        for (int nt = 0; nt < 4; nt++)
#pragma unroll
            for (int e = 0; e < 4; e++) acc[mt][nt][e] = 0.f;

#pragma unroll
    for (int d0 = 0; d0 < DHc; d0 += 32) {
#pragma unroll
        for (int it = 0; it < 4; it++) {
            int lin = tid + it * 256;
            int r = lin >> 3, k4 = (lin & 7) * 4;
            cpa16(smb + (uint32_t)(r * 36 + k4) * 4,
                  &Q[((size_t)z * Srows + i0 + r) * DHc + d0 + k4]);
            cpa16(smb + (uint32_t)(4608 + r * 36 + k4) * 4,
                  &Kk[((size_t)z * Sk + j0 + r) * DHc + d0 + k4]);
            if (RELS) {
                int srcrow = i0 + r + (bb == 0 ? 1 : 0);
                int ok = srcrow < Srows;
                cpa16z(smb + (uint32_t)(9216 + r * 36 + k4) * 4,
                       &Q2[((size_t)z * Srows + (ok ? srcrow : 0)) * DHc + d0 + k4],
                       ok ? 16 : 0);
                cpa16(smb + (uint32_t)(13824 + r * 36 + k4) * 4,
                      &PE[(size_t)(j0 + r) * Dc + hh * DHc + d0 + k4]);
            }
        }
        CP_COMMIT();
        CP_WAIT0();
        __syncthreads();

        const float* Qs  = sm;
        const float* Ks  = sm + 4608;
        const float* Q2s = sm + 9216;
        const float* Ps  = sm + 13824;
#pragma unroll
        for (int k8 = 0; k8 < 32; k8 += 8) {
            uint32_t a[4][4], b[4][2];
#pragma unroll
            for (int mt = 0; mt < 4; mt++) {
                int r = wm * 64 + mt * 16 + lr;
                a[mt][0] = __float_as_uint(Qs[r * 36 + k8 + lc]);
                a[mt][1] = __float_as_uint(Qs[(r + 8) * 36 + k8 + lc]);
                a[mt][2] = __float_as_uint(Qs[r * 36 + k8 + lc + 4]);
                a[mt][3] = __float_as_uint(Qs[(r + 8) * 36 + k8 + lc + 4]);
            }
#pragma unroll
            for (int nt = 0; nt < 4; nt++) {
                int c = wn * 32 + nt * 8 + lr;
                b[nt][0] = __float_as_uint(Ks[c * 36 + k8 + lc]);
                b[nt][1] = __float_as_uint(Ks[c * 36 + k8 + lc + 4]);
            }
#pragma unroll
            for (int mt = 0; mt < 4; mt++)
#pragma unroll
                for (int nt = 0; nt < 4; nt++)
                    mma8(acc[mt][nt], a[mt], b[nt]);
            if (RELS) {
#pragma unroll
                for (int mt = 0; mt < 4; mt++) {
                    int r = wm * 64 + mt * 16 + lr;
                    a[mt][0] = __float_as_uint(Q2s[r * 36 + k8 + lc]);
                    a[mt][1] = __float_as_uint(Q2s[(r + 8) * 36 + k8 + lc]);
                    a[mt][2] = __float_as_uint(Q2s[r * 36 + k8 + lc + 4]);
                    a[mt][3] = __float_as_uint(Q2s[(r + 8) * 36 + k8 + lc + 4]);
                }
#pragma unroll
                for (int nt = 0; nt < 4; nt++) {
                    int c = wn * 32 + nt * 8 + lr;
                    b[nt][0] = __float_as_uint(Ps[c * 36 + k8 + lc]);
                    b[nt][1] = __float_as_uint(Ps[c * 36 + k8 + lc + 4]);
                }
#pragma unroll
                for (int mt = 0; mt < 4; mt++)
#pragma unroll
                    for (int nt = 0; nt < 4; nt++)
                        mma8(acc[mt][nt], a[mt], b[nt]);
            }
        }
        __syncthreads();
    }

#pragma unroll
    for (int mt = 0; mt < 4; mt++)
#pragma unroll
        for (int nt = 0; nt < 4; nt++) {
            int i_ = i0 + wm * 64 + mt * 16 + lr;
            int j_ = j0 + wn * 32 + nt * 8 + 2 * lc;
#pragma unroll
            for (int hf = 0; hf < 2; hf++) {
                int ii = i_ + hf * 8;
#pragma unroll
                for (int e = 0; e < 2; e++) {
                    int jj = j_ + e;
                    float val = acc[mt][nt][hf * 2 + e];
                    if (RELS && jj > ii + Mc) val = -1e30f;   // mask BEFORE scale
                    Out[((size_t)z * Srows + ii) * Sk + jj] = val;
                }
            }
        }
}

// ---------------- column max over i (query axis) ----------------
// block = (2 rows x 128 cols); one block owns 128 columns fully. CAUS: skip masked i.
template<int CAUS>
__global__ void colmax(const float* __restrict__ P, float* __restrict__ Mx,
                       int Srows, int Sk)
{
    __shared__ float red[256];
    const int z = blockIdx.y;
    const int j = blockIdx.x * 128 + (threadIdx.x & 127);
    const int ty = threadIdx.x >> 7;
    const float* base = P + (size_t)z * Srows * Sk + j;
    int start = CAUS ? max(0, j - Mc) : 0;
    float m = -3.4e38f;
#pragma unroll 8
    for (int i = start + ty; i < Srows; i += 2)
        m = fmaxf(m, base[(size_t)i * Sk]);
    red[threadIdx.x] = m;
    __syncthreads();
    if (ty == 0)
        Mx[(size_t)z * Sk + j] = fmaxf(red[threadIdx.x], red[threadIdx.x + 128]);
}

// ---------------- column normalize: P <- rnd(exp(scale*(v - m))), invZ out ----------
__global__ void colnorm(float* __restrict__ P, const float* __restrict__ Mx,
                        float* __restrict__ InvZ, int Srows, int Sk, float scale)
{
    __shared__ float red[256];
    const int z = blockIdx.y;
    const int j = blockIdx.x * 128 + (threadIdx.x & 127);
    const int ty = threadIdx.x >> 7;
    const float msc = Mx[(size_t)z * Sk + j] * scale;
    float* base = P + (size_t)z * Srows * Sk + j;
    float s = 0.f;
#pragma unroll 4
    for (int i = ty; i < Srows; i += 2) {
        float p = __expf(base[(size_t)i * Sk] * scale - msc);
        base[(size_t)i * Sk] = rnd_tf(p);
        s += p;
    }
    red[threadIdx.x] = s;
    __syncthreads();
    if (ty == 0)
        InvZ[(size_t)z * Sk + j] = 1.f / (red[threadIdx.x] + red[threadIdx.x + 128]);
}

// ---------------- Vn = rnd(V * invZ[j]) ----------------
__global__ void vscale(const float* __restrict__ V, const float* __restrict__ InvZ,
                       float* __restrict__ Vn, int lgSk)
{
    int idx = blockIdx.x * 256 + threadIdx.x;      // over Z*Sk*16 float4s
    int zj = idx >> 4;                              // z*Sk + j
    float iz = InvZ[zj];
    float4 v = ((const float4*)V)[idx];
    float4 o = { rnd_tf(v.x * iz), rnd_tf(v.y * iz), rnd_tf(v.z * iz), rnd_tf(v.w * iz) };
    ((float4*)Vn)[idx] = o;
}

// ---------------- AV (cp.async 3-stage): O[b,i,h*64+d] = sum_j P*Vn ---------------
// CAUS: truncate j loop past the causal boundary (P is 0 there).
__global__ void __launch_bounds__(256, 2)
av_tf32(const float* __restrict__ P, const float* __restrict__ V,
        float* __restrict__ O, int Srows, int Sk, int caus)
{
    extern __shared__ float sm[];
    // Ps stage s @ s*4608 ([128][36]); Vs stage s @ 13824 + s*2304 ([32][72])
    const int tid = threadIdx.x, lane = tid & 31, wid = tid >> 5;
    const int wm = wid >> 1, wn = wid & 1;    // 4 x 2 warps
    const int lr = lane >> 2, lc = lane & 3;
    const int z = blockIdx.y;
    const int i0 = blockIdx.x * 128;
    const int bb = z >> 4, hh = z & 15;
    const uint32_t smb = (uint32_t)__cvta_generic_to_shared(sm);

    float acc[2][4][4];
#pragma unroll
    for (int mt = 0; mt < 2; mt++)
#pragma unroll
        for (int nt = 0; nt < 4; nt++)
#pragma unroll
            for (int e = 0; e < 4; e++) acc[mt][nt][e] = 0.f;

    auto loadPV = [&](int s, int j0) {
#pragma unroll
        for (int it = 0; it < 4; it++) {
            int lin = tid + it * 256;
            int r = lin >> 3, k4 = (lin & 7) * 4;
            cpa16(smb + (uint32_t)(s * 4608 + r * 36 + k4) * 4,
                  &P[((size_t)z * Srows + i0 + r) * Sk + j0 + k4]);
        }
#pragma unroll
        for (int it = 0; it < 2; it++) {
            int lin = tid + it * 256;
            int r = lin >> 4, n4 = (lin & 15) * 4;
            cpa16(smb + (uint32_t)(13824 + s * 2304 + r * 72 + n4) * 4,
                  &V[((size_t)z * Sk + j0 + r) * DHc + n4]);
        }
        CP_COMMIT();
    };

    int nk = Sk / 32;
    if (caus) nk = min(nk, (i0 + 127 + Mc) / 32 + 1);   // P==0 beyond the mask
    loadPV(0, 0);
    if (nk > 1) loadPV(1, 32);
    for (int kt = 0; kt < nk; kt++) {
        if (kt + 2 < nk) { loadPV((kt + 2) % 3, (kt + 2) * 32); CP_WAIT2(); }
        else if (kt + 1 < nk) CP_WAIT1();
        else CP_WAIT0();
        __syncthreads();
        const float* Ps = sm + (kt % 3) * 4608;
        const float* Vs = sm + 13824 + (kt % 3) * 2304;
#pragma unroll
        for (int k8 = 0; k8 < 32; k8 += 8) {
            uint32_t a[2][4], b[4][2];
#pragma unroll
            for (int mt = 0; mt < 2; mt++) {
                int r = wm * 32 + mt * 16 + lr;
                a[mt][0] = __float_as_uint(Ps[r * 36 + k8 + lc]);
                a[mt][1] = __float_as_uint(Ps[(r + 8) * 36 + k8 + lc]);
                a[mt][2] = __float_as_uint(Ps[r * 36 + k8 + lc + 4]);
                a[mt][3] = __float_as_uint(Ps[(r + 8) * 36 + k8 + lc + 4]);
            }
#pragma unroll
            for (int nt = 0; nt < 4; nt++) {
                int c = wn * 32 + nt * 8 + lr;
                b[nt][0] = __float_as_uint(Vs[(k8 + lc) * 72 + c]);
                b[nt][1] = __float_as_uint(Vs[(k8 + lc + 4) * 72 + c]);
            }
#pragma unroll
            for (int mt = 0; mt < 2; mt++)
#pragma unroll
                for (int nt = 0; nt < 4; nt++)
                    mma8(acc[mt][nt], a[mt], b[nt]);
        }
        __syncthreads();
    }

#pragma unroll
    for (int mt = 0; mt < 2; mt++)
#pragma unroll
        for (int nt = 0; nt < 4; nt++) {
            int i_ = i0 + wm * 32 + mt * 16 + lr;
            int d_ = wn * 32 + nt * 8 + 2 * lc;
#pragma unroll
            for (int hf = 0; hf < 2; hf++) {
                int ii = i_ + hf * 8;
                size_t o = ((size_t)(bb * Sc) + ii) * Dc + hh * DHc + d_;
                O[o]     = rnd_tf(acc[mt][nt][hf * 2 + 0]);
                O[o + 1] = rnd_tf(acc[mt][nt][hf * 2 + 1]);
            }
        }
}

// ---------------- LayerNorm: Y = LN(X)+Res (exact); Yr = rnd(same) optional ------
__global__ void ln_kernel(const float* __restrict__ X, const float* __restrict__ gw,
                          const float* __restrict__ bw, float* __restrict__ Y,
                          float* __restrict__ Yr, const float* __restrict__ Res)
{
    __shared__ float s1[256], s2[256];
    const int row = blockIdx.x;
    const int tid = threadIdx.x;
    const float* x = X + (size_t)row * Dc;
    float4 v = *(const float4*)&x[tid * 4];
    s1[tid] = v.x + v.y + v.z + v.w;
    s2[tid] = v.x * v.x + v.y * v.y + v.z * v.z + v.w * v.w;
    __syncthreads();
    for (int st = 128; st > 0; st >>= 1) {
        if (tid < st) { s1[tid] += s1[tid + st]; s2[tid] += s2[tid + st]; }
        __syncthreads();
    }
    float mu = s1[0] * (1.f / Dc);
    float var = s2[0] * (1.f / Dc) - mu * mu;
    float rinv = rsqrtf(var + 1e-5f);
    float4 g4 = *(const float4*)&gw[tid * 4];
    float4 b4 = *(const float4*)&bw[tid * 4];
    float4 o;
    o.x = (v.x - mu) * rinv * g4.x + b4.x;
    o.y = (v.y - mu) * rinv * g4.y + b4.y;
    o.z = (v.z - mu) * rinv * g4.z + b4.z;
    o.w = (v.w - mu) * rinv * g4.w + b4.w;
    if (Res) {
        float4 r4 = *(const float4*)&Res[(size_t)row * Dc + tid * 4];
        o.x += r4.x; o.y += r4.y; o.z += r4.z; o.w += r4.w;
    }
    *(float4*)&Y[(size_t)row * Dc + tid * 4] = o;
    if (Yr) {
        float4 r = { rnd_tf(o.x), rnd_tf(o.y), rnd_tf(o.z), rnd_tf(o.w) };
        *(float4*)&Yr[(size_t)row * Dc + tid * 4] = r;
    }
}

// ---------------- concat(mem, xnr) -> h, rounded ----------------
__global__ void concat_kernel(const float* __restrict__ mem, const float* __restrict__ xn,
                              float* __restrict__ h)
{
    size_t idx = (size_t)blockIdx.x * 256 + threadIdx.x;
    int d = idx & (Dc - 1);
    size_t r = idx >> 10;
    int t = r & (Stc - 1);
    int b = (int)(r >> 11);
    float v = (t < Mc) ? mem[((size_t)b * Mc + t) * Dc + d]
                       : xn[((size_t)b * Sc + (t - Mc)) * Dc + d];
    h[idx] = rnd_tf(v);
}

// ---------------- host-side launcher ----------------
static inline float* sym(const void* s)
{
    void* p = nullptr;
    cudaGetSymbolAddress(&p, s);
    return (float*)p;
}

extern "C" void kernel_launch(void* const* d_in, const int* in_sizes, int n_in,
                              void* d_out, int out_size)
{
    const float* x     = (const float*)d_in[0];
    const float* enc   = (const float*)d_in[1];
    const float* pemb  = (const float*)d_in[2];
    const float* u     = (const float*)d_in[3];
    const float* vvec  = (const float*)d_in[4];
    const float* mem   = (const float*)d_in[5];
    // d_in[6] = tgt_mask (bool) — recomputed analytically
    const float* Wq_m  = (const float*)d_in[7];
    const float* Wkv_m = (const float*)d_in[8];
    const float* fcw_m = (const float*)d_in[9];
    const float* fcb_m = (const float*)d_in[10];
    const float* lnm_g = (const float*)d_in[11];
    const float* lnm_b = (const float*)d_in[12];
    const float* Wq_c  = (const float*)d_in[13];
    const float* Wkv_c = (const float*)d_in[14];
    const float* fcw_c = (const float*)d_in[15];
    const float* fcb_c = (const float*)d_in[16];
    const float* lnc_g = (const float*)d_in[17];
    const float* lnc_b = (const float*)d_in[18];
    const float* W1    = (const float*)d_in[19];
    const float* b1    = (const float*)d_in[20];
    const float* W2    = (const float*)d_in[21];
    const float* b2    = (const float*)d_in[22];
    const float* ln1_g = (const float*)d_in[23];
    const float* ln1_b = (const float*)d_in[24];
    const float* ln2_g = (const float*)d_in[25];
    const float* ln2_b = (const float*)d_in[26];
    const float* ln3_g = (const float*)d_in[27];
    const float* ln3_b = (const float*)d_in[28];
    float* out = (float*)d_out;

    float* xn  = sym(g_xn);   float* xnr  = sym(g_xnr); float* hcat = sym(g_h);
    float* q   = sym(g_q);    float* q2   = sym(g_q2);
    float* kk  = sym(g_k);    float* vv   = sym(g_v);   float* vn = sym(g_vn);
    float* scs = sym(g_scb);  float* mx   = sym(g_mx);  float* iz = sym(g_iz);
    float* o   = sym(g_o);    float* tmp  = sym(g_tmp);
    float* o1  = sym(g_out);  float* o2   = sym(g_out2);
    float* ff  = sym(g_ff);   float* w    = sym(g_wts);

    float* wWq_m  = w + OFF_WQ_M;
    float* wWkv_m = w + OFF_WKV_M;
    float* wfcw_m = w + OFF_FCW_M;
    float* wWq_c  = w + OFF_WQ_C;
    float* wWkv_c = w + OFF_WKV_C;
    float* wfcw_c = w + OFF_FCW_C;
    float* wW1    = w + OFF_W1;
    float* wW2    = w + OFF_W2;
    float* wpemb  = w + OFF_PEMB;
    float* wenc   = w + OFF_ENC;

    // smem opt-ins (idempotent)
    cudaFuncSetAttribute(gemm_tf32<0,0,0>, cudaFuncAttributeMaxDynamicSharedMemorySize, 107520);
    cudaFuncSetAttribute(gemm_tf32<0,1,1>, cudaFuncAttributeMaxDynamicSharedMemorySize, 107520);
    cudaFuncSetAttribute(gemm_tf32<0,2,1>, cudaFuncAttributeMaxDynamicSharedMemorySize, 107520);
    cudaFuncSetAttribute(gemm_tf32<1,0,1>, cudaFuncAttributeMaxDynamicSharedMemorySize, 107520);
    cudaFuncSetAttribute(qk_fused<1>,      cudaFuncAttributeMaxDynamicSharedMemorySize, 73728);
    cudaFuncSetAttribute(qk_fused<0>,      cudaFuncAttributeMaxDynamicSharedMemorySize, 73728);
    cudaFuncSetAttribute(av_tf32,          cudaFuncAttributeMaxDynamicSharedMemorySize, 82944);

    const float scale = 0.125f;   // 1/sqrt(64)
    const int rowsBS = Bc * Sc;   // 2048

    // ===== pre-round GEMM operands (weights / pemb / enc) =====
    auto RC = [&](const float* s_, float* d_, int n) {
        round_copy<<<n / 4 / 256, 256>>>((const float4*)s_, (float4*)d_, n / 4);
    };
    RC(Wq_m,  wWq_m,  1*MEG); RC(Wkv_m, wWkv_m, 2*MEG); RC(fcw_m, wfcw_m, 1*MEG);
    RC(Wq_c,  wWq_c,  1*MEG); RC(Wkv_c, wWkv_c, 2*MEG); RC(fcw_c, wfcw_c, 1*MEG);
    RC(W1,    wW1,    4*MEG); RC(W2,    wW2,    4*MEG);
    RC(pemb,  wpemb,  2*MEG); RC(enc,   wenc,   2*MEG);

    // ===== pre-norm 1 =====
    ln_kernel<<<rowsBS, 256>>>(x, ln1_g, ln1_b, xn, xnr, nullptr);

    // ===== self MHA (Transformer-XL relative attention) =====
    concat_kernel<<<(Bc * Stc * Dc) / 256, 256>>>(mem, xnr, hcat);
    gemm_tf32<0,1,1><<<dim3(8, 16), 256, 107520>>>(xnr, wWq_m, q, q2, Dc, Dc, u, vvec, nullptr, Sc);
    gemm_tf32<0,2,1><<<dim3(16, 32), 256, 107520>>>(hcat, wWkv_m, kk, vv, 2 * Dc, Dc, nullptr, nullptr, nullptr, Stc);

    qk_fused<1><<<dim3(16, 8, Zc), 256, 73728>>>(q, q2, kk, wpemb, scs, Sc, Stc);
    colmax<1><<<dim3(Stc / 128, Zc), 256>>>(scs, mx, Sc, Stc);
    colnorm<<<dim3(Stc / 128, Zc), 256>>>(scs, mx, iz, Sc, Stc, scale);
    vscale<<<(Zc * Stc * DHc / 4) / 256, 256>>>(vv, iz, vn, 11);
    av_tf32<<<dim3(8, Zc), 256, 82944>>>(scs, vn, o, Sc, Stc, 1);

    gemm_tf32<0,0,0><<<dim3(8, 16), 256, 107520>>>(o, wfcw_m, tmp, nullptr, Dc, Dc, fcb_m, nullptr, xn, 0);
    ln_kernel<<<rowsBS, 256>>>(tmp, lnm_g, lnm_b, o1, nullptr, x);     // out = x + LN(...)

    // ===== cross attention =====
    ln_kernel<<<rowsBS, 256>>>(o1, ln2_g, ln2_b, xn, xnr, nullptr);
    gemm_tf32<0,1,1><<<dim3(8, 16), 256, 107520>>>(xnr, wWq_c, q, nullptr, Dc, Dc, nullptr, nullptr, nullptr, Sc);
    gemm_tf32<0,2,1><<<dim3(16, 16), 256, 107520>>>(wenc, wWkv_c, kk, vv, 2 * Dc, Dc, nullptr, nullptr, nullptr, Sc);

    qk_fused<0><<<dim3(8, 8, Zc), 256, 73728>>>(q, nullptr, kk, nullptr, scs, Sc, Sc);
    colmax<0><<<dim3(Sc / 128, Zc), 256>>>(scs, mx, Sc, Sc);
    colnorm<<<dim3(Sc / 128, Zc), 256>>>(scs, mx, iz, Sc, Sc, scale);
    vscale<<<(Zc * Sc * DHc / 4) / 256, 256>>>(vv, iz, vn, 10);
    av_tf32<<<dim3(8, Zc), 256, 82944>>>(scs, vn, o, Sc, Sc, 0);

    gemm_tf32<0,0,0><<<dim3(8, 16), 256, 107520>>>(o, wfcw_c, tmp, nullptr, Dc, Dc, fcb_c, nullptr, xn, 0);
    ln_kernel<<<rowsBS, 256>>>(tmp, lnc_g, lnc_b, o2, nullptr, o1);    // out2 = out + LN(...)

    // ===== FFN =====
    ln_kernel<<<rowsBS, 256>>>(o2, ln3_g, ln3_b, xn, xnr, nullptr);
    gemm_tf32<1,0,1><<<dim3(32, 16), 256, 107520>>>(xnr, wW1, ff, nullptr, DFFc, Dc, b1, nullptr, nullptr, 0);
    gemm_tf32<0,0,0><<<dim3(8, 16), 256, 107520>>>(ff, wW2, out, nullptr, Dc, DFFc, b2, nullptr, o2, 0);
}

// round 6
// speedup vs baseline: 3.6428x; 1.0595x over previous
#include <cuda_runtime.h>
#include <math.h>
#include <stdint.h>

#define Bc 2
#define Sc 1024
#define Mc 1024
#define Dc 1024
#define Hc 16
#define DHc 64
#define DFFc 4096
#define Stc 2048
#define Zc (Bc*Hc)
#define MEG (1024*1024)
#define Q4 (MEG/4)

// ---------------- scratch (device globals: no allocation allowed) ----------------
__device__ float g_xn [Bc*Sc*Dc];            // exact LN output (residual use)
__device__ float g_xnr[Bc*Sc*Dc];            // tf32-rounded LN output (GEMM use)
__device__ float g_h  [Bc*Stc*Dc];           // concat(mem, xn) rounded
__device__ float g_q  [Zc*Sc*DHc];
__device__ float g_q2 [Zc*Sc*DHc];
__device__ float g_k  [(size_t)Zc*Stc*DHc];
__device__ float g_v  [(size_t)Zc*Stc*DHc];
__device__ float g_vn [(size_t)Zc*Stc*DHc];  // V * invZ
__device__ float g_scb[(size_t)Zc*Sc*Stc];   // logits / probs
__device__ uint32_t g_mxu[Zc*Stc];           // column max (ordered-uint keys)
__device__ float g_iz [Zc*Stc];              // column 1/sum
__device__ float g_o  [Bc*Sc*Dc];
__device__ float g_tmp[Bc*Sc*Dc];
__device__ float g_out[Bc*Sc*Dc];
__device__ float g_out2[Bc*Sc*Dc];
__device__ float g_ff [(size_t)Bc*Sc*DFFc];
__device__ float g_wts[20*MEG];              // rounded weights/pemb/enc

// offsets into g_wts (floats)
#define OFF_WQ_M   0
#define OFF_WKV_M  (1*MEG)
#define OFF_FCW_M  (3*MEG)
#define OFF_WQ_C   (4*MEG)
#define OFF_WKV_C  (5*MEG)
#define OFF_FCW_C  (7*MEG)
#define OFF_W1     (8*MEG)
#define OFF_W2     (12*MEG)
#define OFF_PEMB   (16*MEG)
#define OFF_ENC    (18*MEG)

// ---------------- helpers ----------------
__device__ __forceinline__ uint32_t f2tf(float f) {
    uint32_t r;
    asm("cvt.rna.tf32.f32 %0, %1;" : "=r"(r) : "f"(f));
    return r;
}
__device__ __forceinline__ float rnd_tf(float f) { return __uint_as_float(f2tf(f)); }

// order-preserving float <-> uint key (for atomicMax on floats incl. negatives)
__device__ __forceinline__ uint32_t fkey(float f) {
    uint32_t b = __float_as_uint(f);
    return (b & 0x80000000u) ? ~b : (b | 0x80000000u);
}
__device__ __forceinline__ float funkey(uint32_t k) {
    uint32_t b = (k & 0x80000000u) ? (k & 0x7FFFFFFFu) : ~k;
    return __uint_as_float(b);
}
#define KEY_NEGINF 0x00800000u   // fkey(-3.4028235e38f)

__device__ __forceinline__ void cpa16(uint32_t dst, const void* src) {
    asm volatile("cp.async.cg.shared.global [%0], [%1], 16;\n" :: "r"(dst), "l"(src));
}
__device__ __forceinline__ void cpa16z(uint32_t dst, const void* src, int srcbytes) {
    asm volatile("cp.async.cg.shared.global [%0], [%1], 16, %2;\n"
                 :: "r"(dst), "l"(src), "r"(srcbytes));
}
#define CP_COMMIT() asm volatile("cp.async.commit_group;\n")
#define CP_WAIT0()  asm volatile("cp.async.wait_group 0;\n")
#define CP_WAIT1()  asm volatile("cp.async.wait_group 1;\n")
#define CP_WAIT2()  asm volatile("cp.async.wait_group 2;\n")

__device__ __forceinline__ void mma8(float* c, const uint32_t* a, const uint32_t* b) {
    asm volatile(
        "mma.sync.aligned.m16n8k8.row.col.f32.tf32.tf32.f32 "
        "{%0,%1,%2,%3}, {%4,%5,%6,%7}, {%8,%9}, {%0,%1,%2,%3};\n"
        : "+f"(c[0]), "+f"(c[1]), "+f"(c[2]), "+f"(c[3])
        : "r"(a[0]), "r"(a[1]), "r"(a[2]), "r"(a[3]), "r"(b[0]), "r"(b[1]));
}

// ---------------- merged pre-round: all weights + pemb + enc + mem->hcat ----------
__global__ void round_all(
    const float4* __restrict__ wq_m, const float4* __restrict__ wkv_m,
    const float4* __restrict__ fcw_m, const float4* __restrict__ wq_c,
    const float4* __restrict__ wkv_c, const float4* __restrict__ fcw_c,
    const float4* __restrict__ w1, const float4* __restrict__ w2,
    const float4* __restrict__ pemb, const float4* __restrict__ enc,
    const float4* __restrict__ mem, float4* __restrict__ w, float4* __restrict__ hc)
{
    int i = blockIdx.x * 256 + threadIdx.x;          // f4 index, total 22*Q4
    const float4* s;
    float4* d;
    if (i < 20 * Q4) {
        d = w + i;
        if      (i <  1 * Q4) s = wq_m  + i;
        else if (i <  3 * Q4) s = wkv_m + (i -  1 * Q4);
        else if (i <  4 * Q4) s = fcw_m + (i -  3 * Q4);
        else if (i <  5 * Q4) s = wq_c  + (i -  4 * Q4);
        else if (i <  7 * Q4) s = wkv_c + (i -  5 * Q4);
        else if (i <  8 * Q4) s = fcw_c + (i -  7 * Q4);
        else if (i < 12 * Q4) s = w1    + (i -  8 * Q4);
        else if (i < 16 * Q4) s = w2    + (i - 12 * Q4);
        else if (i < 18 * Q4) s = pemb  + (i - 16 * Q4);
        else                  s = enc   + (i - 18 * Q4);
    } else {
        int m = i - 20 * Q4;                         // mem: 2 batches x Q4 f4
        int b = m / Q4;
        int t4 = m - b * Q4;
        s = mem + m;
        d = hc + (size_t)b * (Stc * Dc / 4) + t4;    // hcat top half (t < M)
    }
    float4 v = *s;
    float4 o = { rnd_tf(v.x), rnd_tf(v.y), rnd_tf(v.z), rnd_tf(v.w) };
    *d = o;
}

// ---------------- init column-max keys ----------------
__global__ void init_mx(uint32_t* __restrict__ m, int n)
{
    int i = blockIdx.x * 256 + threadIdx.x;
    if (i < n) m[i] = KEY_NEGINF;
}

// ---------------- dense GEMM, cp.async 3-stage, tf32 MMA ----------------
// EPI=0: C = [RND](act(A@B + bias) + Res)
// EPI=1: head-split q write; EPI=2: kv split
template<int ACT, int EPI, int RND>
__global__ void __launch_bounds__(256, 2)
gemm_tf32(const float* __restrict__ A, const float* __restrict__ Bm,
          float* __restrict__ C, float* __restrict__ C2,
          int N, int K, const float* __restrict__ bias, const float* __restrict__ bias2,
          const float* __restrict__ Res, int Sk)
{
    extern __shared__ float sm[];
    const int tid = threadIdx.x, lane = tid & 31, wid = tid >> 5;
    const int wm = wid & 1, wn = wid >> 1;
    const int lr = lane >> 2, lc = lane & 3;
    const int row0 = blockIdx.y * 128, col0 = blockIdx.x * 128;
    const uint32_t smb = (uint32_t)__cvta_generic_to_shared(sm);

    float acc[4][4][4];
#pragma unroll
    for (int mt = 0; mt < 4; mt++)
#pragma unroll
        for (int nt = 0; nt < 4; nt++)
#pragma unroll
            for (int e = 0; e < 4; e++) acc[mt][nt][e] = 0.f;

    const int nk = K / 32;
    auto loadAB = [&](int s, int k0) {
#pragma unroll
        for (int it = 0; it < 4; it++) {
            int lin = tid + it * 256;
            int r = lin >> 3, k4 = (lin & 7) * 4;
            cpa16(smb + (uint32_t)(s * 4608 + r * 36 + k4) * 4,
                  &A[(size_t)(row0 + r) * K + k0 + k4]);
        }
#pragma unroll
        for (int it = 0; it < 4; it++) {
            int lin = tid + it * 256;
            int r = lin >> 5, n4 = (lin & 31) * 4;
            cpa16(smb + (uint32_t)(13824 + s * 4352 + r * 136 + n4) * 4,
                  &Bm[(size_t)(k0 + r) * N + col0 + n4]);
        }
        CP_COMMIT();
    };

    loadAB(0, 0);
    if (nk > 1) loadAB(1, 32);
    for (int kt = 0; kt < nk; kt++) {
        if (kt + 2 < nk) { loadAB((kt + 2) % 3, (kt + 2) * 32); CP_WAIT2(); }
        else if (kt + 1 < nk) CP_WAIT1();
        else CP_WAIT0();
        __syncthreads();
        const float* As = sm + (kt % 3) * 4608;
        const float* Bs = sm + 13824 + (kt % 3) * 4352;
#pragma unroll
        for (int k8 = 0; k8 < 32; k8 += 8) {
            uint32_t a[4][4], b[4][2];
#pragma unroll
            for (int mt = 0; mt < 4; mt++) {
                int r = wm * 64 + mt * 16 + lr;
                a[mt][0] = __float_as_uint(As[r * 36 + k8 + lc]);
                a[mt][1] = __float_as_uint(As[(r + 8) * 36 + k8 + lc]);
                a[mt][2] = __float_as_uint(As[r * 36 + k8 + lc + 4]);
                a[mt][3] = __float_as_uint(As[(r + 8) * 36 + k8 + lc + 4]);
            }
#pragma unroll
            for (int nt = 0; nt < 4; nt++) {
                int c = wn * 32 + nt * 8 + lr;
                b[nt][0] = __float_as_uint(Bs[(k8 + lc) * 136 + c]);
                b[nt][1] = __float_as_uint(Bs[(k8 + lc + 4) * 136 + c]);
            }
#pragma unroll
            for (int mt = 0; mt < 4; mt++)
#pragma unroll
                for (int nt = 0; nt < 4; nt++)
                    mma8(acc[mt][nt], a[mt], b[nt]);
        }
        __syncthreads();
    }

#pragma unroll
    for (int mt = 0; mt < 4; mt++)
#pragma unroll
        for (int nt = 0; nt < 4; nt++) {
            int r_ = row0 + wm * 64 + mt * 16 + lr;
            int c_ = col0 + wn * 32 + nt * 8 + 2 * lc;
#pragma unroll
            for (int hf = 0; hf < 2; hf++) {
                int rr = r_ + hf * 8;
                float v0 = acc[mt][nt][hf * 2 + 0];
                float v1 = acc[mt][nt][hf * 2 + 1];
                if (EPI == 0) {
                    if (bias) { v0 += bias[c_]; v1 += bias[c_ + 1]; }
                    if (ACT == 1) {
                        v0 = 0.5f * v0 * (1.0f + erff(v0 * 0.70710678118654752f));
                        v1 = 0.5f * v1 * (1.0f + erff(v1 * 0.70710678118654752f));
                    }
                    if (Res) {
                        v0 += Res[(size_t)rr * N + c_];
                        v1 += Res[(size_t)rr * N + c_ + 1];
                    }
                    if (RND) { v0 = rnd_tf(v0); v1 = rnd_tf(v1); }
                    C[(size_t)rr * N + c_]     = v0;
                    C[(size_t)rr * N + c_ + 1] = v1;
                } else if (EPI == 1) {
                    int b = rr >> 10, i = rr & 1023;
#pragma unroll
                    for (int e = 0; e < 2; e++) {
                        int cc = c_ + e;
                        int h = cc >> 6, d = cc & 63;
                        float val = e ? v1 : v0;
                        size_t dst = (((size_t)(b * Hc + h)) * Sc + i) * DHc + d;
                        C[dst] = rnd_tf(val + (bias ? bias[cc] : 0.f));
                        if (C2) C2[dst] = rnd_tf(val + bias2[cc]);
                    }
                } else { // EPI == 2
                    int b = rr / Sk, j = rr % Sk;
#pragma unroll
                    for (int e = 0; e < 2; e++) {
                        int cc = c_ + e;
                        int isv = cc >> 10;
                        int h = (cc & 1023) >> 6, d = cc & 63;
                        float val = e ? v1 : v0;
                        size_t dst = (((size_t)(b * Hc + h)) * Sk + j) * DHc + d;
                        (isv ? C2 : C)[dst] = rnd_tf(val);
                    }
                }
            }
        }
}

// ---------------- fused QK^T + shifted-pos + mask + column-max atomics ----------
// RELS=1: acc = Q·K^T + Q2shift·PE^T ; masked -> -1e30; fully-masked tiles skipped.
// RELS=0: acc = Q·K^T (cross attention).
// Both: per-column max contributed to Mxu via atomicMax on ordered keys.
template<int RELS>
__global__ void __launch_bounds__(256, 2)
qk_fused(const float* __restrict__ Q, const float* __restrict__ Q2,
         const float* __restrict__ Kk, const float* __restrict__ PE,
         float* __restrict__ Out, uint32_t* __restrict__ Mxu, int Srows, int Sk)
{
    extern __shared__ float sm[];
    const int tid = threadIdx.x, lane = tid & 31, wid = tid >> 5;
    const int wm = wid & 1, wn = wid >> 1;
    const int lr = lane >> 2, lc = lane & 3;
    const int z = blockIdx.z;
    const int j0 = blockIdx.x * 128, i0 = blockIdx.y * 128;
    const int bb = z >> 4, hh = z & 15;
    const uint32_t smb = (uint32_t)__cvta_generic_to_shared(sm);

    if (RELS && j0 > i0 + 127 + Mc) return;   // fully masked: colnorm zero-fills

    float acc[4][4][4];
#pragma unroll
    for (int mt = 0; mt < 4; mt++)
#pragma unroll
        for (int nt = 0; nt < 4; nt++)
#pragma unroll
            for (int e = 0; e < 4; e++) acc[mt][nt][e] = 0.f;

#pragma unroll
    for (int d0 = 0; d0 < DHc; d0 += 32) {
#pragma unroll
        for (int it = 0; it < 4; it++) {
            int lin = tid + it * 256;
            int r = lin >> 3, k4 = (lin & 7) * 4;
            cpa16(smb + (uint32_t)(r * 36 + k4) * 4,
                  &Q[((size_t)z * Srows + i0 + r) * DHc + d0 + k4]);
            cpa16(smb + (uint32_t)(4608 + r * 36 + k4) * 4,
                  &Kk[((size_t)z * Sk + j0 + r) * DHc + d0 + k4]);
            if (RELS) {
                int srcrow = i0 + r + (bb == 0 ? 1 : 0);
                int ok = srcrow < Srows;
                cpa16z(smb + (uint32_t)(9216 + r * 36 + k4) * 4,
                       &Q2[((size_t)z * Srows + (ok ? srcrow : 0)) * DHc + d0 + k4],
                       ok ? 16 : 0);
                cpa16(smb + (uint32_t)(13824 + r * 36 + k4) * 4,
                      &PE[(size_t)(j0 + r) * Dc + hh * DHc + d0 + k4]);
            }
        }
        CP_COMMIT();
        CP_WAIT0();
        __syncthreads();

        const float* Qs  = sm;
        const float* Ks  = sm + 4608;
        const float* Q2s = sm + 9216;
        const float* Ps  = sm + 13824;
#pragma unroll
        for (int k8 = 0; k8 < 32; k8 += 8) {
            uint32_t a[4][4], b[4][2];
#pragma unroll
            for (int mt = 0; mt < 4; mt++) {
                int r = wm * 64 + mt * 16 + lr;
                a[mt][0] = __float_as_uint(Qs[r * 36 + k8 + lc]);
                a[mt][1] = __float_as_uint(Qs[(r + 8) * 36 + k8 + lc]);
                a[mt][2] = __float_as_uint(Qs[r * 36 + k8 + lc + 4]);
                a[mt][3] = __float_as_uint(Qs[(r + 8) * 36 + k8 + lc + 4]);
            }
#pragma unroll
            for (int nt = 0; nt < 4; nt++) {
                int c = wn * 32 + nt * 8 + lr;
                b[nt][0] = __float_as_uint(Ks[c * 36 + k8 + lc]);
                b[nt][1] = __float_as_uint(Ks[c * 36 + k8 + lc + 4]);
            }
#pragma unroll
            for (int mt = 0; mt < 4; mt++)
#pragma unroll
                for (int nt = 0; nt < 4; nt++)
                    mma8(acc[mt][nt], a[mt], b[nt]);
            if (RELS) {
#pragma unroll
                for (int mt = 0; mt < 4; mt++) {
                    int r = wm * 64 + mt * 16 + lr;
                    a[mt][0] = __float_as_uint(Q2s[r * 36 + k8 + lc]);
                    a[mt][1] = __float_as_uint(Q2s[(r + 8) * 36 + k8 + lc]);
                    a[mt][2] = __float_as_uint(Q2s[r * 36 + k8 + lc + 4]);
                    a[mt][3] = __float_as_uint(Q2s[(r + 8) * 36 + k8 + lc + 4]);
                }
#pragma unroll
                for (int nt = 0; nt < 4; nt++) {
                    int c = wn * 32 + nt * 8 + lr;
                    b[nt][0] = __float_as_uint(Ps[c * 36 + k8 + lc]);
                    b[nt][1] = __float_as_uint(Ps[c * 36 + k8 + lc + 4]);
                }
#pragma unroll
                for (int mt = 0; mt < 4; mt++)
#pragma unroll
                    for (int nt = 0; nt < 4; nt++)
                        mma8(acc[mt][nt], a[mt], b[nt]);
            }
        }
        __syncthreads();
    }

    float cmax[4][2];
#pragma unroll
    for (int nt = 0; nt < 4; nt++) { cmax[nt][0] = -3.4e38f; cmax[nt][1] = -3.4e38f; }

#pragma unroll
    for (int mt = 0; mt < 4; mt++)
#pragma unroll
        for (int nt = 0; nt < 4; nt++) {
            int i_ = i0 + wm * 64 + mt * 16 + lr;
            int j_ = j0 + wn * 32 + nt * 8 + 2 * lc;
#pragma unroll
            for (int hf = 0; hf < 2; hf++) {
                int ii = i_ + hf * 8;
#pragma unroll
                for (int e = 0; e < 2; e++) {
                    int jj = j_ + e;
                    float val = acc[mt][nt][hf * 2 + e];
                    if (RELS && jj > ii + Mc) val = -1e30f;   // mask BEFORE scale
                    Out[((size_t)z * Srows + ii) * Sk + jj] = val;
                    cmax[nt][e] = fmaxf(cmax[nt][e], val);
                }
            }
        }

    // reduce column-max over lr lanes, then atomics from lr==0 lanes
#pragma unroll
    for (int off = 4; off <= 16; off <<= 1)
#pragma unroll
        for (int nt = 0; nt < 4; nt++)
#pragma unroll
            for (int e = 0; e < 2; e++)
                cmax[nt][e] = fmaxf(cmax[nt][e],
                                    __shfl_xor_sync(0xffffffffu, cmax[nt][e], off));
    if (lane < 4) {
#pragma unroll
        for (int nt = 0; nt < 4; nt++)
#pragma unroll
            for (int e = 0; e < 2; e++) {
                int jj = j0 + wn * 32 + nt * 8 + 2 * lc + e;
                atomicMax(&Mxu[(size_t)z * Sk + jj], fkey(cmax[nt][e]));
            }
    }
}

// ---------------- column normalize: zero masked region (no read), exp elsewhere ---
template<int CAUS>
__global__ void colnorm(float* __restrict__ P, const uint32_t* __restrict__ Mxu,
                        float* __restrict__ InvZ, int Srows, int Sk, float scale)
{
    __shared__ float red[256];
    const int z = blockIdx.y;
    const int j = blockIdx.x * 128 + (threadIdx.x & 127);
    const int ty = threadIdx.x >> 7;
    const float msc = funkey(Mxu[(size_t)z * Sk + j]) * scale;
    float* base = P + (size_t)z * Srows * Sk + j;
    const int zend = CAUS ? min(Srows, max(0, j - Mc)) : 0;  // i < j-M is masked
    float s = 0.f;
#pragma unroll 4
    for (int i = ty; i < Srows; i += 2) {
        if (i < zend) {
            base[(size_t)i * Sk] = 0.f;
        } else {
            float p = __expf(base[(size_t)i * Sk] * scale - msc);
            base[(size_t)i * Sk] = rnd_tf(p);
            s += p;
        }
    }
    red[threadIdx.x] = s;
    __syncthreads();
    if (ty == 0)
        InvZ[(size_t)z * Sk + j] = 1.f / (red[threadIdx.x] + red[threadIdx.x + 128]);
}

// ---------------- Vn = rnd(V * invZ[j]) ----------------
__global__ void vscale(const float* __restrict__ V, const float* __restrict__ InvZ,
                       float* __restrict__ Vn)
{
    int idx = blockIdx.x * 256 + threadIdx.x;      // over Z*Sk*16 float4s
    int zj = idx >> 4;                              // z*Sk + j
    float iz = InvZ[zj];
    float4 v = ((const float4*)V)[idx];
    float4 o = { rnd_tf(v.x * iz), rnd_tf(v.y * iz), rnd_tf(v.z * iz), rnd_tf(v.w * iz) };
    ((float4*)Vn)[idx] = o;
}

// ---------------- AV (cp.async 3-stage): O[b,i,h*64+d] = sum_j P*Vn ---------------
__global__ void __launch_bounds__(256, 2)
av_tf32(const float* __restrict__ P, const float* __restrict__ V,
        float* __restrict__ O, int Srows, int Sk, int caus)
{
    extern __shared__ float sm[];
    const int tid = threadIdx.x, lane = tid & 31, wid = tid >> 5;
    const int wm = wid >> 1, wn = wid & 1;    // 4 x 2 warps
    const int lr = lane >> 2, lc = lane & 3;
    const int z = blockIdx.y;
    const int i0 = blockIdx.x * 128;
    const int bb = z >> 4, hh = z & 15;
    const uint32_t smb = (uint32_t)__cvta_generic_to_shared(sm);

    float acc[2][4][4];
#pragma unroll
    for (int mt = 0; mt < 2; mt++)
#pragma unroll
        for (int nt = 0; nt < 4; nt++)
#pragma unroll
            for (int e = 0; e < 4; e++) acc[mt][nt][e] = 0.f;

    auto loadPV = [&](int s, int j0) {
#pragma unroll
        for (int it = 0; it < 4; it++) {
            int lin = tid + it * 256;
            int r = lin >> 3, k4 = (lin & 7) * 4;
            cpa16(smb + (uint32_t)(s * 4608 + r * 36 + k4) * 4,
                  &P[((size_t)z * Srows + i0 + r) * Sk + j0 + k4]);
        }
#pragma unroll
        for (int it = 0; it < 2; it++) {
            int lin = tid + it * 256;
            int r = lin >> 4, n4 = (lin & 15) * 4;
            cpa16(smb + (uint32_t)(13824 + s * 2304 + r * 72 + n4) * 4,
                  &V[((size_t)z * Sk + j0 + r) * DHc + n4]);
        }
        CP_COMMIT();
    };

    int nk = Sk / 32;
    if (caus) nk = min(nk, (i0 + 127 + Mc) / 32 + 1);   // P==0 beyond the mask
    loadPV(0, 0);
    if (nk > 1) loadPV(1, 32);
    for (int kt = 0; kt < nk; kt++) {
        if (kt + 2 < nk) { loadPV((kt + 2) % 3, (kt + 2) * 32); CP_WAIT2(); }
        else if (kt + 1 < nk) CP_WAIT1();
        else CP_WAIT0();
        __syncthreads();
        const float* Ps = sm + (kt % 3) * 4608;
        const float* Vs = sm + 13824 + (kt % 3) * 2304;
#pragma unroll
        for (int k8 = 0; k8 < 32; k8 += 8) {
            uint32_t a[2][4], b[4][2];
#pragma unroll
            for (int mt = 0; mt < 2; mt++) {
                int r = wm * 32 + mt * 16 + lr;
                a[mt][0] = __float_as_uint(Ps[r * 36 + k8 + lc]);
                a[mt][1] = __float_as_uint(Ps[(r + 8) * 36 + k8 + lc]);
                a[mt][2] = __float_as_uint(Ps[r * 36 + k8 + lc + 4]);
                a[mt][3] = __float_as_uint(Ps[(r + 8) * 36 + k8 + lc + 4]);
            }
#pragma unroll
            for (int nt = 0; nt < 4; nt++) {
                int c = wn * 32 + nt * 8 + lr;
                b[nt][0] = __float_as_uint(Vs[(k8 + lc) * 72 + c]);
                b[nt][1] = __float_as_uint(Vs[(k8 + lc + 4) * 72 + c]);
            }
#pragma unroll
            for (int mt = 0; mt < 2; mt++)
#pragma unroll
                for (int nt = 0; nt < 4; nt++)
                    mma8(acc[mt][nt], a[mt], b[nt]);
        }
        __syncthreads();
    }

#pragma unroll
    for (int mt = 0; mt < 2; mt++)
#pragma unroll
        for (int nt = 0; nt < 4; nt++) {
            int i_ = i0 + wm * 32 + mt * 16 + lr;
            int d_ = wn * 32 + nt * 8 + 2 * lc;
#pragma unroll
            for (int hf = 0; hf < 2; hf++) {
                int ii = i_ + hf * 8;
                size_t o = ((size_t)(bb * Sc) + ii) * Dc + hh * DHc + d_;
                O[o]     = rnd_tf(acc[mt][nt][hf * 2 + 0]);
                O[o + 1] = rnd_tf(acc[mt][nt][hf * 2 + 1]);
            }
        }
}

// ---------------- LayerNorm: Y=LN(X)+Res exact; Yr=rnd; Yr2=rnd into hcat slot ----
__global__ void ln_kernel(const float* __restrict__ X, const float* __restrict__ gw,
                          const float* __restrict__ bw, float* __restrict__ Y,
                          float* __restrict__ Yr, float* __restrict__ Yr2,
                          const float* __restrict__ Res)
{
    __shared__ float s1[256], s2[256];
    const int row = blockIdx.x;
    const int tid = threadIdx.x;
    const float* x = X + (size_t)row * Dc;
    float4 v = *(const float4*)&x[tid * 4];
    s1[tid] = v.x + v.y + v.z + v.w;
    s2[tid] = v.x * v.x + v.y * v.y + v.z * v.z + v.w * v.w;
    __syncthreads();
    for (int st = 128; st > 0; st >>= 1) {
        if (tid < st) { s1[tid] += s1[tid + st]; s2[tid] += s2[tid + st]; }
        __syncthreads();
    }
    float mu = s1[0] * (1.f / Dc);
    float var = s2[0] * (1.f / Dc) - mu * mu;
    float rinv = rsqrtf(var + 1e-5f);
    float4 g4 = *(const float4*)&gw[tid * 4];
    float4 b4 = *(const float4*)&bw[tid * 4];
    float4 o;
    o.x = (v.x - mu) * rinv * g4.x + b4.x;
    o.y = (v.y - mu) * rinv * g4.y + b4.y;
    o.z = (v.z - mu) * rinv * g4.z + b4.z;
    o.w = (v.w - mu) * rinv * g4.w + b4.w;
    if (Res) {
        float4 r4 = *(const float4*)&Res[(size_t)row * Dc + tid * 4];
        o.x += r4.x; o.y += r4.y; o.z += r4.z; o.w += r4.w;
    }
    *(float4*)&Y[(size_t)row * Dc + tid * 4] = o;
    if (Yr || Yr2) {
        float4 r = { rnd_tf(o.x), rnd_tf(o.y), rnd_tf(o.z), rnd_tf(o.w) };
        if (Yr) *(float4*)&Yr[(size_t)row * Dc + tid * 4] = r;
        if (Yr2) {
            int b = row >> 10;   // hcat bottom half: row b*Stc + M + i
            *(float4*)&Yr2[((size_t)(row + (b + 1) * Mc)) * Dc + tid * 4] = r;
        }
    }
}

// ---------------- host-side launcher ----------------
static inline float* sym(const void* s)
{
    void* p = nullptr;
    cudaGetSymbolAddress(&p, s);
    return (float*)p;
}

extern "C" void kernel_launch(void* const* d_in, const int* in_sizes, int n_in,
                              void* d_out, int out_size)
{
    const float* x     = (const float*)d_in[0];
    const float* enc   = (const float*)d_in[1];
    const float* pemb  = (const float*)d_in[2];
    const float* u     = (const float*)d_in[3];
    const float* vvec  = (const float*)d_in[4];
    const float* mem   = (const float*)d_in[5];
    // d_in[6] = tgt_mask (bool) — recomputed analytically
    const float* Wq_m  = (const float*)d_in[7];
    const float* Wkv_m = (const float*)d_in[8];
    const float* fcw_m = (const float*)d_in[9];
    const float* fcb_m = (const float*)d_in[10];
    const float* lnm_g = (const float*)d_in[11];
    const float* lnm_b = (const float*)d_in[12];
    const float* Wq_c  = (const float*)d_in[13];
    const float* Wkv_c = (const float*)d_in[14];
    const float* fcw_c = (const float*)d_in[15];
    const float* fcb_c = (const float*)d_in[16];
    const float* lnc_g = (const float*)d_in[17];
    const float* lnc_b = (const float*)d_in[18];
    const float* W1    = (const float*)d_in[19];
    const float* b1    = (const float*)d_in[20];
    const float* W2    = (const float*)d_in[21];
    const float* b2    = (const float*)d_in[22];
    const float* ln1_g = (const float*)d_in[23];
    const float* ln1_b = (const float*)d_in[24];
    const float* ln2_g = (const float*)d_in[25];
    const float* ln2_b = (const float*)d_in[26];
    const float* ln3_g = (const float*)d_in[27];
    const float* ln3_b = (const float*)d_in[28];
    float* out = (float*)d_out;

    float* xn  = sym(g_xn);   float* xnr  = sym(g_xnr); float* hcat = sym(g_h);
    float* q   = sym(g_q);    float* q2   = sym(g_q2);
    float* kk  = sym(g_k);    float* vv   = sym(g_v);   float* vn = sym(g_vn);
    float* scs = sym(g_scb);  float* iz   = sym(g_iz);
    uint32_t* mxu = (uint32_t*)sym(g_mxu);
    float* o   = sym(g_o);    float* tmp  = sym(g_tmp);
    float* o1  = sym(g_out);  float* o2   = sym(g_out2);
    float* ff  = sym(g_ff);   float* w    = sym(g_wts);

    float* wWq_m  = w + OFF_WQ_M;
    float* wWkv_m = w + OFF_WKV_M;
    float* wfcw_m = w + OFF_FCW_M;
    float* wWq_c  = w + OFF_WQ_C;
    float* wWkv_c = w + OFF_WKV_C;
    float* wfcw_c = w + OFF_FCW_C;
    float* wW1    = w + OFF_W1;
    float* wW2    = w + OFF_W2;
    float* wpemb  = w + OFF_PEMB;
    float* wenc   = w + OFF_ENC;

    // smem opt-ins (idempotent)
    cudaFuncSetAttribute(gemm_tf32<0,0,0>, cudaFuncAttributeMaxDynamicSharedMemorySize, 107520);
    cudaFuncSetAttribute(gemm_tf32<0,1,1>, cudaFuncAttributeMaxDynamicSharedMemorySize, 107520);
    cudaFuncSetAttribute(gemm_tf32<0,2,1>, cudaFuncAttributeMaxDynamicSharedMemorySize, 107520);
    cudaFuncSetAttribute(gemm_tf32<1,0,1>, cudaFuncAttributeMaxDynamicSharedMemorySize, 107520);
    cudaFuncSetAttribute(qk_fused<1>,      cudaFuncAttributeMaxDynamicSharedMemorySize, 73728);
    cudaFuncSetAttribute(qk_fused<0>,      cudaFuncAttributeMaxDynamicSharedMemorySize, 73728);
    cudaFuncSetAttribute(av_tf32,          cudaFuncAttributeMaxDynamicSharedMemorySize, 82944);

    const float scale = 0.125f;   // 1/sqrt(64)
    const int rowsBS = Bc * Sc;   // 2048

    // ===== 1: merged pre-round (weights/pemb/enc -> g_wts, mem -> hcat top) =====
    round_all<<<22 * Q4 / 256, 256>>>(
        (const float4*)Wq_m, (const float4*)Wkv_m, (const float4*)fcw_m,
        (const float4*)Wq_c, (const float4*)Wkv_c, (const float4*)fcw_c,
        (const float4*)W1, (const float4*)W2, (const float4*)pemb,
        (const float4*)enc, (const float4*)mem, (float4*)w, (float4*)hcat);

    // ===== 2: pre-norm 1 (also fills hcat bottom half) =====
    ln_kernel<<<rowsBS, 256>>>(x, ln1_g, ln1_b, xn, xnr, hcat, nullptr);

    // ===== self MHA (Transformer-XL relative attention) =====
    gemm_tf32<0,1,1><<<dim3(8, 16), 256, 107520>>>(xnr, wWq_m, q, q2, Dc, Dc, u, vvec, nullptr, Sc);
    gemm_tf32<0,2,1><<<dim3(16, 32), 256, 107520>>>(hcat, wWkv_m, kk, vv, 2 * Dc, Dc, nullptr, nullptr, nullptr, Stc);
    init_mx<<<(Zc * Stc) / 256, 256>>>(mxu, Zc * Stc);

    qk_fused<1><<<dim3(16, 8, Zc), 256, 73728>>>(q, q2, kk, wpemb, scs, mxu, Sc, Stc);
    colnorm<1><<<dim3(Stc / 128, Zc), 256>>>(scs, mxu, iz, Sc, Stc, scale);
    vscale<<<(Zc * Stc * DHc / 4) / 256, 256>>>(vv, iz, vn);
    av_tf32<<<dim3(8, Zc), 256, 82944>>>(scs, vn, o, Sc, Stc, 1);

    gemm_tf32<0,0,0><<<dim3(8, 16), 256, 107520>>>(o, wfcw_m, tmp, nullptr, Dc, Dc, fcb_m, nullptr, xn, 0);
    ln_kernel<<<rowsBS, 256>>>(tmp, lnm_g, lnm_b, o1, nullptr, nullptr, x);   // out = x + LN(...)

    // ===== cross attention =====
    ln_kernel<<<rowsBS, 256>>>(o1, ln2_g, ln2_b, xn, xnr, nullptr, nullptr);
    gemm_tf32<0,1,1><<<dim3(8, 16), 256, 107520>>>(xnr, wWq_c, q, nullptr, Dc, Dc, nullptr, nullptr, nullptr, Sc);
    gemm_tf32<0,2,1><<<dim3(16, 16), 256, 107520>>>(wenc, wWkv_c, kk, vv, 2 * Dc, Dc, nullptr, nullptr, nullptr, Sc);
    init_mx<<<(Zc * Sc) / 256, 256>>>(mxu, Zc * Sc);

    qk_fused<0><<<dim3(8, 8, Zc), 256, 73728>>>(q, nullptr, kk, nullptr, scs, mxu, Sc, Sc);
    colnorm<0><<<dim3(Sc / 128, Zc), 256>>>(scs, mxu, iz, Sc, Sc, scale);
    vscale<<<(Zc * Sc * DHc / 4) / 256, 256>>>(vv, iz, vn);
    av_tf32<<<dim3(8, Zc), 256, 82944>>>(scs, vn, o, Sc, Sc, 0);

    gemm_tf32<0,0,0><<<dim3(8, 16), 256, 107520>>>(o, wfcw_c, tmp, nullptr, Dc, Dc, fcb_c, nullptr, xn, 0);
    ln_kernel<<<rowsBS, 256>>>(tmp, lnc_g, lnc_b, o2, nullptr, nullptr, o1);  // out2 = out + LN(...)

    // ===== FFN =====
    ln_kernel<<<rowsBS, 256>>>(o2, ln3_g, ln3_b, xn, xnr, nullptr, nullptr);
    gemm_tf32<1,0,1><<<dim3(32, 16), 256, 107520>>>(xnr, wW1, ff, nullptr, DFFc, Dc, b1, nullptr, nullptr, 0);
    gemm_tf32<0,0,0><<<dim3(8, 16), 256, 107520>>>(ff, wW2, out, nullptr, Dc, DFFc, b2, nullptr, o2, 0);
}

// round 8
// speedup vs baseline: 3.6604x; 1.0048x over previous
#include <cuda_runtime.h>
#include <math.h>
#include <stdint.h>

#define Bc 2
#define Sc 1024
#define Mc 1024
#define Dc 1024
#define Hc 16
#define DHc 64
#define DFFc 4096
#define Stc 2048
#define Zc (Bc*Hc)
#define MEG (1024*1024)
#define Q4 (MEG/4)

// ---------------- scratch (device globals: no allocation allowed) ----------------
__device__ float g_xn [Bc*Sc*Dc];            // exact LN output (residual use)
__device__ float g_xnr[Bc*Sc*Dc];            // tf32-rounded LN output (GEMM use)
__device__ float g_h  [Bc*Stc*Dc];           // concat(mem, xn) rounded
__device__ float g_q  [Zc*Sc*DHc];
__device__ float g_q2 [Zc*Sc*DHc];
__device__ float g_k  [(size_t)Zc*Stc*DHc];
__device__ float g_v  [(size_t)Zc*Stc*DHc];
__device__ float g_vn [(size_t)Zc*Stc*DHc];  // V * invZ
__device__ float g_scb[(size_t)Zc*Sc*Stc];   // logits / probs
__device__ uint32_t g_mxu[Zc*Stc];           // column max (ordered-uint keys)
__device__ float g_iz [Zc*Stc];              // column 1/sum
__device__ float g_o  [Bc*Sc*Dc];
__device__ float g_tmp[Bc*Sc*Dc];
__device__ float g_out[Bc*Sc*Dc];
__device__ float g_out2[Bc*Sc*Dc];
__device__ float g_ff [(size_t)Bc*Sc*DFFc];
__device__ float g_wts[20*MEG];              // rounded weights/pemb/enc

// offsets into g_wts (floats)
#define OFF_WQ_M   0
#define OFF_WKV_M  (1*MEG)
#define OFF_FCW_M  (3*MEG)
#define OFF_WQ_C   (4*MEG)
#define OFF_WKV_C  (5*MEG)
#define OFF_FCW_C  (7*MEG)
#define OFF_W1     (8*MEG)
#define OFF_W2     (12*MEG)
#define OFF_PEMB   (16*MEG)
#define OFF_ENC    (18*MEG)

// ---------------- helpers ----------------
__device__ __forceinline__ uint32_t f2tf(float f) {
    uint32_t r;
    asm("cvt.rna.tf32.f32 %0, %1;" : "=r"(r) : "f"(f));
    return r;
}
__device__ __forceinline__ float rnd_tf(float f) { return __uint_as_float(f2tf(f)); }

__device__ __forceinline__ uint32_t fkey(float f) {
    uint32_t b = __float_as_uint(f);
    return (b & 0x80000000u) ? ~b : (b | 0x80000000u);
}
__device__ __forceinline__ float funkey(uint32_t k) {
    uint32_t b = (k & 0x80000000u) ? (k & 0x7FFFFFFFu) : ~k;
    return __uint_as_float(b);
}
#define KEY_NEGINF 0x00800000u

__device__ __forceinline__ void cpa16(uint32_t dst, const void* src) {
    asm volatile("cp.async.cg.shared.global [%0], [%1], 16;\n" :: "r"(dst), "l"(src));
}
__device__ __forceinline__ void cpa16z(uint32_t dst, const void* src, int srcbytes) {
    asm volatile("cp.async.cg.shared.global [%0], [%1], 16, %2;\n"
                 :: "r"(dst), "l"(src), "r"(srcbytes));
}
#define CP_COMMIT() asm volatile("cp.async.commit_group;\n")
#define CP_WAIT0()  asm volatile("cp.async.wait_group 0;\n")
#define CP_WAIT1()  asm volatile("cp.async.wait_group 1;\n")
#define CP_WAIT2()  asm volatile("cp.async.wait_group 2;\n")

__device__ __forceinline__ void mma8(float* c, const uint32_t* a, const uint32_t* b) {
    asm volatile(
        "mma.sync.aligned.m16n8k8.row.col.f32.tf32.tf32.f32 "
        "{%0,%1,%2,%3}, {%4,%5,%6,%7}, {%8,%9}, {%0,%1,%2,%3};\n"
        : "+f"(c[0]), "+f"(c[1]), "+f"(c[2]), "+f"(c[3])
        : "r"(a[0]), "r"(a[1]), "r"(a[2]), "r"(a[3]), "r"(b[0]), "r"(b[1]));
}

// ---------------- merged pre-round: all weights + pemb + enc + mem->hcat ----------
__global__ void round_all(
    const float4* __restrict__ wq_m, const float4* __restrict__ wkv_m,
    const float4* __restrict__ fcw_m, const float4* __restrict__ wq_c,
    const float4* __restrict__ wkv_c, const float4* __restrict__ fcw_c,
    const float4* __restrict__ w1, const float4* __restrict__ w2,
    const float4* __restrict__ pemb, const float4* __restrict__ enc,
    const float4* __restrict__ mem, float4* __restrict__ w, float4* __restrict__ hc)
{
    int i = blockIdx.x * 256 + threadIdx.x;          // f4 index, total 22*Q4
    const float4* s;
    float4* d;
    if (i < 20 * Q4) {
        d = w + i;
        if      (i <  1 * Q4) s = wq_m  + i;
        else if (i <  3 * Q4) s = wkv_m + (i -  1 * Q4);
        else if (i <  4 * Q4) s = fcw_m + (i -  3 * Q4);
        else if (i <  5 * Q4) s = wq_c  + (i -  4 * Q4);
        else if (i <  7 * Q4) s = wkv_c + (i -  5 * Q4);
        else if (i <  8 * Q4) s = fcw_c + (i -  7 * Q4);
        else if (i < 12 * Q4) s = w1    + (i -  8 * Q4);
        else if (i < 16 * Q4) s = w2    + (i - 12 * Q4);
        else if (i < 18 * Q4) s = pemb  + (i - 16 * Q4);
        else                  s = enc   + (i - 18 * Q4);
    } else {
        int m = i - 20 * Q4;                         // mem: 2 batches x Q4 f4
        int b = m / Q4;
        int t4 = m - b * Q4;
        s = mem + m;
        d = hc + (size_t)b * (Stc * Dc / 4) + t4;    // hcat top half (t < M)
    }
    float4 v = *s;
    float4 o = { rnd_tf(v.x), rnd_tf(v.y), rnd_tf(v.z), rnd_tf(v.w) };
    *d = o;
}

// ---------------- init column-max keys ----------------
__global__ void init_mx(uint32_t* __restrict__ m, int n)
{
    int i = blockIdx.x * 256 + threadIdx.x;
    if (i < n) m[i] = KEY_NEGINF;
}

// ---------------- dense GEMM, cp.async 3-stage, tf32 MMA ----------------
// 128 threads, 4 warps in 2x2 grid, 64x64 warp tiles -> 2x compute per LDS byte.
// EPI=0: C = [RND](act(A@B + bias) + Res)
// EPI=1: head-split q write; EPI=2: kv split
template<int ACT, int EPI, int RND>
__global__ void __launch_bounds__(128, 2)
gemm_tf32(const float* __restrict__ A, const float* __restrict__ Bm,
          float* __restrict__ C, float* __restrict__ C2,
          int N, int K, const float* __restrict__ bias, const float* __restrict__ bias2,
          const float* __restrict__ Res, int Sk)
{
    extern __shared__ float sm[];
    // As stage s at sm + s*4608 ([128][36]); Bs stage s at sm + 13824 + s*4352 ([32][136])
    const int tid = threadIdx.x, lane = tid & 31, wid = tid >> 5;
    const int wm = wid & 1, wn = wid >> 1;          // 2 x 2 warps, 64x64 each
    const int lr = lane >> 2, lc = lane & 3;
    const int row0 = blockIdx.y * 128, col0 = blockIdx.x * 128;
    const uint32_t smb = (uint32_t)__cvta_generic_to_shared(sm);

    float acc[4][8][4];
#pragma unroll
    for (int mt = 0; mt < 4; mt++)
#pragma unroll
        for (int nt = 0; nt < 8; nt++)
#pragma unroll
            for (int e = 0; e < 4; e++) acc[mt][nt][e] = 0.f;

    const int nk = K / 32;
    auto loadAB = [&](int s, int k0) {
#pragma unroll
        for (int it = 0; it < 8; it++) {
            int lin = tid + it * 128;
            int r = lin >> 3, k4 = (lin & 7) * 4;
            cpa16(smb + (uint32_t)(s * 4608 + r * 36 + k4) * 4,
                  &A[(size_t)(row0 + r) * K + k0 + k4]);
        }
#pragma unroll
        for (int it = 0; it < 8; it++) {
            int lin = tid + it * 128;
            int r = lin >> 5, n4 = (lin & 31) * 4;
            cpa16(smb + (uint32_t)(13824 + s * 4352 + r * 136 + n4) * 4,
                  &Bm[(size_t)(k0 + r) * N + col0 + n4]);
        }
        CP_COMMIT();
    };

    loadAB(0, 0);
    if (nk > 1) loadAB(1, 32);
    for (int kt = 0; kt < nk; kt++) {
        if (kt + 2 < nk) { loadAB((kt + 2) % 3, (kt + 2) * 32); CP_WAIT2(); }
        else if (kt + 1 < nk) CP_WAIT1();
        else CP_WAIT0();
        __syncthreads();
        const float* As = sm + (kt % 3) * 4608;
        const float* Bs = sm + 13824 + (kt % 3) * 4352;
#pragma unroll
        for (int k8 = 0; k8 < 32; k8 += 8) {
            uint32_t a[4][4], b[8][2];
#pragma unroll
            for (int mt = 0; mt < 4; mt++) {
                int r = wm * 64 + mt * 16 + lr;
                a[mt][0] = __float_as_uint(As[r * 36 + k8 + lc]);
                a[mt][1] = __float_as_uint(As[(r + 8) * 36 + k8 + lc]);
                a[mt][2] = __float_as_uint(As[r * 36 + k8 + lc + 4]);
                a[mt][3] = __float_as_uint(As[(r + 8) * 36 + k8 + lc + 4]);
            }
#pragma unroll
            for (int nt = 0; nt < 8; nt++) {
                int c = wn * 64 + nt * 8 + lr;
                b[nt][0] = __float_as_uint(Bs[(k8 + lc) * 136 + c]);
                b[nt][1] = __float_as_uint(Bs[(k8 + lc + 4) * 136 + c]);
            }
#pragma unroll
            for (int mt = 0; mt < 4; mt++)
#pragma unroll
                for (int nt = 0; nt < 8; nt++)
                    mma8(acc[mt][nt], a[mt], b[nt]);
        }
        __syncthreads();
    }

#pragma unroll
    for (int mt = 0; mt < 4; mt++)
#pragma unroll
        for (int nt = 0; nt < 8; nt++) {
            int r_ = row0 + wm * 64 + mt * 16 + lr;
            int c_ = col0 + wn * 64 + nt * 8 + 2 * lc;
#pragma unroll
            for (int hf = 0; hf < 2; hf++) {
                int rr = r_ + hf * 8;
                float v0 = acc[mt][nt][hf * 2 + 0];
                float v1 = acc[mt][nt][hf * 2 + 1];
                if (EPI == 0) {
                    if (bias) { v0 += bias[c_]; v1 += bias[c_ + 1]; }
                    if (ACT == 1) {
                        v0 = 0.5f * v0 * (1.0f + erff(v0 * 0.70710678118654752f));
                        v1 = 0.5f * v1 * (1.0f + erff(v1 * 0.70710678118654752f));
                    }
                    if (Res) {
                        v0 += Res[(size_t)rr * N + c_];
                        v1 += Res[(size_t)rr * N + c_ + 1];
                    }
                    if (RND) { v0 = rnd_tf(v0); v1 = rnd_tf(v1); }
                    C[(size_t)rr * N + c_]     = v0;
                    C[(size_t)rr * N + c_ + 1] = v1;
                } else if (EPI == 1) {
                    int b = rr >> 10, i = rr & 1023;
#pragma unroll
                    for (int e = 0; e < 2; e++) {
                        int cc = c_ + e;
                        int h = cc >> 6, d = cc & 63;
                        float val = e ? v1 : v0;
                        size_t dst = (((size_t)(b * Hc + h)) * Sc + i) * DHc + d;
                        C[dst] = rnd_tf(val + (bias ? bias[cc] : 0.f));
                        if (C2) C2[dst] = rnd_tf(val + bias2[cc]);
                    }
                } else { // EPI == 2
                    int b = rr / Sk, j = rr % Sk;
#pragma unroll
                    for (int e = 0; e < 2; e++) {
                        int cc = c_ + e;
                        int isv = cc >> 10;
                        int h = (cc & 1023) >> 6, d = cc & 63;
                        float val = e ? v1 : v0;
                        size_t dst = (((size_t)(b * Hc + h)) * Sk + j) * DHc + d;
                        (isv ? C2 : C)[dst] = rnd_tf(val);
                    }
                }
            }
        }
}

// ---------------- fused QK^T + shifted-pos + mask + column-max atomics ----------
template<int RELS>
__global__ void __launch_bounds__(256, 2)
qk_fused(const float* __restrict__ Q, const float* __restrict__ Q2,
         const float* __restrict__ Kk, const float* __restrict__ PE,
         float* __restrict__ Out, uint32_t* __restrict__ Mxu, int Srows, int Sk)
{
    extern __shared__ float sm[];
    const int tid = threadIdx.x, lane = tid & 31, wid = tid >> 5;
    const int wm = wid & 1, wn = wid >> 1;
    const int lr = lane >> 2, lc = lane & 3;
    const int z = blockIdx.z;
    const int j0 = blockIdx.x * 128, i0 = blockIdx.y * 128;
    const int bb = z >> 4, hh = z & 15;
    const uint32_t smb = (uint32_t)__cvta_generic_to_shared(sm);

    if (RELS && j0 > i0 + 127 + Mc) return;   // fully masked: colnorm zero-fills

    float acc[4][4][4];
#pragma unroll
    for (int mt = 0; mt < 4; mt++)
#pragma unroll
        for (int nt = 0; nt < 4; nt++)
#pragma unroll
            for (int e = 0; e < 4; e++) acc[mt][nt][e] = 0.f;

#pragma unroll
    for (int d0 = 0; d0 < DHc; d0 += 32) {
#pragma unroll
        for (int it = 0; it < 4; it++) {
            int lin = tid + it * 256;
            int r = lin >> 3, k4 = (lin & 7) * 4;
            cpa16(smb + (uint32_t)(r * 36 + k4) * 4,
                  &Q[((size_t)z * Srows + i0 + r) * DHc + d0 + k4]);
            cpa16(smb + (uint32_t)(4608 + r * 36 + k4) * 4,
                  &Kk[((size_t)z * Sk + j0 + r) * DHc + d0 + k4]);
            if (RELS) {
                int srcrow = i0 + r + (bb == 0 ? 1 : 0);
                int ok = srcrow < Srows;
                cpa16z(smb + (uint32_t)(9216 + r * 36 + k4) * 4,
                       &Q2[((size_t)z * Srows + (ok ? srcrow : 0)) * DHc + d0 + k4],
                       ok ? 16 : 0);
                cpa16(smb + (uint32_t)(13824 + r * 36 + k4) * 4,
                      &PE[(size_t)(j0 + r) * Dc + hh * DHc + d0 + k4]);
            }
        }
        CP_COMMIT();
        CP_WAIT0();
        __syncthreads();

        const float* Qs  = sm;
        const float* Ks  = sm + 4608;
        const float* Q2s = sm + 9216;
        const float* Ps  = sm + 13824;
#pragma unroll
        for (int k8 = 0; k8 < 32; k8 += 8) {
            uint32_t a[4][4], b[4][2];
#pragma unroll
            for (int mt = 0; mt < 4; mt++) {
                int r = wm * 64 + mt * 16 + lr;
                a[mt][0] = __float_as_uint(Qs[r * 36 + k8 + lc]);
                a[mt][1] = __float_as_uint(Qs[(r + 8) * 36 + k8 + lc]);
                a[mt][2] = __float_as_uint(Qs[r * 36 + k8 + lc + 4]);
                a[mt][3] = __float_as_uint(Qs[(r + 8) * 36 + k8 + lc + 4]);
            }
#pragma unroll
            for (int nt = 0; nt < 4; nt++) {
                int c = wn * 32 + nt * 8 + lr;
                b[nt][0] = __float_as_uint(Ks[c * 36 + k8 + lc]);
                b[nt][1] = __float_as_uint(Ks[c * 36 + k8 + lc + 4]);
            }
#pragma unroll
            for (int mt = 0; mt < 4; mt++)
#pragma unroll
                for (int nt = 0; nt < 4; nt++)
                    mma8(acc[mt][nt], a[mt], b[nt]);
            if (RELS) {
#pragma unroll
                for (int mt = 0; mt < 4; mt++) {
                    int r = wm * 64 + mt * 16 + lr;
                    a[mt][0] = __float_as_uint(Q2s[r * 36 + k8 + lc]);
                    a[mt][1] = __float_as_uint(Q2s[(r + 8) * 36 + k8 + lc]);
                    a[mt][2] = __float_as_uint(Q2s[r * 36 + k8 + lc + 4]);
                    a[mt][3] = __float_as_uint(Q2s[(r + 8) * 36 + k8 + lc + 4]);
                }
#pragma unroll
                for (int nt = 0; nt < 4; nt++) {
                    int c = wn * 32 + nt * 8 + lr;
                    b[nt][0] = __float_as_uint(Ps[c * 36 + k8 + lc]);
                    b[nt][1] = __float_as_uint(Ps[c * 36 + k8 + lc + 4]);
                }
#pragma unroll
                for (int mt = 0; mt < 4; mt++)
#pragma unroll
                    for (int nt = 0; nt < 4; nt++)
                        mma8(acc[mt][nt], a[mt], b[nt]);
            }
        }
        __syncthreads();
    }

    float cmax[4][2];
#pragma unroll
    for (int nt = 0; nt < 4; nt++) { cmax[nt][0] = -3.4e38f; cmax[nt][1] = -3.4e38f; }

#pragma unroll
    for (int mt = 0; mt < 4; mt++)
#pragma unroll
        for (int nt = 0; nt < 4; nt++) {
            int i_ = i0 + wm * 64 + mt * 16 + lr;
            int j_ = j0 + wn * 32 + nt * 8 + 2 * lc;
#pragma unroll
            for (int hf = 0; hf < 2; hf++) {
                int ii = i_ + hf * 8;
#pragma unroll
                for (int e = 0; e < 2; e++) {
                    int jj = j_ + e;
                    float val = acc[mt][nt][hf * 2 + e];
                    if (RELS && jj > ii + Mc) val = -1e30f;
                    Out[((size_t)z * Srows + ii) * Sk + jj] = val;
                    cmax[nt][e] = fmaxf(cmax[nt][e], val);
                }
            }
        }

#pragma unroll
    for (int off = 4; off <= 16; off <<= 1)
#pragma unroll
        for (int nt = 0; nt < 4; nt++)
#pragma unroll
            for (int e = 0; e < 2; e++)
                cmax[nt][e] = fmaxf(cmax[nt][e],
                                    __shfl_xor_sync(0xffffffffu, cmax[nt][e], off));
    if (lane < 4) {
#pragma unroll
        for (int nt = 0; nt < 4; nt++)
#pragma unroll
            for (int e = 0; e < 2; e++) {
                int jj = j0 + wn * 32 + nt * 8 + 2 * lc + e;
                atomicMax(&Mxu[(size_t)z * Sk + jj], fkey(cmax[nt][e]));
            }
    }
}

// ---------------- column normalize ----------------
template<int CAUS>
__global__ void colnorm(float* __restrict__ P, const uint32_t* __restrict__ Mxu,
                        float* __restrict__ InvZ, int Srows, int Sk, float scale)
{
    __shared__ float red[256];
    const int z = blockIdx.y;
    const int j = blockIdx.x * 128 + (threadIdx.x & 127);
    const int ty = threadIdx.x >> 7;
    const float msc = funkey(Mxu[(size_t)z * Sk + j]) * scale;
    float* base = P + (size_t)z * Srows * Sk + j;
    const int zend = CAUS ? min(Srows, max(0, j - Mc)) : 0;
    float s = 0.f;
#pragma unroll 4
    for (int i = ty; i < Srows; i += 2) {
        if (i < zend) {
            base[(size_t)i * Sk] = 0.f;
        } else {
            float p = __expf(base[(size_t)i * Sk] * scale - msc);
            base[(size_t)i * Sk] = rnd_tf(p);
            s += p;
        }
    }
    red[threadIdx.x] = s;
    __syncthreads();
    if (ty == 0)
        InvZ[(size_t)z * Sk + j] = 1.f / (red[threadIdx.x] + red[threadIdx.x + 128]);
}

// ---------------- Vn = rnd(V * invZ[j]) ----------------
__global__ void vscale(const float* __restrict__ V, const float* __restrict__ InvZ,
                       float* __restrict__ Vn)
{
    int idx = blockIdx.x * 256 + threadIdx.x;
    int zj = idx >> 4;
    float iz = InvZ[zj];
    float4 v = ((const float4*)V)[idx];
    float4 o = { rnd_tf(v.x * iz), rnd_tf(v.y * iz), rnd_tf(v.z * iz), rnd_tf(v.w * iz) };
    ((float4*)Vn)[idx] = o;
}

// ---------------- AV (cp.async 3-stage) ----------------
__global__ void __launch_bounds__(256, 2)
av_tf32(const float* __restrict__ P, const float* __restrict__ V,
        float* __restrict__ O, int Srows, int Sk, int caus)
{
    extern __shared__ float sm[];
    const int tid = threadIdx.x, lane = tid & 31, wid = tid >> 5;
    const int wm = wid >> 1, wn = wid & 1;
    const int lr = lane >> 2, lc = lane & 3;
    const int z = blockIdx.y;
    const int i0 = blockIdx.x * 128;
    const int bb = z >> 4, hh = z & 15;
    const uint32_t smb = (uint32_t)__cvta_generic_to_shared(sm);

    float acc[2][4][4];
#pragma unroll
    for (int mt = 0; mt < 2; mt++)
#pragma unroll
        for (int nt = 0; nt < 4; nt++)
#pragma unroll
            for (int e = 0; e < 4; e++) acc[mt][nt][e] = 0.f;

    auto loadPV = [&](int s, int j0) {
#pragma unroll
        for (int it = 0; it < 4; it++) {
            int lin = tid + it * 256;
            int r = lin >> 3, k4 = (lin & 7) * 4;
            cpa16(smb + (uint32_t)(s * 4608 + r * 36 + k4) * 4,
                  &P[((size_t)z * Srows + i0 + r) * Sk + j0 + k4]);
        }
#pragma unroll
        for (int it = 0; it < 2; it++) {
            int lin = tid + it * 256;
            int r = lin >> 4, n4 = (lin & 15) * 4;
            cpa16(smb + (uint32_t)(13824 + s * 2304 + r * 72 + n4) * 4,
                  &V[((size_t)z * Sk + j0 + r) * DHc + n4]);
        }
        CP_COMMIT();
    };

    int nk = Sk / 32;
    if (caus) nk = min(nk, (i0 + 127 + Mc) / 32 + 1);
    loadPV(0, 0);
    if (nk > 1) loadPV(1, 32);
    for (int kt = 0; kt < nk; kt++) {
        if (kt + 2 < nk) { loadPV((kt + 2) % 3, (kt + 2) * 32); CP_WAIT2(); }
        else if (kt + 1 < nk) CP_WAIT1();
        else CP_WAIT0();
        __syncthreads();
        const float* Ps = sm + (kt % 3) * 4608;
        const float* Vs = sm + 13824 + (kt % 3) * 2304;
#pragma unroll
        for (int k8 = 0; k8 < 32; k8 += 8) {
            uint32_t a[2][4], b[4][2];
#pragma unroll
            for (int mt = 0; mt < 2; mt++) {
                int r = wm * 32 + mt * 16 + lr;
                a[mt][0] = __float_as_uint(Ps[r * 36 + k8 + lc]);
                a[mt][1] = __float_as_uint(Ps[(r + 8) * 36 + k8 + lc]);
                a[mt][2] = __float_as_uint(Ps[r * 36 + k8 + lc + 4]);
                a[mt][3] = __float_as_uint(Ps[(r + 8) * 36 + k8 + lc + 4]);
            }
#pragma unroll
            for (int nt = 0; nt < 4; nt++) {
                int c = wn * 32 + nt * 8 + lr;
                b[nt][0] = __float_as_uint(Vs[(k8 + lc) * 72 + c]);
                b[nt][1] = __float_as_uint(Vs[(k8 + lc + 4) * 72 + c]);
            }
#pragma unroll
            for (int mt = 0; mt < 2; mt++)
#pragma unroll
                for (int nt = 0; nt < 4; nt++)
                    mma8(acc[mt][nt], a[mt], b[nt]);
        }
        __syncthreads();
    }

#pragma unroll
    for (int mt = 0; mt < 2; mt++)
#pragma unroll
        for (int nt = 0; nt < 4; nt++) {
            int i_ = i0 + wm * 32 + mt * 16 + lr;
            int d_ = wn * 32 + nt * 8 + 2 * lc;
#pragma unroll
            for (int hf = 0; hf < 2; hf++) {
                int ii = i_ + hf * 8;
                size_t o = ((size_t)(bb * Sc) + ii) * Dc + hh * DHc + d_;
                O[o]     = rnd_tf(acc[mt][nt][hf * 2 + 0]);
                O[o + 1] = rnd_tf(acc[mt][nt][hf * 2 + 1]);
            }
        }
}

// ---------------- LayerNorm ----------------
__global__ void ln_kernel(const float* __restrict__ X, const float* __restrict__ gw,
                          const float* __restrict__ bw, float* __restrict__ Y,
                          float* __restrict__ Yr, float* __restrict__ Yr2,
                          const float* __restrict__ Res)
{
    __shared__ float s1[256], s2[256];
    const int row = blockIdx.x;
    const int tid = threadIdx.x;
    const float* x = X + (size_t)row * Dc;
    float4 v = *(const float4*)&x[tid * 4];
    s1[tid] = v.x + v.y + v.z + v.w;
    s2[tid] = v.x * v.x + v.y * v.y + v.z * v.z + v.w * v.w;
    __syncthreads();
    for (int st = 128; st > 0; st >>= 1) {
        if (tid < st) { s1[tid] += s1[tid + st]; s2[tid] += s2[tid + st]; }
        __syncthreads();
    }
    float mu = s1[0] * (1.f / Dc);
    float var = s2[0] * (1.f / Dc) - mu * mu;
    float rinv = rsqrtf(var + 1e-5f);
    float4 g4 = *(const float4*)&gw[tid * 4];
    float4 b4 = *(const float4*)&bw[tid * 4];
    float4 o;
    o.x = (v.x - mu) * rinv * g4.x + b4.x;
    o.y = (v.y - mu) * rinv * g4.y + b4.y;
    o.z = (v.z - mu) * rinv * g4.z + b4.z;
    o.w = (v.w - mu) * rinv * g4.w + b4.w;
    if (Res) {
        float4 r4 = *(const float4*)&Res[(size_t)row * Dc + tid * 4];
        o.x += r4.x; o.y += r4.y; o.z += r4.z; o.w += r4.w;
    }
    *(float4*)&Y[(size_t)row * Dc + tid * 4] = o;
    if (Yr || Yr2) {
        float4 r = { rnd_tf(o.x), rnd_tf(o.y), rnd_tf(o.z), rnd_tf(o.w) };
        if (Yr) *(float4*)&Yr[(size_t)row * Dc + tid * 4] = r;
        if (Yr2) {
            int b = row >> 10;
            *(float4*)&Yr2[((size_t)(row + (b + 1) * Mc)) * Dc + tid * 4] = r;
        }
    }
}

// ---------------- host-side launcher ----------------
static inline float* sym(const void* s)
{
    void* p = nullptr;
    cudaGetSymbolAddress(&p, s);
    return (float*)p;
}

extern "C" void kernel_launch(void* const* d_in, const int* in_sizes, int n_in,
                              void* d_out, int out_size)
{
    const float* x     = (const float*)d_in[0];
    const float* enc   = (const float*)d_in[1];
    const float* pemb  = (const float*)d_in[2];
    const float* u     = (const float*)d_in[3];
    const float* vvec  = (const float*)d_in[4];
    const float* mem   = (const float*)d_in[5];
    // d_in[6] = tgt_mask — recomputed analytically
    const float* Wq_m  = (const float*)d_in[7];
    const float* Wkv_m = (const float*)d_in[8];
    const float* fcw_m = (const float*)d_in[9];
    const float* fcb_m = (const float*)d_in[10];
    const float* lnm_g = (const float*)d_in[11];
    const float* lnm_b = (const float*)d_in[12];
    const float* Wq_c  = (const float*)d_in[13];
    const float* Wkv_c = (const float*)d_in[14];
    const float* fcw_c = (const float*)d_in[15];
    const float* fcb_c = (const float*)d_in[16];
    const float* lnc_g = (const float*)d_in[17];
    const float* lnc_b = (const float*)d_in[18];
    const float* W1    = (const float*)d_in[19];
    const float* b1    = (const float*)d_in[20];
    const float* W2    = (const float*)d_in[21];
    const float* b2    = (const float*)d_in[22];
    const float* ln1_g = (const float*)d_in[23];
    const float* ln1_b = (const float*)d_in[24];
    const float* ln2_g = (const float*)d_in[25];
    const float* ln2_b = (const float*)d_in[26];
    const float* ln3_g = (const float*)d_in[27];
    const float* ln3_b = (const float*)d_in[28];
    float* out = (float*)d_out;

    float* xn  = sym(g_xn);   float* xnr  = sym(g_xnr); float* hcat = sym(g_h);
    float* q   = sym(g_q);    float* q2   = sym(g_q2);
    float* kk  = sym(g_k);    float* vv   = sym(g_v);   float* vn = sym(g_vn);
    float* scs = sym(g_scb);  float* iz   = sym(g_iz);
    uint32_t* mxu = (uint32_t*)sym(g_mxu);
    float* o   = sym(g_o);    float* tmp  = sym(g_tmp);
    float* o1  = sym(g_out);  float* o2   = sym(g_out2);
    float* ff  = sym(g_ff);   float* w    = sym(g_wts);

    float* wWq_m  = w + OFF_WQ_M;
    float* wWkv_m = w + OFF_WKV_M;
    float* wfcw_m = w + OFF_FCW_M;
    float* wWq_c  = w + OFF_WQ_C;
    float* wWkv_c = w + OFF_WKV_C;
    float* wfcw_c = w + OFF_FCW_C;
    float* wW1    = w + OFF_W1;
    float* wW2    = w + OFF_W2;
    float* wpemb  = w + OFF_PEMB;
    float* wenc   = w + OFF_ENC;

    cudaFuncSetAttribute(gemm_tf32<0,0,0>, cudaFuncAttributeMaxDynamicSharedMemorySize, 107520);
    cudaFuncSetAttribute(gemm_tf32<0,1,1>, cudaFuncAttributeMaxDynamicSharedMemorySize, 107520);
    cudaFuncSetAttribute(gemm_tf32<0,2,1>, cudaFuncAttributeMaxDynamicSharedMemorySize, 107520);
    cudaFuncSetAttribute(gemm_tf32<1,0,1>, cudaFuncAttributeMaxDynamicSharedMemorySize, 107520);
    cudaFuncSetAttribute(qk_fused<1>,      cudaFuncAttributeMaxDynamicSharedMemorySize, 73728);
    cudaFuncSetAttribute(qk_fused<0>,      cudaFuncAttributeMaxDynamicSharedMemorySize, 73728);
    cudaFuncSetAttribute(av_tf32,          cudaFuncAttributeMaxDynamicSharedMemorySize, 82944);

    const float scale = 0.125f;
    const int rowsBS = Bc * Sc;

    // ===== 1: merged pre-round =====
    round_all<<<22 * Q4 / 256, 256>>>(
        (const float4*)Wq_m, (const float4*)Wkv_m, (const float4*)fcw_m,
        (const float4*)Wq_c, (const float4*)Wkv_c, (const float4*)fcw_c,
        (const float4*)W1, (const float4*)W2, (const float4*)pemb,
        (const float4*)enc, (const float4*)mem, (float4*)w, (float4*)hcat);

    // ===== 2: pre-norm 1 (also fills hcat bottom half) =====
    ln_kernel<<<rowsBS, 256>>>(x, ln1_g, ln1_b, xn, xnr, hcat, nullptr);

    // ===== self MHA =====
    gemm_tf32<0,1,1><<<dim3(8, 16), 128, 107520>>>(xnr, wWq_m, q, q2, Dc, Dc, u, vvec, nullptr, Sc);
    gemm_tf32<0,2,1><<<dim3(16, 32), 128, 107520>>>(hcat, wWkv_m, kk, vv, 2 * Dc, Dc, nullptr, nullptr, nullptr, Stc);
    init_mx<<<(Zc * Stc) / 256, 256>>>(mxu, Zc * Stc);

    qk_fused<1><<<dim3(16, 8, Zc), 256, 73728>>>(q, q2, kk, wpemb, scs, mxu, Sc, Stc);
    colnorm<1><<<dim3(Stc / 128, Zc), 256>>>(scs, mxu, iz, Sc, Stc, scale);
    vscale<<<(Zc * Stc * DHc / 4) / 256, 256>>>(vv, iz, vn);
    av_tf32<<<dim3(8, Zc), 256, 82944>>>(scs, vn, o, Sc, Stc, 1);

    gemm_tf32<0,0,0><<<dim3(8, 16), 128, 107520>>>(o, wfcw_m, tmp, nullptr, Dc, Dc, fcb_m, nullptr, xn, 0);
    ln_kernel<<<rowsBS, 256>>>(tmp, lnm_g, lnm_b, o1, nullptr, nullptr, x);

    // ===== cross attention =====
    ln_kernel<<<rowsBS, 256>>>(o1, ln2_g, ln2_b, xn, xnr, nullptr, nullptr);
    gemm_tf32<0,1,1><<<dim3(8, 16), 128, 107520>>>(xnr, wWq_c, q, nullptr, Dc, Dc, nullptr, nullptr, nullptr, Sc);
    gemm_tf32<0,2,1><<<dim3(16, 16), 128, 107520>>>(wenc, wWkv_c, kk, vv, 2 * Dc, Dc, nullptr, nullptr, nullptr, Sc);
    init_mx<<<(Zc * Sc) / 256, 256>>>(mxu, Zc * Sc);

    qk_fused<0><<<dim3(8, 8, Zc), 256, 73728>>>(q, nullptr, kk, nullptr, scs, mxu, Sc, Sc);
    colnorm<0><<<dim3(Sc / 128, Zc), 256>>>(scs, mxu, iz, Sc, Sc, scale);
    vscale<<<(Zc * Sc * DHc / 4) / 256, 256>>>(vv, iz, vn);
    av_tf32<<<dim3(8, Zc), 256, 82944>>>(scs, vn, o, Sc, Sc, 0);

    gemm_tf32<0,0,0><<<dim3(8, 16), 128, 107520>>>(o, wfcw_c, tmp, nullptr, Dc, Dc, fcb_c, nullptr, xn, 0);
    ln_kernel<<<rowsBS, 256>>>(tmp, lnc_g, lnc_b, o2, nullptr, nullptr, o1);

    // ===== FFN =====
    ln_kernel<<<rowsBS, 256>>>(o2, ln3_g, ln3_b, xn, xnr, nullptr, nullptr);
    gemm_tf32<1,0,1><<<dim3(32, 16), 128, 107520>>>(xnr, wW1, ff, nullptr, DFFc, Dc, b1, nullptr, nullptr, 0);
    gemm_tf32<0,0,0><<<dim3(8, 16), 128, 107520>>>(ff, wW2, out, nullptr, Dc, DFFc, b2, nullptr, o2, 0);
}

// round 9
// speedup vs baseline: 4.0583x; 1.1087x over previous
#include <cuda_runtime.h>
#include <math.h>
#include <stdint.h>

#define Bc 2
#define Sc 1024
#define Mc 1024
#define Dc 1024
#define Hc 16
#define DHc 64
#define DFFc 4096
#define Stc 2048
#define Zc (Bc*Hc)
#define MEG (1024*1024)
#define Q4 (MEG/4)

// ---------------- scratch (device globals: no allocation allowed) ----------------
__device__ float g_xn [Bc*Sc*Dc];            // exact LN output (residual use)
__device__ float g_xnr[Bc*Sc*Dc];            // tf32-rounded LN output (GEMM use)
__device__ float g_h  [Bc*Stc*Dc];           // concat(mem, xn) rounded
__device__ float g_q  [Zc*Sc*DHc];
__device__ float g_q2 [Zc*Sc*DHc];
__device__ float g_k  [(size_t)Zc*Stc*DHc];
__device__ float g_v  [(size_t)Zc*Stc*DHc];
__device__ float g_vn [(size_t)Zc*Stc*DHc];  // V * invZ
__device__ float g_scb[(size_t)Zc*Sc*Stc];   // raw logits
__device__ uint32_t g_mxu [Zc*Stc];          // column max keys (self)
__device__ uint32_t g_mxu2[Zc*Stc];          // column max keys (cross)
__device__ float g_msc[Zc*Stc];              // column max * scale
__device__ float g_o  [Bc*Sc*Dc];
__device__ float g_tmp[Bc*Sc*Dc];
__device__ float g_out[Bc*Sc*Dc];
__device__ float g_out2[Bc*Sc*Dc];
__device__ float g_ff [(size_t)Bc*Sc*DFFc];
__device__ float g_wts[20*MEG];              // rounded weights/pemb/enc

// offsets into g_wts (floats)
#define OFF_WQ_M   0
#define OFF_WKV_M  (1*MEG)
#define OFF_FCW_M  (3*MEG)
#define OFF_WQ_C   (4*MEG)
#define OFF_WKV_C  (5*MEG)
#define OFF_FCW_C  (7*MEG)
#define OFF_W1     (8*MEG)
#define OFF_W2     (12*MEG)
#define OFF_PEMB   (16*MEG)
#define OFF_ENC    (18*MEG)

// ---------------- helpers ----------------
__device__ __forceinline__ uint32_t f2tf(float f) {
    uint32_t r;
    asm("cvt.rna.tf32.f32 %0, %1;" : "=r"(r) : "f"(f));
    return r;
}
__device__ __forceinline__ float rnd_tf(float f) { return __uint_as_float(f2tf(f)); }

__device__ __forceinline__ uint32_t fkey(float f) {
    uint32_t b = __float_as_uint(f);
    return (b & 0x80000000u) ? ~b : (b | 0x80000000u);
}
__device__ __forceinline__ float funkey(uint32_t k) {
    uint32_t b = (k & 0x80000000u) ? (k & 0x7FFFFFFFu) : ~k;
    return __uint_as_float(b);
}
#define KEY_NEGINF 0x00800000u

__device__ __forceinline__ void cpa16(uint32_t dst, const void* src) {
    asm volatile("cp.async.cg.shared.global [%0], [%1], 16;\n" :: "r"(dst), "l"(src));
}
__device__ __forceinline__ void cpa16z(uint32_t dst, const void* src, int srcbytes) {
    asm volatile("cp.async.cg.shared.global [%0], [%1], 16, %2;\n"
                 :: "r"(dst), "l"(src), "r"(srcbytes));
}
#define CP_COMMIT() asm volatile("cp.async.commit_group;\n")
#define CP_WAIT0()  asm volatile("cp.async.wait_group 0;\n")
#define CP_WAIT1()  asm volatile("cp.async.wait_group 1;\n")
#define CP_WAIT2()  asm volatile("cp.async.wait_group 2;\n")

__device__ __forceinline__ void mma8(float* c, const uint32_t* a, const uint32_t* b) {
    asm volatile(
        "mma.sync.aligned.m16n8k8.row.col.f32.tf32.tf32.f32 "
        "{%0,%1,%2,%3}, {%4,%5,%6,%7}, {%8,%9}, {%0,%1,%2,%3};\n"
        : "+f"(c[0]), "+f"(c[1]), "+f"(c[2]), "+f"(c[3])
        : "r"(a[0]), "r"(a[1]), "r"(a[2]), "r"(a[3]), "r"(b[0]), "r"(b[1]));
}

// ---------------- merged pre-round: all weights + pemb + enc + mem->hcat ----------
__global__ void round_all(
    const float4* __restrict__ wq_m, const float4* __restrict__ wkv_m,
    const float4* __restrict__ fcw_m, const float4* __restrict__ wq_c,
    const float4* __restrict__ wkv_c, const float4* __restrict__ fcw_c,
    const float4* __restrict__ w1, const float4* __restrict__ w2,
    const float4* __restrict__ pemb, const float4* __restrict__ enc,
    const float4* __restrict__ mem, float4* __restrict__ w, float4* __restrict__ hc)
{
    int i = blockIdx.x * 256 + threadIdx.x;          // f4 index, total 22*Q4
    const float4* s;
    float4* d;
    if (i < 20 * Q4) {
        d = w + i;
        if      (i <  1 * Q4) s = wq_m  + i;
        else if (i <  3 * Q4) s = wkv_m + (i -  1 * Q4);
        else if (i <  4 * Q4) s = fcw_m + (i -  3 * Q4);
        else if (i <  5 * Q4) s = wq_c  + (i -  4 * Q4);
        else if (i <  7 * Q4) s = wkv_c + (i -  5 * Q4);
        else if (i <  8 * Q4) s = fcw_c + (i -  7 * Q4);
        else if (i < 12 * Q4) s = w1    + (i -  8 * Q4);
        else if (i < 16 * Q4) s = w2    + (i - 12 * Q4);
        else if (i < 18 * Q4) s = pemb  + (i - 16 * Q4);
        else                  s = enc   + (i - 18 * Q4);
    } else {
        int m = i - 20 * Q4;                         // mem: 2 batches x Q4 f4
        int b = m / Q4;
        int t4 = m - b * Q4;
        s = mem + m;
        d = hc + (size_t)b * (Stc * Dc / 4) + t4;    // hcat top half (t < M)
    }
    float4 v = *s;
    float4 o = { rnd_tf(v.x), rnd_tf(v.y), rnd_tf(v.z), rnd_tf(v.w) };
    *d = o;
}

// ---------------- init both column-max key arrays (once, upfront) ----------------
__global__ void init_mx2(uint32_t* __restrict__ m1, int n1,
                         uint32_t* __restrict__ m2, int n2)
{
    int i = blockIdx.x * 256 + threadIdx.x;
    if (i < n1) m1[i] = KEY_NEGINF;
    if (i < n2) m2[i] = KEY_NEGINF;
}

// ---------------- dense GEMM, cp.async 3-stage, tf32 MMA ----------------
// 128 threads, 4 warps in 2x2 grid, 64x64 warp tiles.
template<int ACT, int EPI, int RND>
__global__ void __launch_bounds__(128, 2)
gemm_tf32(const float* __restrict__ A, const float* __restrict__ Bm,
          float* __restrict__ C, float* __restrict__ C2,
          int N, int K, const float* __restrict__ bias, const float* __restrict__ bias2,
          const float* __restrict__ Res, int Sk)
{
    extern __shared__ float sm[];
    const int tid = threadIdx.x, lane = tid & 31, wid = tid >> 5;
    const int wm = wid & 1, wn = wid >> 1;
    const int lr = lane >> 2, lc = lane & 3;
    const int row0 = blockIdx.y * 128, col0 = blockIdx.x * 128;
    const uint32_t smb = (uint32_t)__cvta_generic_to_shared(sm);

    float acc[4][8][4];
#pragma unroll
    for (int mt = 0; mt < 4; mt++)
#pragma unroll
        for (int nt = 0; nt < 8; nt++)
#pragma unroll
            for (int e = 0; e < 4; e++) acc[mt][nt][e] = 0.f;

    const int nk = K / 32;
    auto loadAB = [&](int s, int k0) {
#pragma unroll
        for (int it = 0; it < 8; it++) {
            int lin = tid + it * 128;
            int r = lin >> 3, k4 = (lin & 7) * 4;
            cpa16(smb + (uint32_t)(s * 4608 + r * 36 + k4) * 4,
                  &A[(size_t)(row0 + r) * K + k0 + k4]);
        }
#pragma unroll
        for (int it = 0; it < 8; it++) {
            int lin = tid + it * 128;
            int r = lin >> 5, n4 = (lin & 31) * 4;
            cpa16(smb + (uint32_t)(13824 + s * 4352 + r * 136 + n4) * 4,
                  &Bm[(size_t)(k0 + r) * N + col0 + n4]);
        }
        CP_COMMIT();
    };

    loadAB(0, 0);
    if (nk > 1) loadAB(1, 32);
    for (int kt = 0; kt < nk; kt++) {
        if (kt + 2 < nk) { loadAB((kt + 2) % 3, (kt + 2) * 32); CP_WAIT2(); }
        else if (kt + 1 < nk) CP_WAIT1();
        else CP_WAIT0();
        __syncthreads();
        const float* As = sm + (kt % 3) * 4608;
        const float* Bs = sm + 13824 + (kt % 3) * 4352;
#pragma unroll
        for (int k8 = 0; k8 < 32; k8 += 8) {
            uint32_t a[4][4], b[8][2];
#pragma unroll
            for (int mt = 0; mt < 4; mt++) {
                int r = wm * 64 + mt * 16 + lr;
                a[mt][0] = __float_as_uint(As[r * 36 + k8 + lc]);
                a[mt][1] = __float_as_uint(As[(r + 8) * 36 + k8 + lc]);
                a[mt][2] = __float_as_uint(As[r * 36 + k8 + lc + 4]);
                a[mt][3] = __float_as_uint(As[(r + 8) * 36 + k8 + lc + 4]);
            }
#pragma unroll
            for (int nt = 0; nt < 8; nt++) {
                int c = wn * 64 + nt * 8 + lr;
                b[nt][0] = __float_as_uint(Bs[(k8 + lc) * 136 + c]);
                b[nt][1] = __float_as_uint(Bs[(k8 + lc + 4) * 136 + c]);
            }
#pragma unroll
            for (int mt = 0; mt < 4; mt++)
#pragma unroll
                for (int nt = 0; nt < 8; nt++)
                    mma8(acc[mt][nt], a[mt], b[nt]);
        }
        __syncthreads();
    }

#pragma unroll
    for (int mt = 0; mt < 4; mt++)
#pragma unroll
        for (int nt = 0; nt < 8; nt++) {
            int r_ = row0 + wm * 64 + mt * 16 + lr;
            int c_ = col0 + wn * 64 + nt * 8 + 2 * lc;
#pragma unroll
            for (int hf = 0; hf < 2; hf++) {
                int rr = r_ + hf * 8;
                float v0 = acc[mt][nt][hf * 2 + 0];
                float v1 = acc[mt][nt][hf * 2 + 1];
                if (EPI == 0) {
                    if (bias) { v0 += bias[c_]; v1 += bias[c_ + 1]; }
                    if (ACT == 1) {
                        v0 = 0.5f * v0 * (1.0f + erff(v0 * 0.70710678118654752f));
                        v1 = 0.5f * v1 * (1.0f + erff(v1 * 0.70710678118654752f));
                    }
                    if (Res) {
                        v0 += Res[(size_t)rr * N + c_];
                        v1 += Res[(size_t)rr * N + c_ + 1];
                    }
                    if (RND) { v0 = rnd_tf(v0); v1 = rnd_tf(v1); }
                    C[(size_t)rr * N + c_]     = v0;
                    C[(size_t)rr * N + c_ + 1] = v1;
                } else if (EPI == 1) {
                    int b = rr >> 10, i = rr & 1023;
#pragma unroll
                    for (int e = 0; e < 2; e++) {
                        int cc = c_ + e;
                        int h = cc >> 6, d = cc & 63;
                        float val = e ? v1 : v0;
                        size_t dst = (((size_t)(b * Hc + h)) * Sc + i) * DHc + d;
                        C[dst] = rnd_tf(val + (bias ? bias[cc] : 0.f));
                        if (C2) C2[dst] = rnd_tf(val + bias2[cc]);
                    }
                } else { // EPI == 2
                    int b = rr / Sk, j = rr % Sk;
#pragma unroll
                    for (int e = 0; e < 2; e++) {
                        int cc = c_ + e;
                        int isv = cc >> 10;
                        int h = (cc & 1023) >> 6, d = cc & 63;
                        float val = e ? v1 : v0;
                        size_t dst = (((size_t)(b * Hc + h)) * Sk + j) * DHc + d;
                        (isv ? C2 : C)[dst] = rnd_tf(val);
                    }
                }
            }
        }
}

// ---------------- fused QK^T + shifted-pos + mask + column-max atomics ----------
template<int RELS>
__global__ void __launch_bounds__(256, 2)
qk_fused(const float* __restrict__ Q, const float* __restrict__ Q2,
         const float* __restrict__ Kk, const float* __restrict__ PE,
         float* __restrict__ Out, uint32_t* __restrict__ Mxu, int Srows, int Sk)
{
    extern __shared__ float sm[];
    const int tid = threadIdx.x, lane = tid & 31, wid = tid >> 5;
    const int wm = wid & 1, wn = wid >> 1;
    const int lr = lane >> 2, lc = lane & 3;
    const int z = blockIdx.z;
    const int j0 = blockIdx.x * 128, i0 = blockIdx.y * 128;
    const int bb = z >> 4, hh = z & 15;
    const uint32_t smb = (uint32_t)__cvta_generic_to_shared(sm);

    if (RELS && j0 > i0 + 127 + Mc) return;   // fully masked: never read downstream

    float acc[4][4][4];
#pragma unroll
    for (int mt = 0; mt < 4; mt++)
#pragma unroll
        for (int nt = 0; nt < 4; nt++)
#pragma unroll
            for (int e = 0; e < 4; e++) acc[mt][nt][e] = 0.f;

#pragma unroll
    for (int d0 = 0; d0 < DHc; d0 += 32) {
#pragma unroll
        for (int it = 0; it < 4; it++) {
            int lin = tid + it * 256;
            int r = lin >> 3, k4 = (lin & 7) * 4;
            cpa16(smb + (uint32_t)(r * 36 + k4) * 4,
                  &Q[((size_t)z * Srows + i0 + r) * DHc + d0 + k4]);
            cpa16(smb + (uint32_t)(4608 + r * 36 + k4) * 4,
                  &Kk[((size_t)z * Sk + j0 + r) * DHc + d0 + k4]);
            if (RELS) {
                int srcrow = i0 + r + (bb == 0 ? 1 : 0);
                int ok = srcrow < Srows;
                cpa16z(smb + (uint32_t)(9216 + r * 36 + k4) * 4,
                       &Q2[((size_t)z * Srows + (ok ? srcrow : 0)) * DHc + d0 + k4],
                       ok ? 16 : 0);
                cpa16(smb + (uint32_t)(13824 + r * 36 + k4) * 4,
                      &PE[(size_t)(j0 + r) * Dc + hh * DHc + d0 + k4]);
            }
        }
        CP_COMMIT();
        CP_WAIT0();
        __syncthreads();

        const float* Qs  = sm;
        const float* Ks  = sm + 4608;
        const float* Q2s = sm + 9216;
        const float* Ps  = sm + 13824;
#pragma unroll
        for (int k8 = 0; k8 < 32; k8 += 8) {
            uint32_t a[4][4], b[4][2];
#pragma unroll
            for (int mt = 0; mt < 4; mt++) {
                int r = wm * 64 + mt * 16 + lr;
                a[mt][0] = __float_as_uint(Qs[r * 36 + k8 + lc]);
                a[mt][1] = __float_as_uint(Qs[(r + 8) * 36 + k8 + lc]);
                a[mt][2] = __float_as_uint(Qs[r * 36 + k8 + lc + 4]);
                a[mt][3] = __float_as_uint(Qs[(r + 8) * 36 + k8 + lc + 4]);
            }
#pragma unroll
            for (int nt = 0; nt < 4; nt++) {
                int c = wn * 32 + nt * 8 + lr;
                b[nt][0] = __float_as_uint(Ks[c * 36 + k8 + lc]);
                b[nt][1] = __float_as_uint(Ks[c * 36 + k8 + lc + 4]);
            }
#pragma unroll
            for (int mt = 0; mt < 4; mt++)
#pragma unroll
                for (int nt = 0; nt < 4; nt++)
                    mma8(acc[mt][nt], a[mt], b[nt]);
            if (RELS) {
#pragma unroll
                for (int mt = 0; mt < 4; mt++) {
                    int r = wm * 64 + mt * 16 + lr;
                    a[mt][0] = __float_as_uint(Q2s[r * 36 + k8 + lc]);
                    a[mt][1] = __float_as_uint(Q2s[(r + 8) * 36 + k8 + lc]);
                    a[mt][2] = __float_as_uint(Q2s[r * 36 + k8 + lc + 4]);
                    a[mt][3] = __float_as_uint(Q2s[(r + 8) * 36 + k8 + lc + 4]);
                }
#pragma unroll
                for (int nt = 0; nt < 4; nt++) {
                    int c = wn * 32 + nt * 8 + lr;
                    b[nt][0] = __float_as_uint(Ps[c * 36 + k8 + lc]);
                    b[nt][1] = __float_as_uint(Ps[c * 36 + k8 + lc + 4]);
                }
#pragma unroll
                for (int mt = 0; mt < 4; mt++)
#pragma unroll
                    for (int nt = 0; nt < 4; nt++)
                        mma8(acc[mt][nt], a[mt], b[nt]);
            }
        }
        __syncthreads();
    }

    float cmax[4][2];
#pragma unroll
    for (int nt = 0; nt < 4; nt++) { cmax[nt][0] = -3.4e38f; cmax[nt][1] = -3.4e38f; }

#pragma unroll
    for (int mt = 0; mt < 4; mt++)
#pragma unroll
        for (int nt = 0; nt < 4; nt++) {
            int i_ = i0 + wm * 64 + mt * 16 + lr;
            int j_ = j0 + wn * 32 + nt * 8 + 2 * lc;
#pragma unroll
            for (int hf = 0; hf < 2; hf++) {
                int ii = i_ + hf * 8;
#pragma unroll
                for (int e = 0; e < 2; e++) {
                    int jj = j_ + e;
                    float val = acc[mt][nt][hf * 2 + e];
                    if (RELS && jj > ii + Mc) val = -1e30f;   // mask BEFORE scale
                    Out[((size_t)z * Srows + ii) * Sk + jj] = val;
                    cmax[nt][e] = fmaxf(cmax[nt][e], val);
                }
            }
        }

#pragma unroll
    for (int off = 4; off <= 16; off <<= 1)
#pragma unroll
        for (int nt = 0; nt < 4; nt++)
#pragma unroll
            for (int e = 0; e < 2; e++)
                cmax[nt][e] = fmaxf(cmax[nt][e],
                                    __shfl_xor_sync(0xffffffffu, cmax[nt][e], off));
    if (lane < 4) {
#pragma unroll
        for (int nt = 0; nt < 4; nt++)
#pragma unroll
            for (int e = 0; e < 2; e++) {
                int jj = j0 + wn * 32 + nt * 8 + 2 * lc + e;
                atomicMax(&Mxu[(size_t)z * Sk + jj], fkey(cmax[nt][e]));
            }
    }
}

// ---------------- colsumv: read-only column sum-of-exp, write msc + Vn ------------
// Identical summation order to old colnorm -> bitwise-identical iz.
template<int CAUS>
__global__ void colsumv(const float* __restrict__ P, const uint32_t* __restrict__ Mxu,
                        const float* __restrict__ V, float* __restrict__ Vn,
                        float* __restrict__ Msc, int Srows, int Sk)
{
    __shared__ float red[256];
    __shared__ float izs[128];
    const int z = blockIdx.y;
    const int jl = threadIdx.x & 127;
    const int ty = threadIdx.x >> 7;
    const int j0b = blockIdx.x * 128;
    const int j = j0b + jl;
    const float msc = funkey(Mxu[(size_t)z * Sk + j]) * 0.125f;
    const float* base = P + (size_t)z * Srows * Sk + j;
    const int zend = CAUS ? min(Srows, max(0, j - Mc)) : 0;
    const int i0s = zend + ((ty ^ zend) & 1);   // first i >= zend with i%2 == ty
    float s = 0.f;
#pragma unroll 4
    for (int i = i0s; i < Srows; i += 2)
        s += __expf(base[(size_t)i * Sk] * 0.125f - msc);
    red[threadIdx.x] = s;
    __syncthreads();
    if (ty == 0) {
        izs[jl] = 1.f / (red[jl] + red[jl + 128]);
        Msc[(size_t)z * Sk + j] = msc;
    }
    __syncthreads();
    // scale V rows j0b..j0b+127: Vn = rnd(V * izs[row])
    for (int t = threadIdx.x; t < 128 * 16; t += 256) {
        int row = t >> 4, c4 = (t & 15) * 4;
        float iz = izs[row];
        size_t idx = ((size_t)z * Sk + j0b + row) * DHc + c4;
        float4 v = *(const float4*)&V[idx];
        float4 o = { rnd_tf(v.x * iz), rnd_tf(v.y * iz),
                     rnd_tf(v.z * iz), rnd_tf(v.w * iz) };
        *(float4*)&Vn[idx] = o;
    }
}

// ---------------- AV: on-the-fly exp of raw logits, 2-stage P / 2-stage V ---------
__global__ void __launch_bounds__(256, 2)
av_tf32(const float* __restrict__ P, const float* __restrict__ V,
        const float* __restrict__ Msc, float* __restrict__ O,
        int Srows, int Sk, int caus)
{
    extern __shared__ float sm[];
    // P stage s @ s*4608 ([128][36]); V stage s @ 9216 + s*2304 ([32][72])
    const int tid = threadIdx.x, lane = tid & 31, wid = tid >> 5;
    const int wm = wid >> 1, wn = wid & 1;
    const int lr = lane >> 2, lc = lane & 3;
    const int z = blockIdx.y;
    const int i0 = blockIdx.x * 128;
    const int bb = z >> 4, hh = z & 15;
    const uint32_t smb = (uint32_t)__cvta_generic_to_shared(sm);

    float acc[2][4][4];
#pragma unroll
    for (int mt = 0; mt < 2; mt++)
#pragma unroll
        for (int nt = 0; nt < 4; nt++)
#pragma unroll
            for (int e = 0; e < 4; e++) acc[mt][nt][e] = 0.f;

    auto ldP = [&](int j0, float4* pr) {
#pragma unroll
        for (int it = 0; it < 4; it++) {
            int lin = tid + it * 256;
            int r = lin >> 3, jb = (lin & 7) * 4;
            pr[it] = *(const float4*)&P[((size_t)z * Srows + i0 + r) * Sk + j0 + jb];
        }
    };
    auto stP = [&](int s, const float4* pr, int j0) {
#pragma unroll
        for (int it = 0; it < 4; it++) {
            int lin = tid + it * 256;
            int r = lin >> 3, jb = (lin & 7) * 4;
            float4 m4 = *(const float4*)&Msc[(size_t)z * Sk + j0 + jb];
            float4 p;
            p.x = rnd_tf(__expf(pr[it].x * 0.125f - m4.x));
            p.y = rnd_tf(__expf(pr[it].y * 0.125f - m4.y));
            p.z = rnd_tf(__expf(pr[it].z * 0.125f - m4.z));
            p.w = rnd_tf(__expf(pr[it].w * 0.125f - m4.w));
            *(float4*)&sm[s * 4608 + r * 36 + jb] = p;
        }
    };
    auto ldV = [&](int s, int j0) {
#pragma unroll
        for (int it = 0; it < 2; it++) {
            int lin = tid + it * 256;
            int r = lin >> 4, n4 = (lin & 15) * 4;
            cpa16(smb + (uint32_t)(9216 + s * 2304 + r * 72 + n4) * 4,
                  &V[((size_t)z * Sk + j0 + r) * DHc + n4]);
        }
        CP_COMMIT();
    };

    int nk = Sk / 32;
    if (caus) nk = min(nk, (i0 + 127 + Mc) / 32 + 1);   // exp of masked -> 0

    float4 pr[2][4];
    ldP(0, pr[0]);
    ldV(0, 0);
    if (nk > 1) { ldP(32, pr[1]); ldV(1, 32); }
    stP(0, pr[0], 0);
    if (nk > 1) { CP_WAIT1(); } else { CP_WAIT0(); }
    __syncthreads();

    for (int kt = 0; kt < nk; kt++) {
        const float* Ps = sm + (kt & 1) * 4608;
        const float* Vs = sm + 9216 + (kt & 1) * 2304;
#pragma unroll
        for (int k8 = 0; k8 < 32; k8 += 8) {
            uint32_t a[2][4], b[4][2];
#pragma unroll
            for (int mt = 0; mt < 2; mt++) {
                int r = wm * 32 + mt * 16 + lr;
                a[mt][0] = __float_as_uint(Ps[r * 36 + k8 + lc]);
                a[mt][1] = __float_as_uint(Ps[(r + 8) * 36 + k8 + lc]);
                a[mt][2] = __float_as_uint(Ps[r * 36 + k8 + lc + 4]);
                a[mt][3] = __float_as_uint(Ps[(r + 8) * 36 + k8 + lc + 4]);
            }
#pragma unroll
            for (int nt = 0; nt < 4; nt++) {
                int c = wn * 32 + nt * 8 + lr;
                b[nt][0] = __float_as_uint(Vs[(k8 + lc) * 72 + c]);
                b[nt][1] = __float_as_uint(Vs[(k8 + lc + 4) * 72 + c]);
            }
#pragma unroll
            for (int mt = 0; mt < 2; mt++)
#pragma unroll
                for (int nt = 0; nt < 4; nt++)
                    mma8(acc[mt][nt], a[mt], b[nt]);
        }
        if (kt + 1 < nk) {
            __syncthreads();
            stP((kt + 1) & 1, pr[(kt + 1) & 1], (kt + 1) * 32);
            if (kt + 2 < nk) {
                ldP((kt + 2) * 32, pr[kt & 1]);
                ldV(kt & 1, (kt + 2) * 32);
                CP_WAIT1();
            } else {
                CP_WAIT0();
            }
            __syncthreads();
        }
    }

#pragma unroll
    for (int mt = 0; mt < 2; mt++)
#pragma unroll
        for (int nt = 0; nt < 4; nt++) {
            int i_ = i0 + wm * 32 + mt * 16 + lr;
            int d_ = wn * 32 + nt * 8 + 2 * lc;
#pragma unroll
            for (int hf = 0; hf < 2; hf++) {
                int ii = i_ + hf * 8;
                size_t o = ((size_t)(bb * Sc) + ii) * Dc + hh * DHc + d_;
                O[o]     = rnd_tf(acc[mt][nt][hf * 2 + 0]);
                O[o + 1] = rnd_tf(acc[mt][nt][hf * 2 + 1]);
            }
        }
}

// ---------------- LayerNorm ----------------
__global__ void ln_kernel(const float* __restrict__ X, const float* __restrict__ gw,
                          const float* __restrict__ bw, float* __restrict__ Y,
                          float* __restrict__ Yr, float* __restrict__ Yr2,
                          const float* __restrict__ Res)
{
    __shared__ float s1[256], s2[256];
    const int row = blockIdx.x;
    const int tid = threadIdx.x;
    const float* x = X + (size_t)row * Dc;
    float4 v = *(const float4*)&x[tid * 4];
    s1[tid] = v.x + v.y + v.z + v.w;
    s2[tid] = v.x * v.x + v.y * v.y + v.z * v.z + v.w * v.w;
    __syncthreads();
    for (int st = 128; st > 0; st >>= 1) {
        if (tid < st) { s1[tid] += s1[tid + st]; s2[tid] += s2[tid + st]; }
        __syncthreads();
    }
    float mu = s1[0] * (1.f / Dc);
    float var = s2[0] * (1.f / Dc) - mu * mu;
    float rinv = rsqrtf(var + 1e-5f);
    float4 g4 = *(const float4*)&gw[tid * 4];
    float4 b4 = *(const float4*)&bw[tid * 4];
    float4 o;
    o.x = (v.x - mu) * rinv * g4.x + b4.x;
    o.y = (v.y - mu) * rinv * g4.y + b4.y;
    o.z = (v.z - mu) * rinv * g4.z + b4.z;
    o.w = (v.w - mu) * rinv * g4.w + b4.w;
    if (Res) {
        float4 r4 = *(const float4*)&Res[(size_t)row * Dc + tid * 4];
        o.x += r4.x; o.y += r4.y; o.z += r4.z; o.w += r4.w;
    }
    *(float4*)&Y[(size_t)row * Dc + tid * 4] = o;
    if (Yr || Yr2) {
        float4 r = { rnd_tf(o.x), rnd_tf(o.y), rnd_tf(o.z), rnd_tf(o.w) };
        if (Yr) *(float4*)&Yr[(size_t)row * Dc + tid * 4] = r;
        if (Yr2) {
            int b = row >> 10;
            *(float4*)&Yr2[((size_t)(row + (b + 1) * Mc)) * Dc + tid * 4] = r;
        }
    }
}

// ---------------- host-side launcher ----------------
static inline float* sym(const void* s)
{
    void* p = nullptr;
    cudaGetSymbolAddress(&p, s);
    return (float*)p;
}

extern "C" void kernel_launch(void* const* d_in, const int* in_sizes, int n_in,
                              void* d_out, int out_size)
{
    const float* x     = (const float*)d_in[0];
    const float* enc   = (const float*)d_in[1];
    const float* pemb  = (const float*)d_in[2];
    const float* u     = (const float*)d_in[3];
    const float* vvec  = (const float*)d_in[4];
    const float* mem   = (const float*)d_in[5];
    // d_in[6] = tgt_mask — recomputed analytically
    const float* Wq_m  = (const float*)d_in[7];
    const float* Wkv_m = (const float*)d_in[8];
    const float* fcw_m = (const float*)d_in[9];
    const float* fcb_m = (const float*)d_in[10];
    const float* lnm_g = (const float*)d_in[11];
    const float* lnm_b = (const float*)d_in[12];
    const float* Wq_c  = (const float*)d_in[13];
    const float* Wkv_c = (const float*)d_in[14];
    const float* fcw_c = (const float*)d_in[15];
    const float* fcb_c = (const float*)d_in[16];
    const float* lnc_g = (const float*)d_in[17];
    const float* lnc_b = (const float*)d_in[18];
    const float* W1    = (const float*)d_in[19];
    const float* b1    = (const float*)d_in[20];
    const float* W2    = (const float*)d_in[21];
    const float* b2    = (const float*)d_in[22];
    const float* ln1_g = (const float*)d_in[23];
    const float* ln1_b = (const float*)d_in[24];
    const float* ln2_g = (const float*)d_in[25];
    const float* ln2_b = (const float*)d_in[26];
    const float* ln3_g = (const float*)d_in[27];
    const float* ln3_b = (const float*)d_in[28];
    float* out = (float*)d_out;

    float* xn  = sym(g_xn);   float* xnr  = sym(g_xnr); float* hcat = sym(g_h);
    float* q   = sym(g_q);    float* q2   = sym(g_q2);
    float* kk  = sym(g_k);    float* vv   = sym(g_v);   float* vn = sym(g_vn);
    float* scs = sym(g_scb);  float* msc  = sym(g_msc);
    uint32_t* mxu  = (uint32_t*)sym(g_mxu);
    uint32_t* mxu2 = (uint32_t*)sym(g_mxu2);
    float* o   = sym(g_o);    float* tmp  = sym(g_tmp);
    float* o1  = sym(g_out);  float* o2   = sym(g_out2);
    float* ff  = sym(g_ff);   float* w    = sym(g_wts);

    float* wWq_m  = w + OFF_WQ_M;
    float* wWkv_m = w + OFF_WKV_M;
    float* wfcw_m = w + OFF_FCW_M;
    float* wWq_c  = w + OFF_WQ_C;
    float* wWkv_c = w + OFF_WKV_C;
    float* wfcw_c = w + OFF_FCW_C;
    float* wW1    = w + OFF_W1;
    float* wW2    = w + OFF_W2;
    float* wpemb  = w + OFF_PEMB;
    float* wenc   = w + OFF_ENC;

    cudaFuncSetAttribute(gemm_tf32<0,0,0>, cudaFuncAttributeMaxDynamicSharedMemorySize, 107520);
    cudaFuncSetAttribute(gemm_tf32<0,1,1>, cudaFuncAttributeMaxDynamicSharedMemorySize, 107520);
    cudaFuncSetAttribute(gemm_tf32<0,2,1>, cudaFuncAttributeMaxDynamicSharedMemorySize, 107520);
    cudaFuncSetAttribute(gemm_tf32<1,0,1>, cudaFuncAttributeMaxDynamicSharedMemorySize, 107520);
    cudaFuncSetAttribute(qk_fused<1>,      cudaFuncAttributeMaxDynamicSharedMemorySize, 73728);
    cudaFuncSetAttribute(qk_fused<0>,      cudaFuncAttributeMaxDynamicSharedMemorySize, 73728);
    cudaFuncSetAttribute(av_tf32,          cudaFuncAttributeMaxDynamicSharedMemorySize, 55296);

    const int rowsBS = Bc * Sc;

    // ===== prep: merged pre-round + one-shot max-key init =====
    round_all<<<22 * Q4 / 256, 256>>>(
        (const float4*)Wq_m, (const float4*)Wkv_m, (const float4*)fcw_m,
        (const float4*)Wq_c, (const float4*)Wkv_c, (const float4*)fcw_c,
        (const float4*)W1, (const float4*)W2, (const float4*)pemb,
        (const float4*)enc, (const float4*)mem, (float4*)w, (float4*)hcat);
    init_mx2<<<(Zc * Stc) / 256, 256>>>(mxu, Zc * Stc, mxu2, Zc * Sc);

    // ===== pre-norm 1 (also fills hcat bottom half) =====
    ln_kernel<<<rowsBS, 256>>>(x, ln1_g, ln1_b, xn, xnr, hcat, nullptr);

    // ===== self MHA (Transformer-XL relative attention) =====
    gemm_tf32<0,1,1><<<dim3(8, 16), 128, 107520>>>(xnr, wWq_m, q, q2, Dc, Dc, u, vvec, nullptr, Sc);
    gemm_tf32<0,2,1><<<dim3(16, 32), 128, 107520>>>(hcat, wWkv_m, kk, vv, 2 * Dc, Dc, nullptr, nullptr, nullptr, Stc);

    qk_fused<1><<<dim3(16, 8, Zc), 256, 73728>>>(q, q2, kk, wpemb, scs, mxu, Sc, Stc);
    colsumv<1><<<dim3(Stc / 128, Zc), 256>>>(scs, mxu, vv, vn, msc, Sc, Stc);
    av_tf32<<<dim3(8, Zc), 256, 55296>>>(scs, vn, msc, o, Sc, Stc, 1);

    gemm_tf32<0,0,0><<<dim3(8, 16), 128, 107520>>>(o, wfcw_m, tmp, nullptr, Dc, Dc, fcb_m, nullptr, xn, 0);
    ln_kernel<<<rowsBS, 256>>>(tmp, lnm_g, lnm_b, o1, nullptr, nullptr, x);

    // ===== cross attention =====
    ln_kernel<<<rowsBS, 256>>>(o1, ln2_g, ln2_b, xn, xnr, nullptr, nullptr);
    gemm_tf32<0,1,1><<<dim3(8, 16), 128, 107520>>>(xnr, wWq_c, q, nullptr, Dc, Dc, nullptr, nullptr, nullptr, Sc);
    gemm_tf32<0,2,1><<<dim3(16, 16), 128, 107520>>>(wenc, wWkv_c, kk, vv, 2 * Dc, Dc, nullptr, nullptr, nullptr, Sc);

    qk_fused<0><<<dim3(8, 8, Zc), 256, 73728>>>(q, nullptr, kk, nullptr, scs, mxu2, Sc, Sc);
    colsumv<0><<<dim3(Sc / 128, Zc), 256>>>(scs, mxu2, vv, vn, msc, Sc, Sc);
    av_tf32<<<dim3(8, Zc), 256, 55296>>>(scs, vn, msc, o, Sc, Sc, 0);

    gemm_tf32<0,0,0><<<dim3(8, 16), 128, 107520>>>(o, wfcw_c, tmp, nullptr, Dc, Dc, fcb_c, nullptr, xn, 0);
    ln_kernel<<<rowsBS, 256>>>(tmp, lnc_g, lnc_b, o2, nullptr, nullptr, o1);

    // ===== FFN =====
    ln_kernel<<<rowsBS, 256>>>(o2, ln3_g, ln3_b, xn, xnr, nullptr, nullptr);
    gemm_tf32<1,0,1><<<dim3(32, 16), 128, 107520>>>(xnr, wW1, ff, nullptr, DFFc, Dc, b1, nullptr, nullptr, 0);
    gemm_tf32<0,0,0><<<dim3(8, 16), 128, 107520>>>(ff, wW2, out, nullptr, Dc, DFFc, b2, nullptr, o2, 0);
}